// round 1
// baseline (speedup 1.0000x reference)
#include <cuda_runtime.h>
#include <math.h>

#define BB 2
#define SEQ 2048
#define RR (BB*SEQ)          // 4096 rows
#define DIM 1024
#define HID 2816
#define NH 16
#define HD 64
#define MCOLS (6*DIM)        // 6144

// ---- scratch buffer (static device memory; no allocations) ----
#define OFF_M    0
#define SZ_M     16384
#define SZ_RD    (RR*DIM)            // 4,194,304
#define SZ_RH    (RR*HID)            // 11,534,336
#define OFF_H    (OFF_M + SZ_M)
#define OFF_Q    (OFF_H + SZ_RD)
#define OFF_K    (OFF_Q + SZ_RD)
#define OFF_V    (OFF_K + SZ_RD)
#define OFF_ATT  (OFF_V + SZ_RD)
#define OFF_TMP  (OFF_ATT + SZ_RD)
#define OFF_XMID (OFF_TMP + SZ_RD)
#define OFF_G1   (OFF_XMID + SZ_RD)
#define OFF_G3   (OFF_G1 + SZ_RH)
#define TOTAL_F  (OFF_G3 + SZ_RH)

__device__ float g_buf[TOTAL_F];

// ---------------------------------------------------------------------------
// adaLN: m[b,j] = sum_k silu(a[b,k]) * W[k,j] + bias[j]
// ---------------------------------------------------------------------------
__global__ __launch_bounds__(256) void adaln_kernel(
    const float* __restrict__ a, const float* __restrict__ W,
    const float* __restrict__ bias, float* __restrict__ m)
{
    __shared__ float act[DIM];
    int b = blockIdx.y;
    int j = blockIdx.x * 256 + threadIdx.x;
    for (int k = threadIdx.x; k < DIM; k += 256) {
        float v = a[b*DIM + k];
        act[k] = v / (1.f + __expf(-v));
    }
    __syncthreads();
    float acc = bias[j];
    #pragma unroll 4
    for (int k = 0; k < DIM; k++)
        acc += act[k] * W[k*MCOLS + j];
    m[b*MCOLS + j] = acc;
}

// ---------------------------------------------------------------------------
// rmsnorm + modulate : dst = x * rsqrt(mean(x^2)+eps) * w * (1+scale) + shift
// one block per row (256 threads x float4)
// ---------------------------------------------------------------------------
__global__ __launch_bounds__(256) void rmsmod_kernel(
    const float* __restrict__ src, const float* __restrict__ w,
    const float* __restrict__ m, int shift_off, int scale_off,
    float* __restrict__ dst)
{
    __shared__ float red[256];
    int row = blockIdx.x;
    int b = row >> 11;
    int tid = threadIdx.x;
    float4 v = ((const float4*)(src + (size_t)row*DIM))[tid];
    red[tid] = v.x*v.x + v.y*v.y + v.z*v.z + v.w*v.w;
    __syncthreads();
    for (int s = 128; s > 0; s >>= 1) {
        if (tid < s) red[tid] += red[tid+s];
        __syncthreads();
    }
    float rms = rsqrtf(red[0] * (1.f/DIM) + 1e-5f);
    int d = tid * 4;
    float4 wv = *(const float4*)(w + d);
    float4 sh = *(const float4*)(m + b*MCOLS + shift_off + d);
    float4 sc = *(const float4*)(m + b*MCOLS + scale_off + d);
    float4 o;
    o.x = v.x*rms*wv.x*(1.f+sc.x) + sh.x;
    o.y = v.y*rms*wv.y*(1.f+sc.y) + sh.y;
    o.z = v.z*rms*wv.z*(1.f+sc.z) + sh.z;
    o.w = v.w*rms*wv.w*(1.f+sc.w) + sh.w;
    ((float4*)(dst + (size_t)row*DIM))[tid] = o;
}

// ---------------------------------------------------------------------------
// SGEMM: C[M,N] = A[M,K] @ B[K,N], row-major. BM=BN=128, BK=8, 8x8/thread.
// M%128==0, N%128==0, K%8==0 (all shapes here satisfy this).
// ---------------------------------------------------------------------------
__global__ __launch_bounds__(256) void sgemm_kernel(
    const float* __restrict__ A, const float* __restrict__ Bm,
    float* __restrict__ C, int M, int N, int K)
{
    __shared__ __align__(16) float As[8][128];
    __shared__ __align__(16) float Bs[8][128];
    int tid = threadIdx.x;
    int crow = blockIdx.y * 128;
    int ccol = blockIdx.x * 128;
    int arow = tid >> 1;
    int acol = (tid & 1) * 4;
    int brow = tid >> 5;
    int bcol = (tid & 31) * 4;
    int tr = (tid >> 4) * 8;
    int tc = (tid & 15) * 8;

    const float* Ap = A + (size_t)(crow + arow)*K + acol;
    const float* Bp = Bm + (size_t)brow*N + ccol + bcol;

    float acc[8][8];
    #pragma unroll
    for (int i = 0; i < 8; i++)
        #pragma unroll
        for (int j = 0; j < 8; j++) acc[i][j] = 0.f;

    for (int k0 = 0; k0 < K; k0 += 8) {
        float4 av = *(const float4*)(Ap + k0);
        As[acol+0][arow] = av.x;
        As[acol+1][arow] = av.y;
        As[acol+2][arow] = av.z;
        As[acol+3][arow] = av.w;
        float4 bv = *(const float4*)(Bp + (size_t)k0*N);
        *(float4*)&Bs[brow][bcol] = bv;
        __syncthreads();
        #pragma unroll
        for (int kk = 0; kk < 8; kk++) {
            float4 a0 = *(const float4*)&As[kk][tr];
            float4 a1 = *(const float4*)&As[kk][tr+4];
            float4 b0 = *(const float4*)&Bs[kk][tc];
            float4 b1 = *(const float4*)&Bs[kk][tc+4];
            float ar[8] = {a0.x,a0.y,a0.z,a0.w,a1.x,a1.y,a1.z,a1.w};
            float br[8] = {b0.x,b0.y,b0.z,b0.w,b1.x,b1.y,b1.z,b1.w};
            #pragma unroll
            for (int i = 0; i < 8; i++)
                #pragma unroll
                for (int j = 0; j < 8; j++)
                    acc[i][j] += ar[i]*br[j];
        }
        __syncthreads();
    }
    #pragma unroll
    for (int i = 0; i < 8; i++) {
        float* cp = C + (size_t)(crow + tr + i)*N + ccol + tc;
        *(float4*)(cp)   = make_float4(acc[i][0],acc[i][1],acc[i][2],acc[i][3]);
        *(float4*)(cp+4) = make_float4(acc[i][4],acc[i][5],acc[i][6],acc[i][7]);
    }
}

// ---------------------------------------------------------------------------
// layernorm (over DIM) + RoPE, in-place on q or k. One block per row.
// ---------------------------------------------------------------------------
__global__ __launch_bounds__(256) void lnrope_kernel(
    float* __restrict__ t, const float* __restrict__ w, const float* __restrict__ bvec,
    const float* __restrict__ cosT, const float* __restrict__ sinT)
{
    __shared__ float redm[256], redv[256];
    int row = blockIdx.x;
    int s = row & (SEQ-1);
    int tid = threadIdx.x;
    float4 v = ((const float4*)(t + (size_t)row*DIM))[tid];
    redm[tid] = v.x + v.y + v.z + v.w;
    redv[tid] = v.x*v.x + v.y*v.y + v.z*v.z + v.w*v.w;
    __syncthreads();
    for (int st = 128; st > 0; st >>= 1) {
        if (tid < st) { redm[tid] += redm[tid+st]; redv[tid] += redv[tid+st]; }
        __syncthreads();
    }
    float mu = redm[0] * (1.f/DIM);
    float var = redv[0] * (1.f/DIM) - mu*mu;
    float rs = rsqrtf(var + 1e-5f);
    int d = tid*4;
    float4 wv = *(const float4*)(w + d);
    float4 bv = *(const float4*)(bvec + d);
    float y0 = (v.x-mu)*rs*wv.x + bv.x;
    float y1 = (v.y-mu)*rs*wv.y + bv.y;
    float y2 = (v.z-mu)*rs*wv.z + bv.z;
    float y3 = (v.w-mu)*rs*wv.w + bv.w;
    int i0 = (d & 63) >> 1;            // pair index within head (0..30, even)
    float c0 = cosT[s*32 + i0],   s0 = sinT[s*32 + i0];
    float c1 = cosT[s*32 + i0+1], s1 = sinT[s*32 + i0+1];
    float4 o;
    o.x = y0*c0 - y1*s0;
    o.y = y0*s0 + y1*c0;
    o.z = y2*c1 - y3*s1;
    o.w = y2*s1 + y3*c1;
    ((float4*)(t + (size_t)row*DIM))[tid] = o;
}

// ---------------------------------------------------------------------------
// Flash attention: block = (qtile 64, head, batch). Key tiles of 64 in smem.
// thread t owns q-rows {2qp, 2qp+1} (qp=t/8) and column group g=t&7.
// ---------------------------------------------------------------------------
#define SMEM_ATT (4*64*65*4)
__global__ __launch_bounds__(256) void attn_kernel(
    const float* __restrict__ q, const float* __restrict__ k,
    const float* __restrict__ v, float* __restrict__ o)
{
    extern __shared__ float sm[];
    float* Qs = sm;
    float* Ks = Qs + 64*65;
    float* Vs = Ks + 64*65;
    float* Ss = Vs + 64*65;
    int tid = threadIdx.x;
    int qt = blockIdx.x, h = blockIdx.y, b = blockIdx.z;
    int hoff = h*HD;
    int qbase = b*SEQ + qt*64;

    for (int idx = tid; idx < 64*64; idx += 256) {
        int r = idx >> 6, c = idx & 63;
        Qs[r*65+c] = q[(size_t)(qbase+r)*DIM + hoff + c] * 0.125f;  // 1/sqrt(64)
    }
    int qp = tid >> 3;
    int g  = tid & 7;
    float m0 = -INFINITY, m1 = -INFINITY, l0 = 0.f, l1 = 0.f;
    float acc0[8], acc1[8];
    #pragma unroll
    for (int i = 0; i < 8; i++) { acc0[i] = 0.f; acc1[i] = 0.f; }

    const float* q0p = Qs + (2*qp)*65;
    const float* q1p = q0p + 65;
    const float* s0p = Ss + (2*qp)*65;
    const float* s1p = s0p + 65;

    for (int kt = 0; kt < SEQ/64; kt++) {
        __syncthreads();
        int kbase = b*SEQ + kt*64;
        for (int idx = tid; idx < 64*64; idx += 256) {
            int r = idx >> 6, c = idx & 63;
            Ks[r*65+c] = k[(size_t)(kbase+r)*DIM + hoff + c];
            Vs[r*65+c] = v[(size_t)(kbase+r)*DIM + hoff + c];
        }
        __syncthreads();

        float sa0[8], sa1[8];
        #pragma unroll
        for (int j = 0; j < 8; j++) { sa0[j] = 0.f; sa1[j] = 0.f; }
        #pragma unroll 4
        for (int i = 0; i < 64; i++) {
            float qv0 = q0p[i], qv1 = q1p[i];
            #pragma unroll
            for (int j = 0; j < 8; j++) {
                float kv = Ks[(g + 8*j)*65 + i];
                sa0[j] += qv0*kv;
                sa1[j] += qv1*kv;
            }
        }
        float mx0 = sa0[0], mx1 = sa1[0];
        #pragma unroll
        for (int j = 1; j < 8; j++) { mx0 = fmaxf(mx0, sa0[j]); mx1 = fmaxf(mx1, sa1[j]); }
        #pragma unroll
        for (int off = 1; off < 8; off <<= 1) {
            mx0 = fmaxf(mx0, __shfl_xor_sync(0xffffffffu, mx0, off));
            mx1 = fmaxf(mx1, __shfl_xor_sync(0xffffffffu, mx1, off));
        }
        float nm0 = fmaxf(m0, mx0), nm1 = fmaxf(m1, mx1);
        float ps0 = 0.f, ps1 = 0.f;
        #pragma unroll
        for (int j = 0; j < 8; j++) {
            float p0 = __expf(sa0[j] - nm0);
            float p1 = __expf(sa1[j] - nm1);
            Ss[(2*qp)*65   + g + 8*j] = p0;
            Ss[(2*qp+1)*65 + g + 8*j] = p1;
            ps0 += p0; ps1 += p1;
        }
        #pragma unroll
        for (int off = 1; off < 8; off <<= 1) {
            ps0 += __shfl_xor_sync(0xffffffffu, ps0, off);
            ps1 += __shfl_xor_sync(0xffffffffu, ps1, off);
        }
        float c0 = __expf(m0 - nm0), c1 = __expf(m1 - nm1);
        l0 = l0*c0 + ps0;  l1 = l1*c1 + ps1;
        m0 = nm0;  m1 = nm1;
        #pragma unroll
        for (int dd = 0; dd < 8; dd++) { acc0[dd] *= c0; acc1[dd] *= c1; }
        __syncwarp();
        #pragma unroll 4
        for (int j = 0; j < 64; j++) {
            float p0 = s0p[j], p1 = s1p[j];
            #pragma unroll
            for (int dd = 0; dd < 8; dd++) {
                float vv = Vs[j*65 + g + 8*dd];
                acc0[dd] += p0*vv;
                acc1[dd] += p1*vv;
            }
        }
    }
    float inv0 = 1.f/l0, inv1 = 1.f/l1;
    size_t r0 = (size_t)(qbase + 2*qp)*DIM + hoff + g;
    size_t r1 = r0 + DIM;
    #pragma unroll
    for (int dd = 0; dd < 8; dd++) {
        o[r0 + 8*dd] = acc0[dd]*inv0;
        o[r1 + 8*dd] = acc1[dd]*inv1;
    }
}

// ---------------------------------------------------------------------------
// residual with per-(b,d) gate: out = x + gate * delta
// ---------------------------------------------------------------------------
__global__ __launch_bounds__(256) void resid_kernel(
    const float* __restrict__ x, const float* __restrict__ delta,
    const float* __restrict__ m, int gate_off, float* __restrict__ out)
{
    int idx = blockIdx.x*256 + threadIdx.x;   // float4 index
    int e = idx*4;
    int b = e >> 21;                           // / (SEQ*DIM)
    int d = e & (DIM-1);
    float4 xv = ((const float4*)x)[idx];
    float4 dv = ((const float4*)delta)[idx];
    float4 gv = *(const float4*)(m + b*MCOLS + gate_off + d);
    float4 o;
    o.x = xv.x + gv.x*dv.x;
    o.y = xv.y + gv.y*dv.y;
    o.z = xv.z + gv.z*dv.z;
    o.w = xv.w + gv.w*dv.w;
    ((float4*)out)[idx] = o;
}

// ---------------------------------------------------------------------------
// g1 = silu(g1) * g3   (elementwise, in place)
// ---------------------------------------------------------------------------
__global__ __launch_bounds__(256) void silugate_kernel(
    float* __restrict__ g1, const float* __restrict__ g3)
{
    int idx = blockIdx.x*256 + threadIdx.x;   // float4 index, exact count
    float4 a = ((const float4*)g1)[idx];
    float4 c = ((const float4*)g3)[idx];
    a.x = a.x / (1.f + __expf(-a.x)) * c.x;
    a.y = a.y / (1.f + __expf(-a.y)) * c.y;
    a.z = a.z / (1.f + __expf(-a.z)) * c.z;
    a.w = a.w / (1.f + __expf(-a.w)) * c.w;
    ((float4*)g1)[idx] = a;
}

// ---------------------------------------------------------------------------
extern "C" void kernel_launch(void* const* d_in, const int* in_sizes, int n_in,
                              void* d_out, int out_size)
{
    const float* x        = (const float*)d_in[0];
    const float* adaln_in = (const float*)d_in[1];
    const float* cosT     = (const float*)d_in[2];
    const float* sinT     = (const float*)d_in[3];
    const float* wq       = (const float*)d_in[4];
    const float* wk       = (const float*)d_in[5];
    const float* wv       = (const float*)d_in[6];
    const float* wo       = (const float*)d_in[7];
    const float* q_norm_w = (const float*)d_in[8];
    const float* q_norm_b = (const float*)d_in[9];
    const float* k_norm_w = (const float*)d_in[10];
    const float* k_norm_b = (const float*)d_in[11];
    const float* attn_norm_w = (const float*)d_in[12];
    const float* ffn_norm_w  = (const float*)d_in[13];
    const float* ada_w    = (const float*)d_in[14];
    const float* ada_b    = (const float*)d_in[15];
    const float* w1       = (const float*)d_in[16];
    const float* w2       = (const float*)d_in[17];
    const float* w3       = (const float*)d_in[18];
    float* out = (float*)d_out;

    float* base = nullptr;
    cudaGetSymbolAddress((void**)&base, g_buf);
    float* m    = base + OFF_M;
    float* hbuf = base + OFF_H;
    float* qb   = base + OFF_Q;
    float* kb   = base + OFF_K;
    float* vb   = base + OFF_V;
    float* att  = base + OFF_ATT;
    float* tmp  = base + OFF_TMP;
    float* xmid = base + OFF_XMID;
    float* g1   = base + OFF_G1;
    float* g3   = base + OFF_G3;

    // adaLN modulation vector
    adaln_kernel<<<dim3(MCOLS/256, BB), 256>>>(adaln_in, ada_w, ada_b, m);

    // h = modulate(rmsnorm(x, attn_norm_w), shift_msa, scale_msa)
    rmsmod_kernel<<<RR, 256>>>(x, attn_norm_w, m, 0, DIM, hbuf);

    // q, k, v projections
    sgemm_kernel<<<dim3(DIM/128, RR/128), 256>>>(hbuf, wq, qb, RR, DIM, DIM);
    sgemm_kernel<<<dim3(DIM/128, RR/128), 256>>>(hbuf, wk, kb, RR, DIM, DIM);
    sgemm_kernel<<<dim3(DIM/128, RR/128), 256>>>(hbuf, wv, vb, RR, DIM, DIM);

    // layernorm + rope on q and k (in place)
    lnrope_kernel<<<RR, 256>>>(qb, q_norm_w, q_norm_b, cosT, sinT);
    lnrope_kernel<<<RR, 256>>>(kb, k_norm_w, k_norm_b, cosT, sinT);

    // attention
    cudaFuncSetAttribute(attn_kernel, cudaFuncAttributeMaxDynamicSharedMemorySize, SMEM_ATT);
    attn_kernel<<<dim3(SEQ/64, NH, BB), 256, SMEM_ATT>>>(qb, kb, vb, att);

    // output projection + gated residual
    sgemm_kernel<<<dim3(DIM/128, RR/128), 256>>>(att, wo, tmp, RR, DIM, DIM);
    resid_kernel<<<(RR*DIM/4)/256, 256>>>(x, tmp, m, 2*DIM, xmid);

    // FFN
    rmsmod_kernel<<<RR, 256>>>(xmid, ffn_norm_w, m, 3*DIM, 4*DIM, hbuf);
    sgemm_kernel<<<dim3(HID/128, RR/128), 256>>>(hbuf, w1, g1, RR, HID, DIM);
    sgemm_kernel<<<dim3(HID/128, RR/128), 256>>>(hbuf, w3, g3, RR, HID, DIM);
    silugate_kernel<<<(RR*HID/4)/256, 256>>>(g1, g3);
    sgemm_kernel<<<dim3(DIM/128, RR/128), 256>>>(g1, w2, tmp, RR, DIM, HID);
    resid_kernel<<<(RR*DIM/4)/256, 256>>>(xmid, tmp, m, 5*DIM, out);
}

// round 3
// speedup vs baseline: 2.2343x; 2.2343x over previous
#include <cuda_runtime.h>
#include <cuda_bf16.h>
#include <math.h>
#include <stdint.h>

#define BB 2
#define SEQ 2048
#define RR (BB*SEQ)          // 4096 rows
#define DIM 1024
#define HID 2816
#define NH 16
#define HD 64
#define MCOLS (6*DIM)        // 6144

// ---- scratch (float units) ----
#define SZ_M     16384
#define SZ_RD    (RR*DIM)
#define SZ_RDH   (RR*DIM/2)
#define SZ_RH    (RR*HID)
#define SZ_RHH   (RR*HID/2)
#define SZ_WS    (DIM*DIM/2)
#define SZ_WB    (DIM*HID/2)

#define OFF_M    0
#define OFF_HBF  (OFF_M + SZ_M)
#define OFF_Q    (OFF_HBF + SZ_RDH)
#define OFF_K    (OFF_Q + SZ_RD)
#define OFF_V    (OFF_K + SZ_RD)
#define OFF_ABF  (OFF_V + SZ_RD)
#define OFF_TMP  (OFF_ABF + SZ_RDH)
#define OFF_XMID (OFF_TMP + SZ_RD)
#define OFF_G1   (OFF_XMID + SZ_RD)
#define OFF_G3   (OFF_G1 + SZ_RH)
#define OFF_G1BF (OFF_G3 + SZ_RH)
#define OFF_WQT  (OFF_G1BF + SZ_RHH)
#define OFF_WKT  (OFF_WQT + SZ_WS)
#define OFF_WVT  (OFF_WKT + SZ_WS)
#define OFF_WOT  (OFF_WVT + SZ_WS)
#define OFF_W1T  (OFF_WOT + SZ_WS)
#define OFF_W3T  (OFF_W1T + SZ_WB)
#define OFF_W2T  (OFF_W3T + SZ_WB)
#define TOTAL_F  (OFF_W2T + SZ_WB)

__device__ float g_buf[TOTAL_F];

// ===========================================================================
// adaLN: m[b,j] = sum_k silu(a[b,k]) * W[k,j] + bias[j]
// ===========================================================================
__global__ __launch_bounds__(256) void adaln_kernel(
    const float* __restrict__ a, const float* __restrict__ W,
    const float* __restrict__ bias, float* __restrict__ m)
{
    __shared__ float act[DIM];
    int b = blockIdx.y;
    int j = blockIdx.x * 256 + threadIdx.x;
    for (int k = threadIdx.x; k < DIM; k += 256) {
        float v = a[b*DIM + k];
        act[k] = v / (1.f + __expf(-v));
    }
    __syncthreads();
    float acc = bias[j];
    #pragma unroll 4
    for (int k = 0; k < DIM; k++)
        acc += act[k] * W[k*MCOLS + j];
    m[b*MCOLS + j] = acc;
}

// ===========================================================================
// weight transpose-convert: W[R,C] fp32 -> Wt[C,R] bf16
// ===========================================================================
__global__ void transposew_kernel(const float* __restrict__ W,
                                  __nv_bfloat16* __restrict__ Wt, int R, int C)
{
    __shared__ float t[32][33];
    int bx = blockIdx.x;   // C/32
    int by = blockIdx.y;   // R/32
    int tx = threadIdx.x, ty = threadIdx.y;
    int x = bx*32 + tx;
    for (int yy = ty; yy < 32; yy += 8)
        t[yy][tx] = W[(size_t)(by*32 + yy)*C + x];
    __syncthreads();
    int xo = by*32 + tx;
    for (int yy = ty; yy < 32; yy += 8)
        Wt[(size_t)(bx*32 + yy)*R + xo] = __float2bfloat16(t[tx][yy]);
}

// ===========================================================================
// rmsnorm + modulate -> bf16
// ===========================================================================
__global__ __launch_bounds__(256) void rmsmod_kernel(
    const float* __restrict__ src, const float* __restrict__ w,
    const float* __restrict__ m, int shift_off, int scale_off,
    __nv_bfloat16* __restrict__ dst)
{
    __shared__ float red[256];
    int row = blockIdx.x;
    int b = row >> 11;
    int tid = threadIdx.x;
    float4 v = ((const float4*)(src + (size_t)row*DIM))[tid];
    red[tid] = v.x*v.x + v.y*v.y + v.z*v.z + v.w*v.w;
    __syncthreads();
    for (int s = 128; s > 0; s >>= 1) {
        if (tid < s) red[tid] += red[tid+s];
        __syncthreads();
    }
    float rms = rsqrtf(red[0] * (1.f/DIM) + 1e-5f);
    int d = tid * 4;
    float4 wv = *(const float4*)(w + d);
    float4 sh = *(const float4*)(m + b*MCOLS + shift_off + d);
    float4 sc = *(const float4*)(m + b*MCOLS + scale_off + d);
    float o0 = v.x*rms*wv.x*(1.f+sc.x) + sh.x;
    float o1 = v.y*rms*wv.y*(1.f+sc.y) + sh.y;
    float o2 = v.z*rms*wv.z*(1.f+sc.z) + sh.z;
    float o3 = v.w*rms*wv.w*(1.f+sc.w) + sh.w;
    __nv_bfloat162* dp = (__nv_bfloat162*)(dst + (size_t)row*DIM);
    dp[tid*2]   = __floats2bfloat162_rn(o0, o1);
    dp[tid*2+1] = __floats2bfloat162_rn(o2, o3);
}

// ===========================================================================
// bf16 tensor-core GEMM via mma.sync (sm_80 path, works on sm_103 baseline):
// C[M,N] fp32 = A[M,K]bf16 @ Bt[N,K]bf16^T
// 128x128x32 tiles, 8 warps (2x4), warp tile 64x32, double-buffered cp.async.
// smem rows are 64B (32 bf16); swizzle: 16B-chunk c -> c ^ ((row>>1)&3).
// ===========================================================================
#define GSMEM (4*8192)

__global__ __launch_bounds__(256) void mma_gemm_kernel(
    const __nv_bfloat16* __restrict__ A,
    const __nv_bfloat16* __restrict__ Bt,
    float* __restrict__ C, int M, int N, int K)
{
    extern __shared__ __align__(128) char smch[];
    uint32_t sb;
    asm("{ .reg .u64 t; cvta.to.shared.u64 t, %1; cvt.u32.u64 %0, t; }"
        : "=r"(sb) : "l"(smch));
    int tid = threadIdx.x;
    int wid = tid >> 5, lid = tid & 31;
    int warp_m = wid & 1;          // 0..1
    int warp_n = wid >> 1;         // 0..3
    int row0 = blockIdx.y * 128;
    int col0 = blockIdx.x * 128;
    int iters = K >> 5;

    // stage s: A at sb + s*16384, B at sb + s*16384 + 8192
    uint32_t tA[2] = { sb,         sb + 16384 };
    uint32_t tB[2] = { sb + 8192,  sb + 16384 + 8192 };

    // per-thread load slots: chunks tid and tid+256 of the 512 16B-chunks
    int r_c0 = tid >> 2,        c_c0 = tid & 3;
    int r_c1 = (tid + 256) >> 2, c_c1 = (tid + 256) & 3;
    uint32_t so0 = r_c0*64 + ((c_c0 ^ ((r_c0 >> 1) & 3)) << 4);
    uint32_t so1 = r_c1*64 + ((c_c1 ^ ((r_c1 >> 1) & 3)) << 4);
    const char* gA0 = (const char*)(A  + (size_t)(row0 + r_c0) * K) + c_c0*16;
    const char* gA1 = (const char*)(A  + (size_t)(row0 + r_c1) * K) + c_c1*16;
    const char* gB0 = (const char*)(Bt + (size_t)(col0 + r_c0) * K) + c_c0*16;
    const char* gB1 = (const char*)(Bt + (size_t)(col0 + r_c1) * K) + c_c1*16;

    float acc[4][4][4];
    #pragma unroll
    for (int i = 0; i < 4; i++)
        #pragma unroll
        for (int j = 0; j < 4; j++)
            #pragma unroll
            for (int q = 0; q < 4; q++) acc[i][j][q] = 0.f;

    // precomputed ldmatrix smem addresses (stage-0 based; add stage offset)
    uint32_t aAddr[4], bAddr[2];
    {
        int rr = lid & 15;
        int half = lid >> 4;
        #pragma unroll
        for (int mt = 0; mt < 4; mt++) {
            int row = warp_m*64 + mt*16 + rr;
            aAddr[mt] = row*64 + half;            // half merged with ck below
        }
        int mat = lid >> 3, r8 = lid & 7;
        #pragma unroll
        for (int nt2 = 0; nt2 < 2; nt2++) {
            int row = warp_n*32 + nt2*16 + (mat >> 1)*8 + r8;
            bAddr[nt2] = row*64 + (mat & 1);
        }
    }

    // prologue: stage 0
    {
        asm volatile("cp.async.cg.shared.global [%0], [%1], 16;" :: "r"(tA[0]+so0), "l"(gA0));
        asm volatile("cp.async.cg.shared.global [%0], [%1], 16;" :: "r"(tA[0]+so1), "l"(gA1));
        asm volatile("cp.async.cg.shared.global [%0], [%1], 16;" :: "r"(tB[0]+so0), "l"(gB0));
        asm volatile("cp.async.cg.shared.global [%0], [%1], 16;" :: "r"(tB[0]+so1), "l"(gB1));
        asm volatile("cp.async.commit_group;");
    }

    for (int kt = 0; kt < iters; kt++) {
        int s = kt & 1;
        if (kt + 1 < iters) {
            int ns = s ^ 1;
            size_t kb = (size_t)(kt + 1) * 64;
            asm volatile("cp.async.cg.shared.global [%0], [%1], 16;" :: "r"(tA[ns]+so0), "l"(gA0+kb));
            asm volatile("cp.async.cg.shared.global [%0], [%1], 16;" :: "r"(tA[ns]+so1), "l"(gA1+kb));
            asm volatile("cp.async.cg.shared.global [%0], [%1], 16;" :: "r"(tB[ns]+so0), "l"(gB0+kb));
            asm volatile("cp.async.cg.shared.global [%0], [%1], 16;" :: "r"(tB[ns]+so1), "l"(gB1+kb));
            asm volatile("cp.async.commit_group;");
            asm volatile("cp.async.wait_group 1;" ::: "memory");
        } else {
            asm volatile("cp.async.wait_group 0;" ::: "memory");
        }
        __syncthreads();

        uint32_t sA = tA[s], sB = tB[s];
        #pragma unroll
        for (int ks = 0; ks < 2; ks++) {
            uint32_t a[4][4], b[4][2];
            #pragma unroll
            for (int mt = 0; mt < 4; mt++) {
                int row = (aAddr[mt] >> 6);       // recover row
                int ck = ks*2 + (aAddr[mt] & 63); // half stored in low bits
                uint32_t ad = sA + (row*64) + (((ck) ^ ((row >> 1) & 3)) << 4);
                asm volatile("ldmatrix.sync.aligned.m8n8.x4.shared.b16 {%0,%1,%2,%3}, [%4];"
                    : "=r"(a[mt][0]), "=r"(a[mt][1]), "=r"(a[mt][2]), "=r"(a[mt][3]) : "r"(ad));
            }
            #pragma unroll
            for (int nt2 = 0; nt2 < 2; nt2++) {
                int row = (bAddr[nt2] >> 6);
                int ck = ks*2 + (bAddr[nt2] & 63);
                uint32_t ad = sB + (row*64) + (((ck) ^ ((row >> 1) & 3)) << 4);
                asm volatile("ldmatrix.sync.aligned.m8n8.x4.shared.b16 {%0,%1,%2,%3}, [%4];"
                    : "=r"(b[nt2*2][0]), "=r"(b[nt2*2][1]),
                      "=r"(b[nt2*2+1][0]), "=r"(b[nt2*2+1][1]) : "r"(ad));
            }
            #pragma unroll
            for (int mt = 0; mt < 4; mt++)
                #pragma unroll
                for (int nt = 0; nt < 4; nt++) {
                    asm volatile(
                        "mma.sync.aligned.m16n8k16.row.col.f32.bf16.bf16.f32 "
                        "{%0,%1,%2,%3}, {%4,%5,%6,%7}, {%8,%9}, {%0,%1,%2,%3};"
                        : "+f"(acc[mt][nt][0]), "+f"(acc[mt][nt][1]),
                          "+f"(acc[mt][nt][2]), "+f"(acc[mt][nt][3])
                        : "r"(a[mt][0]), "r"(a[mt][1]), "r"(a[mt][2]), "r"(a[mt][3]),
                          "r"(b[nt][0]), "r"(b[nt][1]));
                }
        }
        __syncthreads();
    }

    // epilogue: direct fp32 stores (float2 per c-pair)
    int lr = lid >> 2;
    int lc = (lid & 3) * 2;
    #pragma unroll
    for (int mt = 0; mt < 4; mt++) {
        size_t mrow = (size_t)(row0 + warp_m*64 + mt*16 + lr);
        #pragma unroll
        for (int nt = 0; nt < 4; nt++) {
            int col = col0 + warp_n*32 + nt*8 + lc;
            *(float2*)(C + mrow*N + col) =
                make_float2(acc[mt][nt][0], acc[mt][nt][1]);
            *(float2*)(C + (mrow+8)*N + col) =
                make_float2(acc[mt][nt][2], acc[mt][nt][3]);
        }
    }
}

// ===========================================================================
// layernorm + RoPE (in-place, fp32)
// ===========================================================================
__global__ __launch_bounds__(256) void lnrope_kernel(
    float* __restrict__ t, const float* __restrict__ w, const float* __restrict__ bvec,
    const float* __restrict__ cosT, const float* __restrict__ sinT)
{
    __shared__ float redm[256], redv[256];
    int row = blockIdx.x;
    int s = row & (SEQ-1);
    int tid = threadIdx.x;
    float4 v = ((const float4*)(t + (size_t)row*DIM))[tid];
    redm[tid] = v.x + v.y + v.z + v.w;
    redv[tid] = v.x*v.x + v.y*v.y + v.z*v.z + v.w*v.w;
    __syncthreads();
    for (int st = 128; st > 0; st >>= 1) {
        if (tid < st) { redm[tid] += redm[tid+st]; redv[tid] += redv[tid+st]; }
        __syncthreads();
    }
    float mu = redm[0] * (1.f/DIM);
    float var = redv[0] * (1.f/DIM) - mu*mu;
    float rs = rsqrtf(var + 1e-5f);
    int d = tid*4;
    float4 wv = *(const float4*)(w + d);
    float4 bv = *(const float4*)(bvec + d);
    float y0 = (v.x-mu)*rs*wv.x + bv.x;
    float y1 = (v.y-mu)*rs*wv.y + bv.y;
    float y2 = (v.z-mu)*rs*wv.z + bv.z;
    float y3 = (v.w-mu)*rs*wv.w + bv.w;
    int i0 = (d & 63) >> 1;
    float c0 = cosT[s*32 + i0],   s0 = sinT[s*32 + i0];
    float c1 = cosT[s*32 + i0+1], s1 = sinT[s*32 + i0+1];
    float4 o;
    o.x = y0*c0 - y1*s0;
    o.y = y0*s0 + y1*c0;
    o.z = y2*c1 - y3*s1;
    o.w = y2*s1 + y3*c1;
    ((float4*)(t + (size_t)row*DIM))[tid] = o;
}

// ===========================================================================
// Flash attention (fp32 SIMT), output -> bf16
// ===========================================================================
#define SMEM_ATT (4*64*65*4)
__global__ __launch_bounds__(256) void attn_kernel(
    const float* __restrict__ q, const float* __restrict__ k,
    const float* __restrict__ v, __nv_bfloat16* __restrict__ o)
{
    extern __shared__ float sm[];
    float* Qs = sm;
    float* Ks = Qs + 64*65;
    float* Vs = Ks + 64*65;
    float* Ss = Vs + 64*65;
    int tid = threadIdx.x;
    int qt = blockIdx.x, h = blockIdx.y, b = blockIdx.z;
    int hoff = h*HD;
    int qbase = b*SEQ + qt*64;

    for (int idx = tid; idx < 64*64; idx += 256) {
        int r = idx >> 6, c = idx & 63;
        Qs[r*65+c] = q[(size_t)(qbase+r)*DIM + hoff + c] * 0.125f;
    }
    int qp = tid >> 3;
    int g  = tid & 7;
    float m0 = -INFINITY, m1 = -INFINITY, l0 = 0.f, l1 = 0.f;
    float acc0[8], acc1[8];
    #pragma unroll
    for (int i = 0; i < 8; i++) { acc0[i] = 0.f; acc1[i] = 0.f; }

    const float* q0p = Qs + (2*qp)*65;
    const float* q1p = q0p + 65;
    const float* s0p = Ss + (2*qp)*65;
    const float* s1p = s0p + 65;

    for (int kt = 0; kt < SEQ/64; kt++) {
        __syncthreads();
        int kbase = b*SEQ + kt*64;
        for (int idx = tid; idx < 64*64; idx += 256) {
            int r = idx >> 6, c = idx & 63;
            Ks[r*65+c] = k[(size_t)(kbase+r)*DIM + hoff + c];
            Vs[r*65+c] = v[(size_t)(kbase+r)*DIM + hoff + c];
        }
        __syncthreads();

        float sa0[8], sa1[8];
        #pragma unroll
        for (int j = 0; j < 8; j++) { sa0[j] = 0.f; sa1[j] = 0.f; }
        #pragma unroll 4
        for (int i = 0; i < 64; i++) {
            float qv0 = q0p[i], qv1 = q1p[i];
            #pragma unroll
            for (int j = 0; j < 8; j++) {
                float kv = Ks[(g + 8*j)*65 + i];
                sa0[j] += qv0*kv;
                sa1[j] += qv1*kv;
            }
        }
        float mx0 = sa0[0], mx1 = sa1[0];
        #pragma unroll
        for (int j = 1; j < 8; j++) { mx0 = fmaxf(mx0, sa0[j]); mx1 = fmaxf(mx1, sa1[j]); }
        #pragma unroll
        for (int off = 1; off < 8; off <<= 1) {
            mx0 = fmaxf(mx0, __shfl_xor_sync(0xffffffffu, mx0, off));
            mx1 = fmaxf(mx1, __shfl_xor_sync(0xffffffffu, mx1, off));
        }
        float nm0 = fmaxf(m0, mx0), nm1 = fmaxf(m1, mx1);
        float ps0 = 0.f, ps1 = 0.f;
        #pragma unroll
        for (int j = 0; j < 8; j++) {
            float p0 = __expf(sa0[j] - nm0);
            float p1 = __expf(sa1[j] - nm1);
            Ss[(2*qp)*65   + g + 8*j] = p0;
            Ss[(2*qp+1)*65 + g + 8*j] = p1;
            ps0 += p0; ps1 += p1;
        }
        #pragma unroll
        for (int off = 1; off < 8; off <<= 1) {
            ps0 += __shfl_xor_sync(0xffffffffu, ps0, off);
            ps1 += __shfl_xor_sync(0xffffffffu, ps1, off);
        }
        float c0 = __expf(m0 - nm0), c1 = __expf(m1 - nm1);
        l0 = l0*c0 + ps0;  l1 = l1*c1 + ps1;
        m0 = nm0;  m1 = nm1;
        #pragma unroll
        for (int dd = 0; dd < 8; dd++) { acc0[dd] *= c0; acc1[dd] *= c1; }
        __syncwarp();
        #pragma unroll 4
        for (int j = 0; j < 64; j++) {
            float p0 = s0p[j], p1 = s1p[j];
            #pragma unroll
            for (int dd = 0; dd < 8; dd++) {
                float vv = Vs[j*65 + g + 8*dd];
                acc0[dd] += p0*vv;
                acc1[dd] += p1*vv;
            }
        }
    }
    float inv0 = 1.f/l0, inv1 = 1.f/l1;
    size_t r0 = (size_t)(qbase + 2*qp)*DIM + hoff + g;
    size_t r1 = r0 + DIM;
    #pragma unroll
    for (int dd = 0; dd < 8; dd++) {
        o[r0 + 8*dd] = __float2bfloat16(acc0[dd]*inv0);
        o[r1 + 8*dd] = __float2bfloat16(acc1[dd]*inv1);
    }
}

// ===========================================================================
// residual with per-(b,d) gate
// ===========================================================================
__global__ __launch_bounds__(256) void resid_kernel(
    const float* __restrict__ x, const float* __restrict__ delta,
    const float* __restrict__ m, int gate_off, float* __restrict__ out)
{
    int idx = blockIdx.x*256 + threadIdx.x;
    int e = idx*4;
    int b = e >> 21;
    int d = e & (DIM-1);
    float4 xv = ((const float4*)x)[idx];
    float4 dv = ((const float4*)delta)[idx];
    float4 gv = *(const float4*)(m + b*MCOLS + gate_off + d);
    float4 o;
    o.x = xv.x + gv.x*dv.x;
    o.y = xv.y + gv.y*dv.y;
    o.z = xv.z + gv.z*dv.z;
    o.w = xv.w + gv.w*dv.w;
    ((float4*)out)[idx] = o;
}

// ===========================================================================
// outbf = bf16(silu(g1) * g3)
// ===========================================================================
__global__ __launch_bounds__(256) void silugate_kernel(
    const float* __restrict__ g1, const float* __restrict__ g3,
    __nv_bfloat16* __restrict__ outbf)
{
    int idx = blockIdx.x*256 + threadIdx.x;
    float4 a = ((const float4*)g1)[idx];
    float4 c = ((const float4*)g3)[idx];
    float o0 = a.x / (1.f + __expf(-a.x)) * c.x;
    float o1 = a.y / (1.f + __expf(-a.y)) * c.y;
    float o2 = a.z / (1.f + __expf(-a.z)) * c.z;
    float o3 = a.w / (1.f + __expf(-a.w)) * c.w;
    __nv_bfloat162* dp = (__nv_bfloat162*)outbf;
    dp[idx*2]   = __floats2bfloat162_rn(o0, o1);
    dp[idx*2+1] = __floats2bfloat162_rn(o2, o3);
}

// ===========================================================================
extern "C" void kernel_launch(void* const* d_in, const int* in_sizes, int n_in,
                              void* d_out, int out_size)
{
    const float* x        = (const float*)d_in[0];
    const float* adaln_in = (const float*)d_in[1];
    const float* cosT     = (const float*)d_in[2];
    const float* sinT     = (const float*)d_in[3];
    const float* wq       = (const float*)d_in[4];
    const float* wk       = (const float*)d_in[5];
    const float* wv       = (const float*)d_in[6];
    const float* wo       = (const float*)d_in[7];
    const float* q_norm_w = (const float*)d_in[8];
    const float* q_norm_b = (const float*)d_in[9];
    const float* k_norm_w = (const float*)d_in[10];
    const float* k_norm_b = (const float*)d_in[11];
    const float* attn_norm_w = (const float*)d_in[12];
    const float* ffn_norm_w  = (const float*)d_in[13];
    const float* ada_w    = (const float*)d_in[14];
    const float* ada_b    = (const float*)d_in[15];
    const float* w1       = (const float*)d_in[16];
    const float* w2       = (const float*)d_in[17];
    const float* w3       = (const float*)d_in[18];
    float* out = (float*)d_out;

    float* base = nullptr;
    cudaGetSymbolAddress((void**)&base, g_buf);
    float* m    = base + OFF_M;
    __nv_bfloat16* hbf  = (__nv_bfloat16*)(base + OFF_HBF);
    float* qb   = base + OFF_Q;
    float* kb   = base + OFF_K;
    float* vb   = base + OFF_V;
    __nv_bfloat16* abf  = (__nv_bfloat16*)(base + OFF_ABF);
    float* tmp  = base + OFF_TMP;
    float* xmid = base + OFF_XMID;
    float* g1   = base + OFF_G1;
    float* g3   = base + OFF_G3;
    __nv_bfloat16* g1bf = (__nv_bfloat16*)(base + OFF_G1BF);
    __nv_bfloat16* wqT  = (__nv_bfloat16*)(base + OFF_WQT);
    __nv_bfloat16* wkT  = (__nv_bfloat16*)(base + OFF_WKT);
    __nv_bfloat16* wvT  = (__nv_bfloat16*)(base + OFF_WVT);
    __nv_bfloat16* woT  = (__nv_bfloat16*)(base + OFF_WOT);
    __nv_bfloat16* w1T  = (__nv_bfloat16*)(base + OFF_W1T);
    __nv_bfloat16* w3T  = (__nv_bfloat16*)(base + OFF_W3T);
    __nv_bfloat16* w2T  = (__nv_bfloat16*)(base + OFF_W2T);

    cudaFuncSetAttribute(mma_gemm_kernel, cudaFuncAttributeMaxDynamicSharedMemorySize, GSMEM);
    cudaFuncSetAttribute(attn_kernel, cudaFuncAttributeMaxDynamicSharedMemorySize, SMEM_ATT);

    dim3 tb32(32, 8);

    // adaLN modulation + weight transposes (independent)
    adaln_kernel<<<dim3(MCOLS/256, BB), 256>>>(adaln_in, ada_w, ada_b, m);
    transposew_kernel<<<dim3(DIM/32, DIM/32), tb32>>>(wq, wqT, DIM, DIM);
    transposew_kernel<<<dim3(DIM/32, DIM/32), tb32>>>(wk, wkT, DIM, DIM);
    transposew_kernel<<<dim3(DIM/32, DIM/32), tb32>>>(wv, wvT, DIM, DIM);
    transposew_kernel<<<dim3(DIM/32, DIM/32), tb32>>>(wo, woT, DIM, DIM);
    transposew_kernel<<<dim3(HID/32, DIM/32), tb32>>>(w1, w1T, DIM, HID);
    transposew_kernel<<<dim3(HID/32, DIM/32), tb32>>>(w3, w3T, DIM, HID);
    transposew_kernel<<<dim3(DIM/32, HID/32), tb32>>>(w2, w2T, HID, DIM);

    // h = modulate(rmsnorm(x)) -> bf16
    rmsmod_kernel<<<RR, 256>>>(x, attn_norm_w, m, 0, DIM, hbf);

    // q, k, v projections (tensor cores)
    mma_gemm_kernel<<<dim3(DIM/128, RR/128), 256, GSMEM>>>(hbf, wqT, qb, RR, DIM, DIM);
    mma_gemm_kernel<<<dim3(DIM/128, RR/128), 256, GSMEM>>>(hbf, wkT, kb, RR, DIM, DIM);
    mma_gemm_kernel<<<dim3(DIM/128, RR/128), 256, GSMEM>>>(hbf, wvT, vb, RR, DIM, DIM);

    lnrope_kernel<<<RR, 256>>>(qb, q_norm_w, q_norm_b, cosT, sinT);
    lnrope_kernel<<<RR, 256>>>(kb, k_norm_w, k_norm_b, cosT, sinT);

    attn_kernel<<<dim3(SEQ/64, NH, BB), 256, SMEM_ATT>>>(qb, kb, vb, abf);

    mma_gemm_kernel<<<dim3(DIM/128, RR/128), 256, GSMEM>>>(abf, woT, tmp, RR, DIM, DIM);
    resid_kernel<<<(RR*DIM/4)/256, 256>>>(x, tmp, m, 2*DIM, xmid);

    rmsmod_kernel<<<RR, 256>>>(xmid, ffn_norm_w, m, 3*DIM, 4*DIM, hbf);
    mma_gemm_kernel<<<dim3(HID/128, RR/128), 256, GSMEM>>>(hbf, w1T, g1, RR, HID, DIM);
    mma_gemm_kernel<<<dim3(HID/128, RR/128), 256, GSMEM>>>(hbf, w3T, g3, RR, HID, DIM);
    silugate_kernel<<<(RR*HID/4)/256, 256>>>(g1, g3, g1bf);
    mma_gemm_kernel<<<dim3(DIM/128, RR/128), 256, GSMEM>>>(g1bf, w2T, tmp, RR, DIM, HID);
    resid_kernel<<<(RR*DIM/4)/256, 256>>>(xmid, tmp, m, 5*DIM, out);
}

// round 6
// speedup vs baseline: 5.5104x; 2.4663x over previous
#include <cuda_runtime.h>
#include <cuda_bf16.h>
#include <math.h>
#include <stdint.h>

#define BB 2
#define SEQ 2048
#define RR (BB*SEQ)          // 4096 rows
#define DIM 1024
#define HID 2816
#define NH 16
#define HD 64
#define MCOLS (6*DIM)        // 6144

// ---- scratch (float units) ----
#define SZ_M     16384
#define SZ_RD    (RR*DIM)
#define SZ_RDH   (RR*DIM/2)
#define SZ_RH    (RR*HID)
#define SZ_RHH   (RR*HID/2)
#define SZ_WS    (DIM*DIM/2)
#define SZ_WB    (DIM*HID/2)

#define OFF_M    0
#define OFF_HBF  (OFF_M + SZ_M)
#define OFF_QF   (OFF_HBF + SZ_RDH)
#define OFF_KF   (OFF_QF + SZ_RD)
#define OFF_QBF  (OFF_KF + SZ_RD)
#define OFF_KBF  (OFF_QBF + SZ_RDH)
#define OFF_VBF  (OFF_KBF + SZ_RDH)
#define OFF_ABF  (OFF_VBF + SZ_RDH)
#define OFF_TMP  (OFF_ABF + SZ_RDH)
#define OFF_XMID (OFF_TMP + SZ_RD)
#define OFF_G1   (OFF_XMID + SZ_RD)
#define OFF_G3   (OFF_G1 + SZ_RH)
#define OFF_G1BF (OFF_G3 + SZ_RH)
#define OFF_WQT  (OFF_G1BF + SZ_RHH)
#define OFF_WKT  (OFF_WQT + SZ_WS)
#define OFF_WVT  (OFF_WKT + SZ_WS)
#define OFF_WOT  (OFF_WVT + SZ_WS)
#define OFF_W1T  (OFF_WOT + SZ_WS)
#define OFF_W3T  (OFF_W1T + SZ_WB)
#define OFF_W2T  (OFF_W3T + SZ_WB)
#define TOTAL_F  (OFF_W2T + SZ_WB)

__device__ float g_buf[TOTAL_F];

__device__ __forceinline__ uint32_t smem_u32(const void* p) {
    uint32_t a;
    asm("{ .reg .u64 t; cvta.to.shared.u64 t, %1; cvt.u32.u64 %0, t; }" : "=r"(a) : "l"(p));
    return a;
}

// ===========================================================================
// adaLN: m[b,j] = sum_k silu(a[b,k]) * W[k,j] + bias[j]
// ===========================================================================
__global__ __launch_bounds__(256) void adaln_kernel(
    const float* __restrict__ a, const float* __restrict__ W,
    const float* __restrict__ bias, float* __restrict__ m)
{
    __shared__ float act[DIM];
    int b = blockIdx.y;
    int j = blockIdx.x * 256 + threadIdx.x;
    for (int k = threadIdx.x; k < DIM; k += 256) {
        float v = a[b*DIM + k];
        act[k] = v / (1.f + __expf(-v));
    }
    __syncthreads();
    float acc = bias[j];
    #pragma unroll 4
    for (int k = 0; k < DIM; k++)
        acc += act[k] * W[k*MCOLS + j];
    m[b*MCOLS + j] = acc;
}

// ===========================================================================
// weight transpose-convert: W[R,C] fp32 -> Wt[C,R] bf16
// ===========================================================================
__global__ void transposew_kernel(const float* __restrict__ W,
                                  __nv_bfloat16* __restrict__ Wt, int R, int C)
{
    __shared__ float t[32][33];
    int bx = blockIdx.x;
    int by = blockIdx.y;
    int tx = threadIdx.x, ty = threadIdx.y;
    int x = bx*32 + tx;
    for (int yy = ty; yy < 32; yy += 8)
        t[yy][tx] = W[(size_t)(by*32 + yy)*C + x];
    __syncthreads();
    int xo = by*32 + tx;
    for (int yy = ty; yy < 32; yy += 8)
        Wt[(size_t)(bx*32 + yy)*R + xo] = __float2bfloat16(t[tx][yy]);
}

// ===========================================================================
// rmsnorm + modulate -> bf16
// ===========================================================================
__global__ __launch_bounds__(256) void rmsmod_kernel(
    const float* __restrict__ src, const float* __restrict__ w,
    const float* __restrict__ m, int shift_off, int scale_off,
    __nv_bfloat16* __restrict__ dst)
{
    __shared__ float red[256];
    int row = blockIdx.x;
    int b = row >> 11;
    int tid = threadIdx.x;
    float4 v = ((const float4*)(src + (size_t)row*DIM))[tid];
    red[tid] = v.x*v.x + v.y*v.y + v.z*v.z + v.w*v.w;
    __syncthreads();
    for (int s = 128; s > 0; s >>= 1) {
        if (tid < s) red[tid] += red[tid+s];
        __syncthreads();
    }
    float rms = rsqrtf(red[0] * (1.f/DIM) + 1e-5f);
    int d = tid * 4;
    float4 wv = *(const float4*)(w + d);
    float4 sh = *(const float4*)(m + b*MCOLS + shift_off + d);
    float4 sc = *(const float4*)(m + b*MCOLS + scale_off + d);
    float o0 = v.x*rms*wv.x*(1.f+sc.x) + sh.x;
    float o1 = v.y*rms*wv.y*(1.f+sc.y) + sh.y;
    float o2 = v.z*rms*wv.z*(1.f+sc.z) + sh.z;
    float o3 = v.w*rms*wv.w*(1.f+sc.w) + sh.w;
    __nv_bfloat162* dp = (__nv_bfloat162*)(dst + (size_t)row*DIM);
    dp[tid*2]   = __floats2bfloat162_rn(o0, o1);
    dp[tid*2+1] = __floats2bfloat162_rn(o2, o3);
}

// ===========================================================================
// bf16 tensor-core GEMM via mma.sync:
// C[M,N] (fp32 or bf16) = A[M,K]bf16 @ Bt[N,K]bf16^T
// 128x128x32 tiles, 8 warps (2x4), warp tile 64x32, double-buffered cp.async.
// ===========================================================================
#define GSMEM (4*8192)

template<bool OBF>
__global__ __launch_bounds__(256) void mma_gemm_kernel(
    const __nv_bfloat16* __restrict__ A,
    const __nv_bfloat16* __restrict__ Bt,
    void* __restrict__ Cv, int M, int N, int K)
{
    extern __shared__ __align__(128) char smch[];
    uint32_t sb = smem_u32(smch);
    int tid = threadIdx.x;
    int wid = tid >> 5, lid = tid & 31;
    int warp_m = wid & 1;
    int warp_n = wid >> 1;
    int row0 = blockIdx.y * 128;
    int col0 = blockIdx.x * 128;
    int iters = K >> 5;

    uint32_t tA[2] = { sb,         sb + 16384 };
    uint32_t tB[2] = { sb + 8192,  sb + 16384 + 8192 };

    int r_c0 = tid >> 2,         c_c0 = tid & 3;
    int r_c1 = (tid + 256) >> 2, c_c1 = (tid + 256) & 3;
    uint32_t so0 = r_c0*64 + ((c_c0 ^ ((r_c0 >> 1) & 3)) << 4);
    uint32_t so1 = r_c1*64 + ((c_c1 ^ ((r_c1 >> 1) & 3)) << 4);
    const char* gA0 = (const char*)(A  + (size_t)(row0 + r_c0) * K) + c_c0*16;
    const char* gA1 = (const char*)(A  + (size_t)(row0 + r_c1) * K) + c_c1*16;
    const char* gB0 = (const char*)(Bt + (size_t)(col0 + r_c0) * K) + c_c0*16;
    const char* gB1 = (const char*)(Bt + (size_t)(col0 + r_c1) * K) + c_c1*16;

    float acc[4][4][4];
    #pragma unroll
    for (int i = 0; i < 4; i++)
        #pragma unroll
        for (int j = 0; j < 4; j++)
            #pragma unroll
            for (int q = 0; q < 4; q++) acc[i][j][q] = 0.f;

    uint32_t aAddr[4], bAddr[2];
    {
        int rr = lid & 15;
        int half = lid >> 4;
        #pragma unroll
        for (int mt = 0; mt < 4; mt++) {
            int row = warp_m*64 + mt*16 + rr;
            aAddr[mt] = row*64 + half;
        }
        int mat = lid >> 3, r8 = lid & 7;
        #pragma unroll
        for (int nt2 = 0; nt2 < 2; nt2++) {
            int row = warp_n*32 + nt2*16 + (mat >> 1)*8 + r8;
            bAddr[nt2] = row*64 + (mat & 1);
        }
    }

    {
        asm volatile("cp.async.cg.shared.global [%0], [%1], 16;" :: "r"(tA[0]+so0), "l"(gA0));
        asm volatile("cp.async.cg.shared.global [%0], [%1], 16;" :: "r"(tA[0]+so1), "l"(gA1));
        asm volatile("cp.async.cg.shared.global [%0], [%1], 16;" :: "r"(tB[0]+so0), "l"(gB0));
        asm volatile("cp.async.cg.shared.global [%0], [%1], 16;" :: "r"(tB[0]+so1), "l"(gB1));
        asm volatile("cp.async.commit_group;");
    }

    for (int kt = 0; kt < iters; kt++) {
        int s = kt & 1;
        if (kt + 1 < iters) {
            int ns = s ^ 1;
            size_t kb = (size_t)(kt + 1) * 64;
            asm volatile("cp.async.cg.shared.global [%0], [%1], 16;" :: "r"(tA[ns]+so0), "l"(gA0+kb));
            asm volatile("cp.async.cg.shared.global [%0], [%1], 16;" :: "r"(tA[ns]+so1), "l"(gA1+kb));
            asm volatile("cp.async.cg.shared.global [%0], [%1], 16;" :: "r"(tB[ns]+so0), "l"(gB0+kb));
            asm volatile("cp.async.cg.shared.global [%0], [%1], 16;" :: "r"(tB[ns]+so1), "l"(gB1+kb));
            asm volatile("cp.async.commit_group;");
            asm volatile("cp.async.wait_group 1;" ::: "memory");
        } else {
            asm volatile("cp.async.wait_group 0;" ::: "memory");
        }
        __syncthreads();

        uint32_t sA = tA[s], sB = tB[s];
        #pragma unroll
        for (int ks = 0; ks < 2; ks++) {
            uint32_t a[4][4], b[4][2];
            #pragma unroll
            for (int mt = 0; mt < 4; mt++) {
                int row = (aAddr[mt] >> 6);
                int ck = ks*2 + (aAddr[mt] & 63);
                uint32_t ad = sA + (row*64) + (((ck) ^ ((row >> 1) & 3)) << 4);
                asm volatile("ldmatrix.sync.aligned.m8n8.x4.shared.b16 {%0,%1,%2,%3}, [%4];"
                    : "=r"(a[mt][0]), "=r"(a[mt][1]), "=r"(a[mt][2]), "=r"(a[mt][3]) : "r"(ad));
            }
            #pragma unroll
            for (int nt2 = 0; nt2 < 2; nt2++) {
                int row = (bAddr[nt2] >> 6);
                int ck = ks*2 + (bAddr[nt2] & 63);
                uint32_t ad = sB + (row*64) + (((ck) ^ ((row >> 1) & 3)) << 4);
                asm volatile("ldmatrix.sync.aligned.m8n8.x4.shared.b16 {%0,%1,%2,%3}, [%4];"
                    : "=r"(b[nt2*2][0]), "=r"(b[nt2*2][1]),
                      "=r"(b[nt2*2+1][0]), "=r"(b[nt2*2+1][1]) : "r"(ad));
            }
            #pragma unroll
            for (int mt = 0; mt < 4; mt++)
                #pragma unroll
                for (int nt = 0; nt < 4; nt++) {
                    asm volatile(
                        "mma.sync.aligned.m16n8k16.row.col.f32.bf16.bf16.f32 "
                        "{%0,%1,%2,%3}, {%4,%5,%6,%7}, {%8,%9}, {%0,%1,%2,%3};"
                        : "+f"(acc[mt][nt][0]), "+f"(acc[mt][nt][1]),
                          "+f"(acc[mt][nt][2]), "+f"(acc[mt][nt][3])
                        : "r"(a[mt][0]), "r"(a[mt][1]), "r"(a[mt][2]), "r"(a[mt][3]),
                          "r"(b[nt][0]), "r"(b[nt][1]));
                }
        }
        __syncthreads();
    }

    int lr = lid >> 2;
    int lc = (lid & 3) * 2;
    #pragma unroll
    for (int mt = 0; mt < 4; mt++) {
        size_t mrow = (size_t)(row0 + warp_m*64 + mt*16 + lr);
        #pragma unroll
        for (int nt = 0; nt < 4; nt++) {
            int col = col0 + warp_n*32 + nt*8 + lc;
            if (OBF) {
                __nv_bfloat16* C = (__nv_bfloat16*)Cv;
                *(__nv_bfloat162*)(C + mrow*N + col) =
                    __floats2bfloat162_rn(acc[mt][nt][0], acc[mt][nt][1]);
                *(__nv_bfloat162*)(C + (mrow+8)*N + col) =
                    __floats2bfloat162_rn(acc[mt][nt][2], acc[mt][nt][3]);
            } else {
                float* C = (float*)Cv;
                *(float2*)(C + mrow*N + col) =
                    make_float2(acc[mt][nt][0], acc[mt][nt][1]);
                *(float2*)(C + (mrow+8)*N + col) =
                    make_float2(acc[mt][nt][2], acc[mt][nt][3]);
            }
        }
    }
}

// ===========================================================================
// layernorm + RoPE: read fp32, write bf16
// ===========================================================================
__global__ __launch_bounds__(256) void lnrope_kernel(
    const float* __restrict__ t, const float* __restrict__ w, const float* __restrict__ bvec,
    const float* __restrict__ cosT, const float* __restrict__ sinT,
    __nv_bfloat16* __restrict__ dst)
{
    __shared__ float redm[256], redv[256];
    int row = blockIdx.x;
    int s = row & (SEQ-1);
    int tid = threadIdx.x;
    float4 v = ((const float4*)(t + (size_t)row*DIM))[tid];
    redm[tid] = v.x + v.y + v.z + v.w;
    redv[tid] = v.x*v.x + v.y*v.y + v.z*v.z + v.w*v.w;
    __syncthreads();
    for (int st = 128; st > 0; st >>= 1) {
        if (tid < st) { redm[tid] += redm[tid+st]; redv[tid] += redv[tid+st]; }
        __syncthreads();
    }
    float mu = redm[0] * (1.f/DIM);
    float var = redv[0] * (1.f/DIM) - mu*mu;
    float rs = rsqrtf(var + 1e-5f);
    int d = tid*4;
    float4 wv = *(const float4*)(w + d);
    float4 bv = *(const float4*)(bvec + d);
    float y0 = (v.x-mu)*rs*wv.x + bv.x;
    float y1 = (v.y-mu)*rs*wv.y + bv.y;
    float y2 = (v.z-mu)*rs*wv.z + bv.z;
    float y3 = (v.w-mu)*rs*wv.w + bv.w;
    int i0 = (d & 63) >> 1;
    float c0 = cosT[s*32 + i0],   s0 = sinT[s*32 + i0];
    float c1 = cosT[s*32 + i0+1], s1 = sinT[s*32 + i0+1];
    float o0 = y0*c0 - y1*s0;
    float o1 = y0*s0 + y1*c0;
    float o2 = y2*c1 - y3*s1;
    float o3 = y2*s1 + y3*c1;
    __nv_bfloat162* dp = (__nv_bfloat162*)(dst + (size_t)row*DIM);
    dp[tid*2]   = __floats2bfloat162_rn(o0, o1);
    dp[tid*2+1] = __floats2bfloat162_rn(o2, o3);
}

// ===========================================================================
// Tensor-core flash attention (bf16 in, fp32 accum, bf16 out)
// block = (qtile 128, head, batch); 8 warps, warp owns 16 q-rows.
// K/V 64-key tiles, double-buffered cp.async. smem rows 128B, swizzle
// chunk ^= (row & 7).
// ===========================================================================
#define ATT_SMEM 49152

__global__ __launch_bounds__(256, 1) void attn_mma_kernel(
    const __nv_bfloat16* __restrict__ q, const __nv_bfloat16* __restrict__ k,
    const __nv_bfloat16* __restrict__ v, __nv_bfloat16* __restrict__ o)
{
    extern __shared__ __align__(128) char smch[];
    uint32_t sb = smem_u32(smch);
    const uint32_t sq  = sb;
    const uint32_t sk0 = sb + 16384;
    const uint32_t sv0 = sb + 32768;
    int tid = threadIdx.x, wid = tid >> 5, lid = tid & 31;
    int qt = blockIdx.x, h = blockIdx.y, b = blockIdx.z;
    int hoffb = h * HD * 2;           // byte offset within a row
    int qbase = b*SEQ + qt*128;
    int kbb   = b*SEQ;

    // Q tile loads: 128 rows x 8 chunks
    #pragma unroll
    for (int i = 0; i < 4; i++) {
        int cid = tid + 256*i;
        int row = cid >> 3, ch = cid & 7;
        const char* g = (const char*)(q + (size_t)(qbase+row)*DIM) + hoffb + ch*16;
        uint32_t so = sq + row*128 + ((ch ^ (row & 7)) << 4);
        asm volatile("cp.async.cg.shared.global [%0], [%1], 16;" :: "r"(so), "l"(g));
    }
    // K/V stage 0 (ktile 0)
    #pragma unroll
    for (int i = 0; i < 2; i++) {
        int cid = tid + 256*i;
        int row = cid >> 3, ch = cid & 7;
        uint32_t so = row*128 + ((ch ^ (row & 7)) << 4);
        const char* gk = (const char*)(k + (size_t)(kbb+row)*DIM) + hoffb + ch*16;
        const char* gv = (const char*)(v + (size_t)(kbb+row)*DIM) + hoffb + ch*16;
        asm volatile("cp.async.cg.shared.global [%0], [%1], 16;" :: "r"(sk0+so), "l"(gk));
        asm volatile("cp.async.cg.shared.global [%0], [%1], 16;" :: "r"(sv0+so), "l"(gv));
    }
    asm volatile("cp.async.commit_group;");

    int wr = wid * 16;
    uint32_t qf[4][4];
    float oacc[8][4];
    #pragma unroll
    for (int j = 0; j < 8; j++)
        #pragma unroll
        for (int i = 0; i < 4; i++) oacc[j][i] = 0.f;
    float m0 = -INFINITY, m1 = -INFINITY, l0 = 0.f, l1 = 0.f;

    for (int kt = 0; kt < SEQ/64; kt++) {
        int s = kt & 1;
        if (kt + 1 < SEQ/64) {
            int ns = s ^ 1;
            int kb2 = kbb + (kt+1)*64;
            #pragma unroll
            for (int i = 0; i < 2; i++) {
                int cid = tid + 256*i;
                int row = cid >> 3, ch = cid & 7;
                uint32_t so = row*128 + ((ch ^ (row & 7)) << 4);
                const char* gk = (const char*)(k + (size_t)(kb2+row)*DIM) + hoffb + ch*16;
                const char* gv = (const char*)(v + (size_t)(kb2+row)*DIM) + hoffb + ch*16;
                asm volatile("cp.async.cg.shared.global [%0], [%1], 16;" :: "r"(sk0+ns*8192+so), "l"(gk));
                asm volatile("cp.async.cg.shared.global [%0], [%1], 16;" :: "r"(sv0+ns*8192+so), "l"(gv));
            }
            asm volatile("cp.async.commit_group;");
            asm volatile("cp.async.wait_group 1;" ::: "memory");
        } else {
            asm volatile("cp.async.wait_group 0;" ::: "memory");
        }
        __syncthreads();

        if (kt == 0) {
            // Q fragments (once): kstep s2 covers chunks 2*s2, 2*s2+1
            int arow = wr + (lid & 15);
            #pragma unroll
            for (int s2 = 0; s2 < 4; s2++) {
                int ch = 2*s2 + (lid >> 4);
                uint32_t ad = sq + arow*128 + ((ch ^ (arow & 7)) << 4);
                asm volatile("ldmatrix.sync.aligned.m8n8.x4.shared.b16 {%0,%1,%2,%3}, [%4];"
                    : "=r"(qf[s2][0]), "=r"(qf[s2][1]), "=r"(qf[s2][2]), "=r"(qf[s2][3]) : "r"(ad));
            }
        }
        uint32_t skst = sk0 + s*8192, svst = sv0 + s*8192;

        // ---- S = Q @ K^T  (warp: 16 x 64) ----
        float sa[8][4];
        #pragma unroll
        for (int j = 0; j < 8; j++)
            #pragma unroll
            for (int i = 0; i < 4; i++) sa[j][i] = 0.f;

        #pragma unroll
        for (int s2 = 0; s2 < 4; s2++) {
            #pragma unroll
            for (int p = 0; p < 4; p++) {
                int mat = lid >> 3;
                int krow = p*16 + ((mat >> 1) << 3) + (lid & 7);
                int ch = 2*s2 + (mat & 1);
                uint32_t ad = skst + krow*128 + ((ch ^ (krow & 7)) << 4);
                uint32_t b0, b1, b2, b3;
                asm volatile("ldmatrix.sync.aligned.m8n8.x4.shared.b16 {%0,%1,%2,%3}, [%4];"
                    : "=r"(b0), "=r"(b1), "=r"(b2), "=r"(b3) : "r"(ad));
                asm volatile(
                    "mma.sync.aligned.m16n8k16.row.col.f32.bf16.bf16.f32 "
                    "{%0,%1,%2,%3}, {%4,%5,%6,%7}, {%8,%9}, {%0,%1,%2,%3};"
                    : "+f"(sa[2*p][0]), "+f"(sa[2*p][1]), "+f"(sa[2*p][2]), "+f"(sa[2*p][3])
                    : "r"(qf[s2][0]), "r"(qf[s2][1]), "r"(qf[s2][2]), "r"(qf[s2][3]),
                      "r"(b0), "r"(b1));
                asm volatile(
                    "mma.sync.aligned.m16n8k16.row.col.f32.bf16.bf16.f32 "
                    "{%0,%1,%2,%3}, {%4,%5,%6,%7}, {%8,%9}, {%0,%1,%2,%3};"
                    : "+f"(sa[2*p+1][0]), "+f"(sa[2*p+1][1]), "+f"(sa[2*p+1][2]), "+f"(sa[2*p+1][3])
                    : "r"(qf[s2][0]), "r"(qf[s2][1]), "r"(qf[s2][2]), "r"(qf[s2][3]),
                      "r"(b2), "r"(b3));
            }
        }

        // ---- online softmax (rows r=lid>>2 and r+8; quad = lanes sharing row) ----
        float mx0 = -INFINITY, mx1 = -INFINITY;
        #pragma unroll
        for (int j = 0; j < 8; j++) {
            sa[j][0] *= 0.125f; sa[j][1] *= 0.125f;
            sa[j][2] *= 0.125f; sa[j][3] *= 0.125f;
            mx0 = fmaxf(mx0, fmaxf(sa[j][0], sa[j][1]));
            mx1 = fmaxf(mx1, fmaxf(sa[j][2], sa[j][3]));
        }
        mx0 = fmaxf(mx0, __shfl_xor_sync(0xffffffffu, mx0, 1));
        mx0 = fmaxf(mx0, __shfl_xor_sync(0xffffffffu, mx0, 2));
        mx1 = fmaxf(mx1, __shfl_xor_sync(0xffffffffu, mx1, 1));
        mx1 = fmaxf(mx1, __shfl_xor_sync(0xffffffffu, mx1, 2));
        float nm0 = fmaxf(m0, mx0), nm1 = fmaxf(m1, mx1);

        float ps0 = 0.f, ps1 = 0.f;
        uint32_t pf[4][4];
        #pragma unroll
        for (int j = 0; j < 8; j++) {
            float e0 = __expf(sa[j][0] - nm0);
            float e1 = __expf(sa[j][1] - nm0);
            float e2 = __expf(sa[j][2] - nm1);
            float e3 = __expf(sa[j][3] - nm1);
            ps0 += e0 + e1; ps1 += e2 + e3;
            int s2 = j >> 1;
            __nv_bfloat162 lo = __floats2bfloat162_rn(e0, e1);
            __nv_bfloat162 hi = __floats2bfloat162_rn(e2, e3);
            if ((j & 1) == 0) {
                pf[s2][0] = *(uint32_t*)&lo;
                pf[s2][1] = *(uint32_t*)&hi;
            } else {
                pf[s2][2] = *(uint32_t*)&lo;
                pf[s2][3] = *(uint32_t*)&hi;
            }
        }
        ps0 += __shfl_xor_sync(0xffffffffu, ps0, 1);
        ps0 += __shfl_xor_sync(0xffffffffu, ps0, 2);
        ps1 += __shfl_xor_sync(0xffffffffu, ps1, 1);
        ps1 += __shfl_xor_sync(0xffffffffu, ps1, 2);

        float c0 = __expf(m0 - nm0), c1 = __expf(m1 - nm1);
        l0 = l0*c0 + ps0;  l1 = l1*c1 + ps1;
        m0 = nm0;  m1 = nm1;
        #pragma unroll
        for (int j = 0; j < 8; j++) {
            oacc[j][0] *= c0; oacc[j][1] *= c0;
            oacc[j][2] *= c1; oacc[j][3] *= c1;
        }

        // ---- O += P @ V ---- (V^T fragments via ldmatrix.trans)
        #pragma unroll
        for (int s2 = 0; s2 < 4; s2++) {
            #pragma unroll
            for (int p = 0; p < 4; p++) {
                int mat = lid >> 3;
                int vrow = s2*16 + ((mat & 1) << 3) + (lid & 7);
                int ch = 2*p + (mat >> 1);
                uint32_t ad = svst + vrow*128 + ((ch ^ (vrow & 7)) << 4);
                uint32_t v0, v1, v2, v3;
                asm volatile("ldmatrix.sync.aligned.m8n8.x4.trans.shared.b16 {%0,%1,%2,%3}, [%4];"
                    : "=r"(v0), "=r"(v1), "=r"(v2), "=r"(v3) : "r"(ad));
                asm volatile(
                    "mma.sync.aligned.m16n8k16.row.col.f32.bf16.bf16.f32 "
                    "{%0,%1,%2,%3}, {%4,%5,%6,%7}, {%8,%9}, {%0,%1,%2,%3};"
                    : "+f"(oacc[2*p][0]), "+f"(oacc[2*p][1]), "+f"(oacc[2*p][2]), "+f"(oacc[2*p][3])
                    : "r"(pf[s2][0]), "r"(pf[s2][1]), "r"(pf[s2][2]), "r"(pf[s2][3]),
                      "r"(v0), "r"(v1));
                asm volatile(
                    "mma.sync.aligned.m16n8k16.row.col.f32.bf16.bf16.f32 "
                    "{%0,%1,%2,%3}, {%4,%5,%6,%7}, {%8,%9}, {%0,%1,%2,%3};"
                    : "+f"(oacc[2*p+1][0]), "+f"(oacc[2*p+1][1]), "+f"(oacc[2*p+1][2]), "+f"(oacc[2*p+1][3])
                    : "r"(pf[s2][0]), "r"(pf[s2][1]), "r"(pf[s2][2]), "r"(pf[s2][3]),
                      "r"(v2), "r"(v3));
            }
        }
        __syncthreads();
    }

    // epilogue
    float inv0 = 1.f / l0, inv1 = 1.f / l1;
    int r = lid >> 2, c2 = (lid & 3) * 2;
    size_t row0 = (size_t)(qbase + wr + r)*DIM + h*HD + c2;
    size_t row1 = row0 + 8*DIM;
    #pragma unroll
    for (int j = 0; j < 8; j++) {
        *(__nv_bfloat162*)(o + row0 + 8*j) =
            __floats2bfloat162_rn(oacc[j][0]*inv0, oacc[j][1]*inv0);
        *(__nv_bfloat162*)(o + row1 + 8*j) =
            __floats2bfloat162_rn(oacc[j][2]*inv1, oacc[j][3]*inv1);
    }
}

// ===========================================================================
// residual with per-(b,d) gate
// ===========================================================================
__global__ __launch_bounds__(256) void resid_kernel(
    const float* __restrict__ x, const float* __restrict__ delta,
    const float* __restrict__ m, int gate_off, float* __restrict__ out)
{
    int idx = blockIdx.x*256 + threadIdx.x;
    int e = idx*4;
    int b = e >> 21;
    int d = e & (DIM-1);
    float4 xv = ((const float4*)x)[idx];
    float4 dv = ((const float4*)delta)[idx];
    float4 gv = *(const float4*)(m + b*MCOLS + gate_off + d);
    float4 o;
    o.x = xv.x + gv.x*dv.x;
    o.y = xv.y + gv.y*dv.y;
    o.z = xv.z + gv.z*dv.z;
    o.w = xv.w + gv.w*dv.w;
    ((float4*)out)[idx] = o;
}

// ===========================================================================
// outbf = bf16(silu(g1) * g3)
// ===========================================================================
__global__ __launch_bounds__(256) void silugate_kernel(
    const float* __restrict__ g1, const float* __restrict__ g3,
    __nv_bfloat16* __restrict__ outbf)
{
    int idx = blockIdx.x*256 + threadIdx.x;
    float4 a = ((const float4*)g1)[idx];
    float4 c = ((const float4*)g3)[idx];
    float o0 = a.x / (1.f + __expf(-a.x)) * c.x;
    float o1 = a.y / (1.f + __expf(-a.y)) * c.y;
    float o2 = a.z / (1.f + __expf(-a.z)) * c.z;
    float o3 = a.w / (1.f + __expf(-a.w)) * c.w;
    __nv_bfloat162* dp = (__nv_bfloat162*)outbf;
    dp[idx*2]   = __floats2bfloat162_rn(o0, o1);
    dp[idx*2+1] = __floats2bfloat162_rn(o2, o3);
}

// ===========================================================================
extern "C" void kernel_launch(void* const* d_in, const int* in_sizes, int n_in,
                              void* d_out, int out_size)
{
    const float* x        = (const float*)d_in[0];
    const float* adaln_in = (const float*)d_in[1];
    const float* cosT     = (const float*)d_in[2];
    const float* sinT     = (const float*)d_in[3];
    const float* wq       = (const float*)d_in[4];
    const float* wk       = (const float*)d_in[5];
    const float* wv       = (const float*)d_in[6];
    const float* wo       = (const float*)d_in[7];
    const float* q_norm_w = (const float*)d_in[8];
    const float* q_norm_b = (const float*)d_in[9];
    const float* k_norm_w = (const float*)d_in[10];
    const float* k_norm_b = (const float*)d_in[11];
    const float* attn_norm_w = (const float*)d_in[12];
    const float* ffn_norm_w  = (const float*)d_in[13];
    const float* ada_w    = (const float*)d_in[14];
    const float* ada_b    = (const float*)d_in[15];
    const float* w1       = (const float*)d_in[16];
    const float* w2       = (const float*)d_in[17];
    const float* w3       = (const float*)d_in[18];
    float* out = (float*)d_out;

    float* base = nullptr;
    cudaGetSymbolAddress((void**)&base, g_buf);
    float* m    = base + OFF_M;
    __nv_bfloat16* hbf  = (__nv_bfloat16*)(base + OFF_HBF);
    float* qf   = base + OFF_QF;
    float* kf   = base + OFF_KF;
    __nv_bfloat16* qbf  = (__nv_bfloat16*)(base + OFF_QBF);
    __nv_bfloat16* kbf  = (__nv_bfloat16*)(base + OFF_KBF);
    __nv_bfloat16* vbf  = (__nv_bfloat16*)(base + OFF_VBF);
    __nv_bfloat16* abf  = (__nv_bfloat16*)(base + OFF_ABF);
    float* tmp  = base + OFF_TMP;
    float* xmid = base + OFF_XMID;
    float* g1   = base + OFF_G1;
    float* g3   = base + OFF_G3;
    __nv_bfloat16* g1bf = (__nv_bfloat16*)(base + OFF_G1BF);
    __nv_bfloat16* wqT  = (__nv_bfloat16*)(base + OFF_WQT);
    __nv_bfloat16* wkT  = (__nv_bfloat16*)(base + OFF_WKT);
    __nv_bfloat16* wvT  = (__nv_bfloat16*)(base + OFF_WVT);
    __nv_bfloat16* woT  = (__nv_bfloat16*)(base + OFF_WOT);
    __nv_bfloat16* w1T  = (__nv_bfloat16*)(base + OFF_W1T);
    __nv_bfloat16* w3T  = (__nv_bfloat16*)(base + OFF_W3T);
    __nv_bfloat16* w2T  = (__nv_bfloat16*)(base + OFF_W2T);

    cudaFuncSetAttribute(mma_gemm_kernel<false>, cudaFuncAttributeMaxDynamicSharedMemorySize, GSMEM);
    cudaFuncSetAttribute(mma_gemm_kernel<true>,  cudaFuncAttributeMaxDynamicSharedMemorySize, GSMEM);
    cudaFuncSetAttribute(attn_mma_kernel, cudaFuncAttributeMaxDynamicSharedMemorySize, ATT_SMEM);

    dim3 tb32(32, 8);

    adaln_kernel<<<dim3(MCOLS/256, BB), 256>>>(adaln_in, ada_w, ada_b, m);
    transposew_kernel<<<dim3(DIM/32, DIM/32), tb32>>>(wq, wqT, DIM, DIM);
    transposew_kernel<<<dim3(DIM/32, DIM/32), tb32>>>(wk, wkT, DIM, DIM);
    transposew_kernel<<<dim3(DIM/32, DIM/32), tb32>>>(wv, wvT, DIM, DIM);
    transposew_kernel<<<dim3(DIM/32, DIM/32), tb32>>>(wo, woT, DIM, DIM);
    transposew_kernel<<<dim3(HID/32, DIM/32), tb32>>>(w1, w1T, DIM, HID);
    transposew_kernel<<<dim3(HID/32, DIM/32), tb32>>>(w3, w3T, DIM, HID);
    transposew_kernel<<<dim3(DIM/32, HID/32), tb32>>>(w2, w2T, HID, DIM);

    rmsmod_kernel<<<RR, 256>>>(x, attn_norm_w, m, 0, DIM, hbf);

    mma_gemm_kernel<false><<<dim3(DIM/128, RR/128), 256, GSMEM>>>(hbf, wqT, qf, RR, DIM, DIM);
    mma_gemm_kernel<false><<<dim3(DIM/128, RR/128), 256, GSMEM>>>(hbf, wkT, kf, RR, DIM, DIM);
    mma_gemm_kernel<true><<<dim3(DIM/128, RR/128), 256, GSMEM>>>(hbf, wvT, vbf, RR, DIM, DIM);

    lnrope_kernel<<<RR, 256>>>(qf, q_norm_w, q_norm_b, cosT, sinT, qbf);
    lnrope_kernel<<<RR, 256>>>(kf, k_norm_w, k_norm_b, cosT, sinT, kbf);

    attn_mma_kernel<<<dim3(SEQ/128, NH, BB), 256, ATT_SMEM>>>(qbf, kbf, vbf, abf);

    mma_gemm_kernel<false><<<dim3(DIM/128, RR/128), 256, GSMEM>>>(abf, woT, tmp, RR, DIM, DIM);
    resid_kernel<<<(RR*DIM/4)/256, 256>>>(x, tmp, m, 2*DIM, xmid);

    rmsmod_kernel<<<RR, 256>>>(xmid, ffn_norm_w, m, 3*DIM, 4*DIM, hbf);
    mma_gemm_kernel<false><<<dim3(HID/128, RR/128), 256, GSMEM>>>(hbf, w1T, g1, RR, HID, DIM);
    mma_gemm_kernel<false><<<dim3(HID/128, RR/128), 256, GSMEM>>>(hbf, w3T, g3, RR, HID, DIM);
    silugate_kernel<<<(RR*HID/4)/256, 256>>>(g1, g3, g1bf);
    mma_gemm_kernel<false><<<dim3(DIM/128, RR/128), 256, GSMEM>>>(g1bf, w2T, tmp, RR, DIM, HID);
    resid_kernel<<<(RR*DIM/4)/256, 256>>>(xmid, tmp, m, 5*DIM, out);
}

// round 7
// speedup vs baseline: 5.8008x; 1.0527x over previous
#include <cuda_runtime.h>
#include <cuda_bf16.h>
#include <math.h>
#include <stdint.h>

#define BB 2
#define SEQ 2048
#define RR (BB*SEQ)          // 4096 rows
#define DIM 1024
#define HID 2816
#define NH 16
#define HD 64
#define MCOLS (6*DIM)        // 6144

// ---- scratch (float units) ----
#define SZ_M     16384
#define SZ_RD    (RR*DIM)
#define SZ_RDH   (RR*DIM/2)
#define SZ_RHH   (RR*HID/2)
#define SZ_WS    (DIM*DIM/2)
#define SZ_WB    (DIM*HID/2)

#define OFF_M    0
#define OFF_HBF  (OFF_M + SZ_M)
#define OFF_QF   (OFF_HBF + SZ_RDH)
#define OFF_KF   (OFF_QF + SZ_RD)
#define OFF_QBF  (OFF_KF + SZ_RD)
#define OFF_KBF  (OFF_QBF + SZ_RDH)
#define OFF_VBF  (OFF_KBF + SZ_RDH)
#define OFF_ABF  (OFF_VBF + SZ_RDH)
#define OFF_XMID (OFF_ABF + SZ_RDH)
#define OFF_G1BF (OFF_XMID + SZ_RD)
#define OFF_WQT  (OFF_G1BF + SZ_RHH)
#define OFF_WKT  (OFF_WQT + SZ_WS)
#define OFF_WVT  (OFF_WKT + SZ_WS)
#define OFF_WOT  (OFF_WVT + SZ_WS)
#define OFF_W1T  (OFF_WOT + SZ_WS)
#define OFF_W3T  (OFF_W1T + SZ_WB)
#define OFF_W2T  (OFF_W3T + SZ_WB)
#define TOTAL_F  (OFF_W2T + SZ_WB)

__device__ float g_buf[TOTAL_F];

__device__ __forceinline__ uint32_t smem_u32(const void* p) {
    uint32_t a;
    asm("{ .reg .u64 t; cvta.to.shared.u64 t, %1; cvt.u32.u64 %0, t; }" : "=r"(a) : "l"(p));
    return a;
}

// ===========================================================================
// adaLN: m[b,j] = sum_k silu(a[b,k]) * W[k,j] + bias[j]
// ===========================================================================
__global__ __launch_bounds__(256) void adaln_kernel(
    const float* __restrict__ a, const float* __restrict__ W,
    const float* __restrict__ bias, float* __restrict__ m)
{
    __shared__ float act[DIM];
    int b = blockIdx.y;
    int j = blockIdx.x * 256 + threadIdx.x;
    for (int k = threadIdx.x; k < DIM; k += 256) {
        float v = a[b*DIM + k];
        act[k] = v / (1.f + __expf(-v));
    }
    __syncthreads();
    float acc = bias[j];
    #pragma unroll 4
    for (int k = 0; k < DIM; k++)
        acc += act[k] * W[k*MCOLS + j];
    m[b*MCOLS + j] = acc;
}

// ===========================================================================
// weight transpose-convert: W[R,C] fp32 -> Wt[C,R] bf16
// ===========================================================================
__global__ void transposew_kernel(const float* __restrict__ W,
                                  __nv_bfloat16* __restrict__ Wt, int R, int C)
{
    __shared__ float t[32][33];
    int bx = blockIdx.x;
    int by = blockIdx.y;
    int tx = threadIdx.x, ty = threadIdx.y;
    int x = bx*32 + tx;
    for (int yy = ty; yy < 32; yy += 8)
        t[yy][tx] = W[(size_t)(by*32 + yy)*C + x];
    __syncthreads();
    int xo = by*32 + tx;
    for (int yy = ty; yy < 32; yy += 8)
        Wt[(size_t)(bx*32 + yy)*R + xo] = __float2bfloat16(t[tx][yy]);
}

// ===========================================================================
// rmsnorm + modulate -> bf16
// ===========================================================================
__global__ __launch_bounds__(256) void rmsmod_kernel(
    const float* __restrict__ src, const float* __restrict__ w,
    const float* __restrict__ m, int shift_off, int scale_off,
    __nv_bfloat16* __restrict__ dst)
{
    __shared__ float red[256];
    int row = blockIdx.x;
    int b = row >> 11;
    int tid = threadIdx.x;
    float4 v = ((const float4*)(src + (size_t)row*DIM))[tid];
    red[tid] = v.x*v.x + v.y*v.y + v.z*v.z + v.w*v.w;
    __syncthreads();
    for (int s = 128; s > 0; s >>= 1) {
        if (tid < s) red[tid] += red[tid+s];
        __syncthreads();
    }
    float rms = rsqrtf(red[0] * (1.f/DIM) + 1e-5f);
    int d = tid * 4;
    float4 wv = *(const float4*)(w + d);
    float4 sh = *(const float4*)(m + b*MCOLS + shift_off + d);
    float4 sc = *(const float4*)(m + b*MCOLS + scale_off + d);
    float o0 = v.x*rms*wv.x*(1.f+sc.x) + sh.x;
    float o1 = v.y*rms*wv.y*(1.f+sc.y) + sh.y;
    float o2 = v.z*rms*wv.z*(1.f+sc.z) + sh.z;
    float o3 = v.w*rms*wv.w*(1.f+sc.w) + sh.w;
    __nv_bfloat162* dp = (__nv_bfloat162*)(dst + (size_t)row*DIM);
    dp[tid*2]   = __floats2bfloat162_rn(o0, o1);
    dp[tid*2+1] = __floats2bfloat162_rn(o2, o3);
}

// ===========================================================================
// bf16 tensor-core GEMM, 128x128x32 tiles, 3-stage cp.async, 1 sync/iter.
// MODE 0: fp32 C   MODE 1: bf16 C   MODE 2: fp32 C = xres + gate*acc
// ===========================================================================
#define GSMEM (3*16384)

template<int MODE>
__global__ __launch_bounds__(256) void mma_gemm_kernel(
    const __nv_bfloat16* __restrict__ A,
    const __nv_bfloat16* __restrict__ Bt,
    void* __restrict__ Cv,
    const float* __restrict__ xres,
    const float* __restrict__ mvec, int gate_off,
    int M, int N, int K)
{
    extern __shared__ __align__(128) char smch[];
    uint32_t sb = smem_u32(smch);
    int tid = threadIdx.x;
    int wid = tid >> 5, lid = tid & 31;
    int warp_m = wid & 1;
    int warp_n = wid >> 1;
    int row0 = blockIdx.y * 128;
    int col0 = blockIdx.x * 128;
    int iters = K >> 5;

    int r_c0 = tid >> 2,         c_c0 = tid & 3;
    int r_c1 = (tid + 256) >> 2, c_c1 = (tid + 256) & 3;
    uint32_t so0 = r_c0*64 + ((c_c0 ^ ((r_c0 >> 1) & 3)) << 4);
    uint32_t so1 = r_c1*64 + ((c_c1 ^ ((r_c1 >> 1) & 3)) << 4);
    const char* gA0 = (const char*)(A  + (size_t)(row0 + r_c0) * K) + c_c0*16;
    const char* gA1 = (const char*)(A  + (size_t)(row0 + r_c1) * K) + c_c1*16;
    const char* gB0 = (const char*)(Bt + (size_t)(col0 + r_c0) * K) + c_c0*16;
    const char* gB1 = (const char*)(Bt + (size_t)(col0 + r_c1) * K) + c_c1*16;

    float acc[4][4][4];
    #pragma unroll
    for (int i = 0; i < 4; i++)
        #pragma unroll
        for (int j = 0; j < 4; j++)
            #pragma unroll
            for (int q = 0; q < 4; q++) acc[i][j][q] = 0.f;

    uint32_t aAddr[4], bAddr[2];
    {
        int rr = lid & 15;
        int half = lid >> 4;
        #pragma unroll
        for (int mt = 0; mt < 4; mt++) {
            int row = warp_m*64 + mt*16 + rr;
            aAddr[mt] = row*64 + half;
        }
        int mat = lid >> 3, r8 = lid & 7;
        #pragma unroll
        for (int nt2 = 0; nt2 < 2; nt2++) {
            int row = warp_n*32 + nt2*16 + (mat >> 1)*8 + r8;
            bAddr[nt2] = row*64 + (mat & 1);
        }
    }

    // prologue: stages 0,1
    #pragma unroll
    for (int p = 0; p < 2; p++) {
        uint32_t tA = sb + p*16384, tB = tA + 8192;
        size_t kb = (size_t)p * 64;
        asm volatile("cp.async.cg.shared.global [%0], [%1], 16;" :: "r"(tA+so0), "l"(gA0+kb));
        asm volatile("cp.async.cg.shared.global [%0], [%1], 16;" :: "r"(tA+so1), "l"(gA1+kb));
        asm volatile("cp.async.cg.shared.global [%0], [%1], 16;" :: "r"(tB+so0), "l"(gB0+kb));
        asm volatile("cp.async.cg.shared.global [%0], [%1], 16;" :: "r"(tB+so1), "l"(gB1+kb));
        asm volatile("cp.async.commit_group;");
    }

    int sidx = 0, pidx = 2;
    for (int kt = 0; kt < iters; kt++) {
        if (kt < iters-1) asm volatile("cp.async.wait_group 1;" ::: "memory");
        else              asm volatile("cp.async.wait_group 0;" ::: "memory");
        __syncthreads();

        if (kt + 2 < iters) {
            uint32_t tA = sb + pidx*16384, tB = tA + 8192;
            size_t kb = (size_t)(kt + 2) * 64;
            asm volatile("cp.async.cg.shared.global [%0], [%1], 16;" :: "r"(tA+so0), "l"(gA0+kb));
            asm volatile("cp.async.cg.shared.global [%0], [%1], 16;" :: "r"(tA+so1), "l"(gA1+kb));
            asm volatile("cp.async.cg.shared.global [%0], [%1], 16;" :: "r"(tB+so0), "l"(gB0+kb));
            asm volatile("cp.async.cg.shared.global [%0], [%1], 16;" :: "r"(tB+so1), "l"(gB1+kb));
            asm volatile("cp.async.commit_group;");
        }

        uint32_t sA = sb + sidx*16384, sB = sA + 8192;
        #pragma unroll
        for (int ks = 0; ks < 2; ks++) {
            uint32_t a[4][4], b[4][2];
            #pragma unroll
            for (int mt = 0; mt < 4; mt++) {
                int row = (aAddr[mt] >> 6);
                int ck = ks*2 + (aAddr[mt] & 63);
                uint32_t ad = sA + (row*64) + (((ck) ^ ((row >> 1) & 3)) << 4);
                asm volatile("ldmatrix.sync.aligned.m8n8.x4.shared.b16 {%0,%1,%2,%3}, [%4];"
                    : "=r"(a[mt][0]), "=r"(a[mt][1]), "=r"(a[mt][2]), "=r"(a[mt][3]) : "r"(ad));
            }
            #pragma unroll
            for (int nt2 = 0; nt2 < 2; nt2++) {
                int row = (bAddr[nt2] >> 6);
                int ck = ks*2 + (bAddr[nt2] & 63);
                uint32_t ad = sB + (row*64) + (((ck) ^ ((row >> 1) & 3)) << 4);
                asm volatile("ldmatrix.sync.aligned.m8n8.x4.shared.b16 {%0,%1,%2,%3}, [%4];"
                    : "=r"(b[nt2*2][0]), "=r"(b[nt2*2][1]),
                      "=r"(b[nt2*2+1][0]), "=r"(b[nt2*2+1][1]) : "r"(ad));
            }
            #pragma unroll
            for (int mt = 0; mt < 4; mt++)
                #pragma unroll
                for (int nt = 0; nt < 4; nt++) {
                    asm volatile(
                        "mma.sync.aligned.m16n8k16.row.col.f32.bf16.bf16.f32 "
                        "{%0,%1,%2,%3}, {%4,%5,%6,%7}, {%8,%9}, {%0,%1,%2,%3};"
                        : "+f"(acc[mt][nt][0]), "+f"(acc[mt][nt][1]),
                          "+f"(acc[mt][nt][2]), "+f"(acc[mt][nt][3])
                        : "r"(a[mt][0]), "r"(a[mt][1]), "r"(a[mt][2]), "r"(a[mt][3]),
                          "r"(b[nt][0]), "r"(b[nt][1]));
                }
        }
        sidx = (sidx == 2) ? 0 : sidx + 1;
        pidx = (pidx == 2) ? 0 : pidx + 1;
    }

    int lr = lid >> 2;
    int lc = (lid & 3) * 2;
    int bsel = row0 >> 11;
    const float* gv = (MODE == 2) ? (mvec + bsel*MCOLS + gate_off) : nullptr;
    #pragma unroll
    for (int mt = 0; mt < 4; mt++) {
        size_t mrow = (size_t)(row0 + warp_m*64 + mt*16 + lr);
        #pragma unroll
        for (int nt = 0; nt < 4; nt++) {
            int col = col0 + warp_n*32 + nt*8 + lc;
            if (MODE == 1) {
                __nv_bfloat16* C = (__nv_bfloat16*)Cv;
                *(__nv_bfloat162*)(C + mrow*N + col) =
                    __floats2bfloat162_rn(acc[mt][nt][0], acc[mt][nt][1]);
                *(__nv_bfloat162*)(C + (mrow+8)*N + col) =
                    __floats2bfloat162_rn(acc[mt][nt][2], acc[mt][nt][3]);
            } else if (MODE == 2) {
                float* C = (float*)Cv;
                float2 g = *(const float2*)(gv + col);
                float2 x0 = *(const float2*)(xres + mrow*N + col);
                float2 x1 = *(const float2*)(xres + (mrow+8)*N + col);
                *(float2*)(C + mrow*N + col) =
                    make_float2(x0.x + g.x*acc[mt][nt][0], x0.y + g.y*acc[mt][nt][1]);
                *(float2*)(C + (mrow+8)*N + col) =
                    make_float2(x1.x + g.x*acc[mt][nt][2], x1.y + g.y*acc[mt][nt][3]);
            } else {
                float* C = (float*)Cv;
                *(float2*)(C + mrow*N + col) =
                    make_float2(acc[mt][nt][0], acc[mt][nt][1]);
                *(float2*)(C + (mrow+8)*N + col) =
                    make_float2(acc[mt][nt][2], acc[mt][nt][3]);
            }
        }
    }
}

// ===========================================================================
// Fused FFN dual GEMM: g = bf16( silu(A@B1t^T) * (A@B3t^T) )
// tile 128(M) x 64(N), two B operands share the A tile. 3-stage cp.async.
// ===========================================================================
#define FSMEM (3*16384)

__global__ __launch_bounds__(256) void ffn_gemm_kernel(
    const __nv_bfloat16* __restrict__ A,
    const __nv_bfloat16* __restrict__ B1t,
    const __nv_bfloat16* __restrict__ B3t,
    __nv_bfloat16* __restrict__ Og, int M, int N, int K)
{
    extern __shared__ __align__(128) char smch[];
    uint32_t sb = smem_u32(smch);
    int tid = threadIdx.x;
    int wid = tid >> 5, lid = tid & 31;
    int warp_m = wid & 1;          // 2 x 64 rows
    int warp_n = wid >> 1;         // 4 x 16 cols
    int row0 = blockIdx.y * 128;
    int col0 = blockIdx.x * 64;
    int iters = K >> 5;

    // per-stage: A 8192B, B1 4096B, B3 4096B
    int r_c0 = tid >> 2,         c_c0 = tid & 3;
    int r_c1 = (tid + 256) >> 2, c_c1 = (tid + 256) & 3;
    uint32_t so0 = r_c0*64 + ((c_c0 ^ ((r_c0 >> 1) & 3)) << 4);
    uint32_t so1 = r_c1*64 + ((c_c1 ^ ((r_c1 >> 1) & 3)) << 4);
    const char* gA0 = (const char*)(A   + (size_t)(row0 + r_c0) * K) + c_c0*16;
    const char* gA1 = (const char*)(A   + (size_t)(row0 + r_c1) * K) + c_c1*16;
    const char* g1p = (const char*)(B1t + (size_t)(col0 + r_c0) * K) + c_c0*16;
    const char* g3p = (const char*)(B3t + (size_t)(col0 + r_c0) * K) + c_c0*16;

    float acc1[4][2][4], acc3[4][2][4];
    #pragma unroll
    for (int i = 0; i < 4; i++)
        #pragma unroll
        for (int j = 0; j < 2; j++)
            #pragma unroll
            for (int q = 0; q < 4; q++) { acc1[i][j][q] = 0.f; acc3[i][j][q] = 0.f; }

    uint32_t aAddr[4], bAddr;
    {
        int rr = lid & 15;
        int half = lid >> 4;
        #pragma unroll
        for (int mt = 0; mt < 4; mt++) {
            int row = warp_m*64 + mt*16 + rr;
            aAddr[mt] = row*64 + half;
        }
        int mat = lid >> 3, r8 = lid & 7;
        int row = warp_n*16 + (mat >> 1)*8 + r8;
        bAddr = row*64 + (mat & 1);
    }

    #pragma unroll
    for (int p = 0; p < 2; p++) {
        uint32_t tA = sb + p*16384, tB1 = tA + 8192, tB3 = tA + 12288;
        size_t kb = (size_t)p * 64;
        asm volatile("cp.async.cg.shared.global [%0], [%1], 16;" :: "r"(tA+so0),  "l"(gA0+kb));
        asm volatile("cp.async.cg.shared.global [%0], [%1], 16;" :: "r"(tA+so1),  "l"(gA1+kb));
        asm volatile("cp.async.cg.shared.global [%0], [%1], 16;" :: "r"(tB1+so0), "l"(g1p+kb));
        asm volatile("cp.async.cg.shared.global [%0], [%1], 16;" :: "r"(tB3+so0), "l"(g3p+kb));
        asm volatile("cp.async.commit_group;");
    }

    int sidx = 0, pidx = 2;
    for (int kt = 0; kt < iters; kt++) {
        if (kt < iters-1) asm volatile("cp.async.wait_group 1;" ::: "memory");
        else              asm volatile("cp.async.wait_group 0;" ::: "memory");
        __syncthreads();

        if (kt + 2 < iters) {
            uint32_t tA = sb + pidx*16384, tB1 = tA + 8192, tB3 = tA + 12288;
            size_t kb = (size_t)(kt + 2) * 64;
            asm volatile("cp.async.cg.shared.global [%0], [%1], 16;" :: "r"(tA+so0),  "l"(gA0+kb));
            asm volatile("cp.async.cg.shared.global [%0], [%1], 16;" :: "r"(tA+so1),  "l"(gA1+kb));
            asm volatile("cp.async.cg.shared.global [%0], [%1], 16;" :: "r"(tB1+so0), "l"(g1p+kb));
            asm volatile("cp.async.cg.shared.global [%0], [%1], 16;" :: "r"(tB3+so0), "l"(g3p+kb));
            asm volatile("cp.async.commit_group;");
        }

        uint32_t sA = sb + sidx*16384, sB1 = sA + 8192, sB3 = sA + 12288;
        #pragma unroll
        for (int ks = 0; ks < 2; ks++) {
            uint32_t a[4][4];
            #pragma unroll
            for (int mt = 0; mt < 4; mt++) {
                int row = (aAddr[mt] >> 6);
                int ck = ks*2 + (aAddr[mt] & 63);
                uint32_t ad = sA + (row*64) + (((ck) ^ ((row >> 1) & 3)) << 4);
                asm volatile("ldmatrix.sync.aligned.m8n8.x4.shared.b16 {%0,%1,%2,%3}, [%4];"
                    : "=r"(a[mt][0]), "=r"(a[mt][1]), "=r"(a[mt][2]), "=r"(a[mt][3]) : "r"(ad));
            }
            int row = (bAddr >> 6);
            int ck = ks*2 + (bAddr & 63);
            uint32_t swoff = (row*64) + (((ck) ^ ((row >> 1) & 3)) << 4);
            uint32_t b1[4], b3[4];
            asm volatile("ldmatrix.sync.aligned.m8n8.x4.shared.b16 {%0,%1,%2,%3}, [%4];"
                : "=r"(b1[0]), "=r"(b1[1]), "=r"(b1[2]), "=r"(b1[3]) : "r"(sB1 + swoff));
            asm volatile("ldmatrix.sync.aligned.m8n8.x4.shared.b16 {%0,%1,%2,%3}, [%4];"
                : "=r"(b3[0]), "=r"(b3[1]), "=r"(b3[2]), "=r"(b3[3]) : "r"(sB3 + swoff));
            #pragma unroll
            for (int mt = 0; mt < 4; mt++) {
                #pragma unroll
                for (int nt = 0; nt < 2; nt++) {
                    asm volatile(
                        "mma.sync.aligned.m16n8k16.row.col.f32.bf16.bf16.f32 "
                        "{%0,%1,%2,%3}, {%4,%5,%6,%7}, {%8,%9}, {%0,%1,%2,%3};"
                        : "+f"(acc1[mt][nt][0]), "+f"(acc1[mt][nt][1]),
                          "+f"(acc1[mt][nt][2]), "+f"(acc1[mt][nt][3])
                        : "r"(a[mt][0]), "r"(a[mt][1]), "r"(a[mt][2]), "r"(a[mt][3]),
                          "r"(b1[nt*2]), "r"(b1[nt*2+1]));
                    asm volatile(
                        "mma.sync.aligned.m16n8k16.row.col.f32.bf16.bf16.f32 "
                        "{%0,%1,%2,%3}, {%4,%5,%6,%7}, {%8,%9}, {%0,%1,%2,%3};"
                        : "+f"(acc3[mt][nt][0]), "+f"(acc3[mt][nt][1]),
                          "+f"(acc3[mt][nt][2]), "+f"(acc3[mt][nt][3])
                        : "r"(a[mt][0]), "r"(a[mt][1]), "r"(a[mt][2]), "r"(a[mt][3]),
                          "r"(b3[nt*2]), "r"(b3[nt*2+1]));
                }
            }
        }
        sidx = (sidx == 2) ? 0 : sidx + 1;
        pidx = (pidx == 2) ? 0 : pidx + 1;
    }

    int lr = lid >> 2;
    int lc = (lid & 3) * 2;
    #pragma unroll
    for (int mt = 0; mt < 4; mt++) {
        size_t mrow = (size_t)(row0 + warp_m*64 + mt*16 + lr);
        #pragma unroll
        for (int nt = 0; nt < 2; nt++) {
            int col = col0 + warp_n*16 + nt*8 + lc;
            float s0 = acc1[mt][nt][0], s1 = acc1[mt][nt][1];
            float s2 = acc1[mt][nt][2], s3 = acc1[mt][nt][3];
            float o0 = s0 / (1.f + __expf(-s0)) * acc3[mt][nt][0];
            float o1 = s1 / (1.f + __expf(-s1)) * acc3[mt][nt][1];
            float o2 = s2 / (1.f + __expf(-s2)) * acc3[mt][nt][2];
            float o3 = s3 / (1.f + __expf(-s3)) * acc3[mt][nt][3];
            *(__nv_bfloat162*)(Og + mrow*N + col)     = __floats2bfloat162_rn(o0, o1);
            *(__nv_bfloat162*)(Og + (mrow+8)*N + col) = __floats2bfloat162_rn(o2, o3);
        }
    }
}

// ===========================================================================
// layernorm + RoPE: read fp32, write bf16
// ===========================================================================
__global__ __launch_bounds__(256) void lnrope_kernel(
    const float* __restrict__ t, const float* __restrict__ w, const float* __restrict__ bvec,
    const float* __restrict__ cosT, const float* __restrict__ sinT,
    __nv_bfloat16* __restrict__ dst)
{
    __shared__ float redm[256], redv[256];
    int row = blockIdx.x;
    int s = row & (SEQ-1);
    int tid = threadIdx.x;
    float4 v = ((const float4*)(t + (size_t)row*DIM))[tid];
    redm[tid] = v.x + v.y + v.z + v.w;
    redv[tid] = v.x*v.x + v.y*v.y + v.z*v.z + v.w*v.w;
    __syncthreads();
    for (int st = 128; st > 0; st >>= 1) {
        if (tid < st) { redm[tid] += redm[tid+st]; redv[tid] += redv[tid+st]; }
        __syncthreads();
    }
    float mu = redm[0] * (1.f/DIM);
    float var = redv[0] * (1.f/DIM) - mu*mu;
    float rs = rsqrtf(var + 1e-5f);
    int d = tid*4;
    float4 wv = *(const float4*)(w + d);
    float4 bv = *(const float4*)(bvec + d);
    float y0 = (v.x-mu)*rs*wv.x + bv.x;
    float y1 = (v.y-mu)*rs*wv.y + bv.y;
    float y2 = (v.z-mu)*rs*wv.z + bv.z;
    float y3 = (v.w-mu)*rs*wv.w + bv.w;
    int i0 = (d & 63) >> 1;
    float c0 = cosT[s*32 + i0],   s0 = sinT[s*32 + i0];
    float c1 = cosT[s*32 + i0+1], s1 = sinT[s*32 + i0+1];
    float o0 = y0*c0 - y1*s0;
    float o1 = y0*s0 + y1*c0;
    float o2 = y2*c1 - y3*s1;
    float o3 = y2*s1 + y3*c1;
    __nv_bfloat162* dp = (__nv_bfloat162*)(dst + (size_t)row*DIM);
    dp[tid*2]   = __floats2bfloat162_rn(o0, o1);
    dp[tid*2+1] = __floats2bfloat162_rn(o2, o3);
}

// ===========================================================================
// Tensor-core flash attention (bf16 in, fp32 accum, bf16 out)
// ===========================================================================
#define ATT_SMEM 49152

__global__ __launch_bounds__(256, 1) void attn_mma_kernel(
    const __nv_bfloat16* __restrict__ q, const __nv_bfloat16* __restrict__ k,
    const __nv_bfloat16* __restrict__ v, __nv_bfloat16* __restrict__ o)
{
    extern __shared__ __align__(128) char smch[];
    uint32_t sb = smem_u32(smch);
    const uint32_t sq  = sb;
    const uint32_t sk0 = sb + 16384;
    const uint32_t sv0 = sb + 32768;
    int tid = threadIdx.x, wid = tid >> 5, lid = tid & 31;
    int qt = blockIdx.x, h = blockIdx.y, b = blockIdx.z;
    int hoffb = h * HD * 2;
    int qbase = b*SEQ + qt*128;
    int kbb   = b*SEQ;

    #pragma unroll
    for (int i = 0; i < 4; i++) {
        int cid = tid + 256*i;
        int row = cid >> 3, ch = cid & 7;
        const char* g = (const char*)(q + (size_t)(qbase+row)*DIM) + hoffb + ch*16;
        uint32_t so = sq + row*128 + ((ch ^ (row & 7)) << 4);
        asm volatile("cp.async.cg.shared.global [%0], [%1], 16;" :: "r"(so), "l"(g));
    }
    #pragma unroll
    for (int i = 0; i < 2; i++) {
        int cid = tid + 256*i;
        int row = cid >> 3, ch = cid & 7;
        uint32_t so = row*128 + ((ch ^ (row & 7)) << 4);
        const char* gk = (const char*)(k + (size_t)(kbb+row)*DIM) + hoffb + ch*16;
        const char* gv = (const char*)(v + (size_t)(kbb+row)*DIM) + hoffb + ch*16;
        asm volatile("cp.async.cg.shared.global [%0], [%1], 16;" :: "r"(sk0+so), "l"(gk));
        asm volatile("cp.async.cg.shared.global [%0], [%1], 16;" :: "r"(sv0+so), "l"(gv));
    }
    asm volatile("cp.async.commit_group;");

    int wr = wid * 16;
    uint32_t qf[4][4];
    float oacc[8][4];
    #pragma unroll
    for (int j = 0; j < 8; j++)
        #pragma unroll
        for (int i = 0; i < 4; i++) oacc[j][i] = 0.f;
    float m0 = -INFINITY, m1 = -INFINITY, l0 = 0.f, l1 = 0.f;

    for (int kt = 0; kt < SEQ/64; kt++) {
        int s = kt & 1;
        if (kt + 1 < SEQ/64) {
            int ns = s ^ 1;
            int kb2 = kbb + (kt+1)*64;
            #pragma unroll
            for (int i = 0; i < 2; i++) {
                int cid = tid + 256*i;
                int row = cid >> 3, ch = cid & 7;
                uint32_t so = row*128 + ((ch ^ (row & 7)) << 4);
                const char* gk = (const char*)(k + (size_t)(kb2+row)*DIM) + hoffb + ch*16;
                const char* gv = (const char*)(v + (size_t)(kb2+row)*DIM) + hoffb + ch*16;
                asm volatile("cp.async.cg.shared.global [%0], [%1], 16;" :: "r"(sk0+ns*8192+so), "l"(gk));
                asm volatile("cp.async.cg.shared.global [%0], [%1], 16;" :: "r"(sv0+ns*8192+so), "l"(gv));
            }
            asm volatile("cp.async.commit_group;");
            asm volatile("cp.async.wait_group 1;" ::: "memory");
        } else {
            asm volatile("cp.async.wait_group 0;" ::: "memory");
        }
        __syncthreads();

        if (kt == 0) {
            int arow = wr + (lid & 15);
            #pragma unroll
            for (int s2 = 0; s2 < 4; s2++) {
                int ch = 2*s2 + (lid >> 4);
                uint32_t ad = sq + arow*128 + ((ch ^ (arow & 7)) << 4);
                asm volatile("ldmatrix.sync.aligned.m8n8.x4.shared.b16 {%0,%1,%2,%3}, [%4];"
                    : "=r"(qf[s2][0]), "=r"(qf[s2][1]), "=r"(qf[s2][2]), "=r"(qf[s2][3]) : "r"(ad));
            }
        }
        uint32_t skst = sk0 + s*8192, svst = sv0 + s*8192;

        float sa[8][4];
        #pragma unroll
        for (int j = 0; j < 8; j++)
            #pragma unroll
            for (int i = 0; i < 4; i++) sa[j][i] = 0.f;

        #pragma unroll
        for (int s2 = 0; s2 < 4; s2++) {
            #pragma unroll
            for (int p = 0; p < 4; p++) {
                int mat = lid >> 3;
                int krow = p*16 + ((mat >> 1) << 3) + (lid & 7);
                int ch = 2*s2 + (mat & 1);
                uint32_t ad = skst + krow*128 + ((ch ^ (krow & 7)) << 4);
                uint32_t b0, b1, b2, b3;
                asm volatile("ldmatrix.sync.aligned.m8n8.x4.shared.b16 {%0,%1,%2,%3}, [%4];"
                    : "=r"(b0), "=r"(b1), "=r"(b2), "=r"(b3) : "r"(ad));
                asm volatile(
                    "mma.sync.aligned.m16n8k16.row.col.f32.bf16.bf16.f32 "
                    "{%0,%1,%2,%3}, {%4,%5,%6,%7}, {%8,%9}, {%0,%1,%2,%3};"
                    : "+f"(sa[2*p][0]), "+f"(sa[2*p][1]), "+f"(sa[2*p][2]), "+f"(sa[2*p][3])
                    : "r"(qf[s2][0]), "r"(qf[s2][1]), "r"(qf[s2][2]), "r"(qf[s2][3]),
                      "r"(b0), "r"(b1));
                asm volatile(
                    "mma.sync.aligned.m16n8k16.row.col.f32.bf16.bf16.f32 "
                    "{%0,%1,%2,%3}, {%4,%5,%6,%7}, {%8,%9}, {%0,%1,%2,%3};"
                    : "+f"(sa[2*p+1][0]), "+f"(sa[2*p+1][1]), "+f"(sa[2*p+1][2]), "+f"(sa[2*p+1][3])
                    : "r"(qf[s2][0]), "r"(qf[s2][1]), "r"(qf[s2][2]), "r"(qf[s2][3]),
                      "r"(b2), "r"(b3));
            }
        }

        float mx0 = -INFINITY, mx1 = -INFINITY;
        #pragma unroll
        for (int j = 0; j < 8; j++) {
            sa[j][0] *= 0.125f; sa[j][1] *= 0.125f;
            sa[j][2] *= 0.125f; sa[j][3] *= 0.125f;
            mx0 = fmaxf(mx0, fmaxf(sa[j][0], sa[j][1]));
            mx1 = fmaxf(mx1, fmaxf(sa[j][2], sa[j][3]));
        }
        mx0 = fmaxf(mx0, __shfl_xor_sync(0xffffffffu, mx0, 1));
        mx0 = fmaxf(mx0, __shfl_xor_sync(0xffffffffu, mx0, 2));
        mx1 = fmaxf(mx1, __shfl_xor_sync(0xffffffffu, mx1, 1));
        mx1 = fmaxf(mx1, __shfl_xor_sync(0xffffffffu, mx1, 2));
        float nm0 = fmaxf(m0, mx0), nm1 = fmaxf(m1, mx1);

        float ps0 = 0.f, ps1 = 0.f;
        uint32_t pf[4][4];
        #pragma unroll
        for (int j = 0; j < 8; j++) {
            float e0 = __expf(sa[j][0] - nm0);
            float e1 = __expf(sa[j][1] - nm0);
            float e2 = __expf(sa[j][2] - nm1);
            float e3 = __expf(sa[j][3] - nm1);
            ps0 += e0 + e1; ps1 += e2 + e3;
            int s2 = j >> 1;
            __nv_bfloat162 lo = __floats2bfloat162_rn(e0, e1);
            __nv_bfloat162 hi = __floats2bfloat162_rn(e2, e3);
            if ((j & 1) == 0) {
                pf[s2][0] = *(uint32_t*)&lo;
                pf[s2][1] = *(uint32_t*)&hi;
            } else {
                pf[s2][2] = *(uint32_t*)&lo;
                pf[s2][3] = *(uint32_t*)&hi;
            }
        }
        ps0 += __shfl_xor_sync(0xffffffffu, ps0, 1);
        ps0 += __shfl_xor_sync(0xffffffffu, ps0, 2);
        ps1 += __shfl_xor_sync(0xffffffffu, ps1, 1);
        ps1 += __shfl_xor_sync(0xffffffffu, ps1, 2);

        float c0 = __expf(m0 - nm0), c1 = __expf(m1 - nm1);
        l0 = l0*c0 + ps0;  l1 = l1*c1 + ps1;
        m0 = nm0;  m1 = nm1;
        #pragma unroll
        for (int j = 0; j < 8; j++) {
            oacc[j][0] *= c0; oacc[j][1] *= c0;
            oacc[j][2] *= c1; oacc[j][3] *= c1;
        }

        #pragma unroll
        for (int s2 = 0; s2 < 4; s2++) {
            #pragma unroll
            for (int p = 0; p < 4; p++) {
                int mat = lid >> 3;
                int vrow = s2*16 + ((mat & 1) << 3) + (lid & 7);
                int ch = 2*p + (mat >> 1);
                uint32_t ad = svst + vrow*128 + ((ch ^ (vrow & 7)) << 4);
                uint32_t v0, v1, v2, v3;
                asm volatile("ldmatrix.sync.aligned.m8n8.x4.trans.shared.b16 {%0,%1,%2,%3}, [%4];"
                    : "=r"(v0), "=r"(v1), "=r"(v2), "=r"(v3) : "r"(ad));
                asm volatile(
                    "mma.sync.aligned.m16n8k16.row.col.f32.bf16.bf16.f32 "
                    "{%0,%1,%2,%3}, {%4,%5,%6,%7}, {%8,%9}, {%0,%1,%2,%3};"
                    : "+f"(oacc[2*p][0]), "+f"(oacc[2*p][1]), "+f"(oacc[2*p][2]), "+f"(oacc[2*p][3])
                    : "r"(pf[s2][0]), "r"(pf[s2][1]), "r"(pf[s2][2]), "r"(pf[s2][3]),
                      "r"(v0), "r"(v1));
                asm volatile(
                    "mma.sync.aligned.m16n8k16.row.col.f32.bf16.bf16.f32 "
                    "{%0,%1,%2,%3}, {%4,%5,%6,%7}, {%8,%9}, {%0,%1,%2,%3};"
                    : "+f"(oacc[2*p+1][0]), "+f"(oacc[2*p+1][1]), "+f"(oacc[2*p+1][2]), "+f"(oacc[2*p+1][3])
                    : "r"(pf[s2][0]), "r"(pf[s2][1]), "r"(pf[s2][2]), "r"(pf[s2][3]),
                      "r"(v2), "r"(v3));
            }
        }
        __syncthreads();
    }

    float inv0 = 1.f / l0, inv1 = 1.f / l1;
    int r = lid >> 2, c2 = (lid & 3) * 2;
    size_t row0 = (size_t)(qbase + wr + r)*DIM + h*HD + c2;
    size_t row1 = row0 + 8*DIM;
    #pragma unroll
    for (int j = 0; j < 8; j++) {
        *(__nv_bfloat162*)(o + row0 + 8*j) =
            __floats2bfloat162_rn(oacc[j][0]*inv0, oacc[j][1]*inv0);
        *(__nv_bfloat162*)(o + row1 + 8*j) =
            __floats2bfloat162_rn(oacc[j][2]*inv1, oacc[j][3]*inv1);
    }
}

// ===========================================================================
extern "C" void kernel_launch(void* const* d_in, const int* in_sizes, int n_in,
                              void* d_out, int out_size)
{
    const float* x        = (const float*)d_in[0];
    const float* adaln_in = (const float*)d_in[1];
    const float* cosT     = (const float*)d_in[2];
    const float* sinT     = (const float*)d_in[3];
    const float* wq       = (const float*)d_in[4];
    const float* wk       = (const float*)d_in[5];
    const float* wv       = (const float*)d_in[6];
    const float* wo       = (const float*)d_in[7];
    const float* q_norm_w = (const float*)d_in[8];
    const float* q_norm_b = (const float*)d_in[9];
    const float* k_norm_w = (const float*)d_in[10];
    const float* k_norm_b = (const float*)d_in[11];
    const float* attn_norm_w = (const float*)d_in[12];
    const float* ffn_norm_w  = (const float*)d_in[13];
    const float* ada_w    = (const float*)d_in[14];
    const float* ada_b    = (const float*)d_in[15];
    const float* w1       = (const float*)d_in[16];
    const float* w2       = (const float*)d_in[17];
    const float* w3       = (const float*)d_in[18];
    float* out = (float*)d_out;

    float* base = nullptr;
    cudaGetSymbolAddress((void**)&base, g_buf);
    float* m    = base + OFF_M;
    __nv_bfloat16* hbf  = (__nv_bfloat16*)(base + OFF_HBF);
    float* qf   = base + OFF_QF;
    float* kf   = base + OFF_KF;
    __nv_bfloat16* qbf  = (__nv_bfloat16*)(base + OFF_QBF);
    __nv_bfloat16* kbf  = (__nv_bfloat16*)(base + OFF_KBF);
    __nv_bfloat16* vbf  = (__nv_bfloat16*)(base + OFF_VBF);
    __nv_bfloat16* abf  = (__nv_bfloat16*)(base + OFF_ABF);
    float* xmid = base + OFF_XMID;
    __nv_bfloat16* g1bf = (__nv_bfloat16*)(base + OFF_G1BF);
    __nv_bfloat16* wqT  = (__nv_bfloat16*)(base + OFF_WQT);
    __nv_bfloat16* wkT  = (__nv_bfloat16*)(base + OFF_WKT);
    __nv_bfloat16* wvT  = (__nv_bfloat16*)(base + OFF_WVT);
    __nv_bfloat16* woT  = (__nv_bfloat16*)(base + OFF_WOT);
    __nv_bfloat16* w1T  = (__nv_bfloat16*)(base + OFF_W1T);
    __nv_bfloat16* w3T  = (__nv_bfloat16*)(base + OFF_W3T);
    __nv_bfloat16* w2T  = (__nv_bfloat16*)(base + OFF_W2T);

    cudaFuncSetAttribute(mma_gemm_kernel<0>, cudaFuncAttributeMaxDynamicSharedMemorySize, GSMEM);
    cudaFuncSetAttribute(mma_gemm_kernel<1>, cudaFuncAttributeMaxDynamicSharedMemorySize, GSMEM);
    cudaFuncSetAttribute(mma_gemm_kernel<2>, cudaFuncAttributeMaxDynamicSharedMemorySize, GSMEM);
    cudaFuncSetAttribute(ffn_gemm_kernel, cudaFuncAttributeMaxDynamicSharedMemorySize, FSMEM);
    cudaFuncSetAttribute(attn_mma_kernel, cudaFuncAttributeMaxDynamicSharedMemorySize, ATT_SMEM);

    dim3 tb32(32, 8);

    // launches 1-5 (ncu -s 5 -c 1 profiles launch #6 = Q GEMM)
    adaln_kernel<<<dim3(MCOLS/256, BB), 256>>>(adaln_in, ada_w, ada_b, m);
    transposew_kernel<<<dim3(DIM/32, DIM/32), tb32>>>(wq, wqT, DIM, DIM);
    transposew_kernel<<<dim3(DIM/32, DIM/32), tb32>>>(wk, wkT, DIM, DIM);
    transposew_kernel<<<dim3(DIM/32, DIM/32), tb32>>>(wv, wvT, DIM, DIM);
    rmsmod_kernel<<<RR, 256>>>(x, attn_norm_w, m, 0, DIM, hbf);

    // launch 6: profiled
    mma_gemm_kernel<0><<<dim3(DIM/128, RR/128), 256, GSMEM>>>(hbf, wqT, qf, nullptr, nullptr, 0, RR, DIM, DIM);
    mma_gemm_kernel<0><<<dim3(DIM/128, RR/128), 256, GSMEM>>>(hbf, wkT, kf, nullptr, nullptr, 0, RR, DIM, DIM);
    mma_gemm_kernel<1><<<dim3(DIM/128, RR/128), 256, GSMEM>>>(hbf, wvT, vbf, nullptr, nullptr, 0, RR, DIM, DIM);

    // remaining weight transposes (needed later)
    transposew_kernel<<<dim3(DIM/32, DIM/32), tb32>>>(wo, woT, DIM, DIM);
    transposew_kernel<<<dim3(HID/32, DIM/32), tb32>>>(w1, w1T, DIM, HID);
    transposew_kernel<<<dim3(HID/32, DIM/32), tb32>>>(w3, w3T, DIM, HID);
    transposew_kernel<<<dim3(DIM/32, HID/32), tb32>>>(w2, w2T, HID, DIM);

    lnrope_kernel<<<RR, 256>>>(qf, q_norm_w, q_norm_b, cosT, sinT, qbf);
    lnrope_kernel<<<RR, 256>>>(kf, k_norm_w, k_norm_b, cosT, sinT, kbf);

    attn_mma_kernel<<<dim3(SEQ/128, NH, BB), 256, ATT_SMEM>>>(qbf, kbf, vbf, abf);

    // wo projection with fused gated residual: xmid = x + gate_msa * (attn@wo)
    mma_gemm_kernel<2><<<dim3(DIM/128, RR/128), 256, GSMEM>>>(abf, woT, xmid, x, m, 2*DIM, RR, DIM, DIM);

    rmsmod_kernel<<<RR, 256>>>(xmid, ffn_norm_w, m, 3*DIM, 4*DIM, hbf);

    // fused dual FFN gemm: g1bf = bf16(silu(h@w1) * (h@w3))
    ffn_gemm_kernel<<<dim3(HID/64, RR/128), 256, FSMEM>>>(hbf, w1T, w3T, g1bf, RR, HID, DIM);

    // w2 projection with fused gated residual: out = xmid + gate_mlp * (g@w2)
    mma_gemm_kernel<2><<<dim3(DIM/128, RR/128), 256, GSMEM>>>(g1bf, w2T, out, xmid, m, 5*DIM, RR, DIM, HID);
}

// round 8
// speedup vs baseline: 6.2433x; 1.0763x over previous
#include <cuda_runtime.h>
#include <cuda_bf16.h>
#include <math.h>
#include <stdint.h>

#define BB 2
#define SEQ 2048
#define RR (BB*SEQ)          // 4096 rows
#define DIM 1024
#define HID 2816
#define NH 16
#define HD 64
#define MCOLS (6*DIM)        // 6144

// ---- scratch (float units) ----
#define SZ_M     16384
#define SZ_RD    (RR*DIM)
#define SZ_RDH   (RR*DIM/2)
#define SZ_RHH   (RR*HID/2)
#define SZ_WS    (DIM*DIM/2)
#define SZ_WB    (DIM*HID/2)

#define OFF_M    0
#define OFF_HBF  (OFF_M + SZ_M)
#define OFF_QF   (OFF_HBF + SZ_RDH)
#define OFF_KF   (OFF_QF + SZ_RD)
#define OFF_QBF  (OFF_KF + SZ_RD)
#define OFF_KBF  (OFF_QBF + SZ_RDH)
#define OFF_VBF  (OFF_KBF + SZ_RDH)
#define OFF_ABF  (OFF_VBF + SZ_RDH)
#define OFF_XMID (OFF_ABF + SZ_RDH)
#define OFF_G1BF (OFF_XMID + SZ_RD)
#define OFF_WQC  (OFF_G1BF + SZ_RHH)
#define OFF_WKC  (OFF_WQC + SZ_WS)
#define OFF_WVC  (OFF_WKC + SZ_WS)
#define OFF_WOC  (OFF_WVC + SZ_WS)
#define OFF_W1C  (OFF_WOC + SZ_WS)
#define OFF_W3C  (OFF_W1C + SZ_WB)
#define OFF_W2C  (OFF_W3C + SZ_WB)
#define TOTAL_F  (OFF_W2C + SZ_WB)

__device__ float g_buf[TOTAL_F];

__device__ __forceinline__ uint32_t smem_u32(const void* p) {
    uint32_t a;
    asm("{ .reg .u64 t; cvta.to.shared.u64 t, %1; cvt.u32.u64 %0, t; }" : "=r"(a) : "l"(p));
    return a;
}

// ===========================================================================
// adaLN: m[b,j] = sum_k silu(a[b,k]) * W[k,j] + bias[j]
// ===========================================================================
__global__ __launch_bounds__(256) void adaln_kernel(
    const float* __restrict__ a, const float* __restrict__ W,
    const float* __restrict__ bias, float* __restrict__ m)
{
    __shared__ float act[DIM];
    int b = blockIdx.y;
    int j = blockIdx.x * 256 + threadIdx.x;
    for (int k = threadIdx.x; k < DIM; k += 256) {
        float v = a[b*DIM + k];
        act[k] = v / (1.f + __expf(-v));
    }
    __syncthreads();
    float acc = bias[j];
    #pragma unroll 4
    for (int k = 0; k < DIM; k++)
        acc += act[k] * W[k*MCOLS + j];
    m[b*MCOLS + j] = acc;
}

// ===========================================================================
// streaming fp32 -> bf16 converts (same layout), 2 or 3 matrices per launch
// ===========================================================================
__device__ __forceinline__ void conv8(const float* s, __nv_bfloat16* d, int i) {
    float4 a = *(const float4*)(s + i);
    float4 b = *(const float4*)(s + i + 4);
    __nv_bfloat162 p0 = __floats2bfloat162_rn(a.x, a.y);
    __nv_bfloat162 p1 = __floats2bfloat162_rn(a.z, a.w);
    __nv_bfloat162 p2 = __floats2bfloat162_rn(b.x, b.y);
    __nv_bfloat162 p3 = __floats2bfloat162_rn(b.z, b.w);
    uint4 o;
    o.x = *(uint32_t*)&p0; o.y = *(uint32_t*)&p1;
    o.z = *(uint32_t*)&p2; o.w = *(uint32_t*)&p3;
    *(uint4*)(d + i) = o;
}

__global__ __launch_bounds__(256) void convert2_kernel(
    const float* __restrict__ s0, const float* __restrict__ s1,
    __nv_bfloat16* __restrict__ d0, __nv_bfloat16* __restrict__ d1)
{
    const float* s = blockIdx.y ? s1 : s0;
    __nv_bfloat16* d = blockIdx.y ? d1 : d0;
    conv8(s, d, (blockIdx.x*256 + threadIdx.x)*8);
}

__global__ __launch_bounds__(256) void convert3_kernel(
    const float* __restrict__ s0, const float* __restrict__ s1, const float* __restrict__ s2,
    __nv_bfloat16* __restrict__ d0, __nv_bfloat16* __restrict__ d1, __nv_bfloat16* __restrict__ d2)
{
    const float* s = (blockIdx.y == 0) ? s0 : (blockIdx.y == 1) ? s1 : s2;
    __nv_bfloat16* d = (blockIdx.y == 0) ? d0 : (blockIdx.y == 1) ? d1 : d2;
    conv8(s, d, (blockIdx.x*256 + threadIdx.x)*8);
}

// ===========================================================================
// rmsnorm + modulate -> bf16
// ===========================================================================
__global__ __launch_bounds__(256) void rmsmod_kernel(
    const float* __restrict__ src, const float* __restrict__ w,
    const float* __restrict__ m, int shift_off, int scale_off,
    __nv_bfloat16* __restrict__ dst)
{
    __shared__ float red[256];
    int row = blockIdx.x;
    int b = row >> 11;
    int tid = threadIdx.x;
    float4 v = ((const float4*)(src + (size_t)row*DIM))[tid];
    red[tid] = v.x*v.x + v.y*v.y + v.z*v.z + v.w*v.w;
    __syncthreads();
    for (int s = 128; s > 0; s >>= 1) {
        if (tid < s) red[tid] += red[tid+s];
        __syncthreads();
    }
    float rms = rsqrtf(red[0] * (1.f/DIM) + 1e-5f);
    int d = tid * 4;
    float4 wv = *(const float4*)(w + d);
    float4 sh = *(const float4*)(m + b*MCOLS + shift_off + d);
    float4 sc = *(const float4*)(m + b*MCOLS + scale_off + d);
    float o0 = v.x*rms*wv.x*(1.f+sc.x) + sh.x;
    float o1 = v.y*rms*wv.y*(1.f+sc.y) + sh.y;
    float o2 = v.z*rms*wv.z*(1.f+sc.z) + sh.z;
    float o3 = v.w*rms*wv.w*(1.f+sc.w) + sh.w;
    __nv_bfloat162* dp = (__nv_bfloat162*)(dst + (size_t)row*DIM);
    dp[tid*2]   = __floats2bfloat162_rn(o0, o1);
    dp[tid*2+1] = __floats2bfloat162_rn(o2, o3);
}

// ===========================================================================
// Shared GEMM building blocks (A [M,K] k-contig bf16; B [K,N] n-contig bf16)
// A tile: 128 rows x 64B (32 bf16).  B tile: 32 rows x 256B (128 bf16).
// B fragments via ldmatrix.x4.trans (same pattern as attention V path).
// ===========================================================================
#define GSMEM (3*16384)

// MODE 2: fp32 C = xres + gate*acc   MODE 3: fused QKV (3 outputs)
template<int MODE>
__global__ __launch_bounds__(256) void mma_gemm_kernel(
    const __nv_bfloat16* __restrict__ A,
    const __nv_bfloat16* __restrict__ B0,
    const __nv_bfloat16* __restrict__ B1m,
    const __nv_bfloat16* __restrict__ B2m,
    int ldb,
    float* __restrict__ Cf,            // MODE2 out / MODE3 qf
    float* __restrict__ kf,            // MODE3 kf
    __nv_bfloat16* __restrict__ vbf,   // MODE3 vbf
    const float* __restrict__ xres,
    const float* __restrict__ mvec, int gate_off,
    int M, int N, int K)
{
    extern __shared__ __align__(128) char smch[];
    uint32_t sb = smem_u32(smch);
    int tid = threadIdx.x;
    int wid = tid >> 5, lid = tid & 31;
    int warp_m = wid & 1;
    int warp_n = wid >> 1;
    int row0 = blockIdx.y * 128;
    int col0 = blockIdx.x * 128;
    int iters = K >> 5;

    const __nv_bfloat16* B = B0;
    int msel = 0, colB = col0;
    if (MODE == 3) {
        msel = col0 >> 10;
        colB = col0 & 1023;
        B = (msel == 0) ? B0 : (msel == 1) ? B1m : B2m;
    }

    // A chunk slots (2 per thread)
    int ra0 = tid >> 2,          ca0 = tid & 3;
    int ra1 = (tid + 256) >> 2,  ca1 = (tid + 256) & 3;
    uint32_t soA0 = ra0*64 + ((ca0 ^ ((ra0 >> 1) & 3)) << 4);
    uint32_t soA1 = ra1*64 + ((ca1 ^ ((ra1 >> 1) & 3)) << 4);
    const char* gA0 = (const char*)(A + (size_t)(row0 + ra0)*K) + ca0*16;
    const char* gA1 = (const char*)(A + (size_t)(row0 + ra1)*K) + ca1*16;
    // B chunk slots (2 per thread): row rb (k), chunk cb (n/8)
    int rb0 = tid >> 4,          cb0 = tid & 15;
    int rb1 = (tid + 256) >> 4,  cb1 = (tid + 256) & 15;
    uint32_t soB0 = rb0*256 + ((cb0 ^ (rb0 & 7)) << 4);
    uint32_t soB1 = rb1*256 + ((cb1 ^ (rb1 & 7)) << 4);
    const char* gB0 = (const char*)(B + (size_t)rb0*ldb + colB) + cb0*16;
    const char* gB1 = (const char*)(B + (size_t)rb1*ldb + colB) + cb1*16;
    size_t bstep = (size_t)32 * ldb * 2;

    float acc[4][4][4];
    #pragma unroll
    for (int i = 0; i < 4; i++)
        #pragma unroll
        for (int j = 0; j < 4; j++)
            #pragma unroll
            for (int q = 0; q < 4; q++) acc[i][j][q] = 0.f;

    uint32_t aAddr[4];
    {
        int rr = lid & 15;
        int half = lid >> 4;
        #pragma unroll
        for (int mt = 0; mt < 4; mt++) {
            int row = warp_m*64 + mt*16 + rr;
            aAddr[mt] = row*64 + half;
        }
    }
    int matq = lid >> 3, r8 = lid & 7;

    #pragma unroll
    for (int p = 0; p < 2; p++) {
        uint32_t tA = sb + p*16384, tB = tA + 8192;
        asm volatile("cp.async.cg.shared.global [%0], [%1], 16;" :: "r"(tA+soA0), "l"(gA0 + p*64));
        asm volatile("cp.async.cg.shared.global [%0], [%1], 16;" :: "r"(tA+soA1), "l"(gA1 + p*64));
        asm volatile("cp.async.cg.shared.global [%0], [%1], 16;" :: "r"(tB+soB0), "l"(gB0 + p*bstep));
        asm volatile("cp.async.cg.shared.global [%0], [%1], 16;" :: "r"(tB+soB1), "l"(gB1 + p*bstep));
        asm volatile("cp.async.commit_group;");
    }

    int sidx = 0, pidx = 2;
    for (int kt = 0; kt < iters; kt++) {
        if (kt < iters-1) asm volatile("cp.async.wait_group 1;" ::: "memory");
        else              asm volatile("cp.async.wait_group 0;" ::: "memory");
        __syncthreads();

        if (kt + 2 < iters) {
            uint32_t tA = sb + pidx*16384, tB = tA + 8192;
            size_t ka = (size_t)(kt + 2) * 64;
            size_t kb = (size_t)(kt + 2) * bstep;
            asm volatile("cp.async.cg.shared.global [%0], [%1], 16;" :: "r"(tA+soA0), "l"(gA0+ka));
            asm volatile("cp.async.cg.shared.global [%0], [%1], 16;" :: "r"(tA+soA1), "l"(gA1+ka));
            asm volatile("cp.async.cg.shared.global [%0], [%1], 16;" :: "r"(tB+soB0), "l"(gB0+kb));
            asm volatile("cp.async.cg.shared.global [%0], [%1], 16;" :: "r"(tB+soB1), "l"(gB1+kb));
            asm volatile("cp.async.commit_group;");
        }

        uint32_t sA = sb + sidx*16384, sB = sA + 8192;
        #pragma unroll
        for (int ks = 0; ks < 2; ks++) {
            uint32_t a[4][4], b[4][2];
            #pragma unroll
            for (int mt = 0; mt < 4; mt++) {
                int row = (aAddr[mt] >> 6);
                int ck = ks*2 + (aAddr[mt] & 63);
                uint32_t ad = sA + (row*64) + (((ck) ^ ((row >> 1) & 3)) << 4);
                asm volatile("ldmatrix.sync.aligned.m8n8.x4.shared.b16 {%0,%1,%2,%3}, [%4];"
                    : "=r"(a[mt][0]), "=r"(a[mt][1]), "=r"(a[mt][2]), "=r"(a[mt][3]) : "r"(ad));
            }
            #pragma unroll
            for (int nt2 = 0; nt2 < 2; nt2++) {
                int krow = ks*16 + ((matq & 1) << 3) + r8;
                int ch = warp_n*4 + nt2*2 + (matq >> 1);
                uint32_t ad = sB + krow*256 + ((ch ^ (krow & 7)) << 4);
                asm volatile("ldmatrix.sync.aligned.m8n8.x4.trans.shared.b16 {%0,%1,%2,%3}, [%4];"
                    : "=r"(b[nt2*2][0]), "=r"(b[nt2*2][1]),
                      "=r"(b[nt2*2+1][0]), "=r"(b[nt2*2+1][1]) : "r"(ad));
            }
            #pragma unroll
            for (int mt = 0; mt < 4; mt++)
                #pragma unroll
                for (int nt = 0; nt < 4; nt++) {
                    asm volatile(
                        "mma.sync.aligned.m16n8k16.row.col.f32.bf16.bf16.f32 "
                        "{%0,%1,%2,%3}, {%4,%5,%6,%7}, {%8,%9}, {%0,%1,%2,%3};"
                        : "+f"(acc[mt][nt][0]), "+f"(acc[mt][nt][1]),
                          "+f"(acc[mt][nt][2]), "+f"(acc[mt][nt][3])
                        : "r"(a[mt][0]), "r"(a[mt][1]), "r"(a[mt][2]), "r"(a[mt][3]),
                          "r"(b[nt][0]), "r"(b[nt][1]));
                }
        }
        sidx = (sidx == 2) ? 0 : sidx + 1;
        pidx = (pidx == 2) ? 0 : pidx + 1;
    }

    int lr = lid >> 2;
    int lc = (lid & 3) * 2;
    if (MODE == 2) {
        int bsel = row0 >> 11;
        const float* gv = mvec + bsel*MCOLS + gate_off;
        #pragma unroll
        for (int mt = 0; mt < 4; mt++) {
            size_t mrow = (size_t)(row0 + warp_m*64 + mt*16 + lr);
            #pragma unroll
            for (int nt = 0; nt < 4; nt++) {
                int col = col0 + warp_n*32 + nt*8 + lc;
                float2 g = *(const float2*)(gv + col);
                float2 x0 = *(const float2*)(xres + mrow*N + col);
                float2 x1 = *(const float2*)(xres + (mrow+8)*N + col);
                *(float2*)(Cf + mrow*N + col) =
                    make_float2(x0.x + g.x*acc[mt][nt][0], x0.y + g.y*acc[mt][nt][1]);
                *(float2*)(Cf + (mrow+8)*N + col) =
                    make_float2(x1.x + g.x*acc[mt][nt][2], x1.y + g.y*acc[mt][nt][3]);
            }
        }
    } else {  // MODE 3
        #pragma unroll
        for (int mt = 0; mt < 4; mt++) {
            size_t mrow = (size_t)(row0 + warp_m*64 + mt*16 + lr);
            #pragma unroll
            for (int nt = 0; nt < 4; nt++) {
                int col = colB + warp_n*32 + nt*8 + lc;
                if (msel == 2) {
                    *(__nv_bfloat162*)(vbf + mrow*DIM + col) =
                        __floats2bfloat162_rn(acc[mt][nt][0], acc[mt][nt][1]);
                    *(__nv_bfloat162*)(vbf + (mrow+8)*DIM + col) =
                        __floats2bfloat162_rn(acc[mt][nt][2], acc[mt][nt][3]);
                } else {
                    float* dst = msel ? kf : Cf;
                    *(float2*)(dst + mrow*DIM + col) =
                        make_float2(acc[mt][nt][0], acc[mt][nt][1]);
                    *(float2*)(dst + (mrow+8)*DIM + col) =
                        make_float2(acc[mt][nt][2], acc[mt][nt][3]);
                }
            }
        }
    }
}

// ===========================================================================
// Fused FFN dual GEMM: g = bf16( silu(A@W1) * (A@W3) ), W1/W3 [K,N] n-contig
// tile 128(M) x 64(N); B tiles 32 rows x 128B.
// ===========================================================================
#define FSMEM (3*16384)

__global__ __launch_bounds__(256) void ffn_gemm_kernel(
    const __nv_bfloat16* __restrict__ A,
    const __nv_bfloat16* __restrict__ W1c,
    const __nv_bfloat16* __restrict__ W3c,
    __nv_bfloat16* __restrict__ Og, int M, int N, int K)
{
    extern __shared__ __align__(128) char smch[];
    uint32_t sb = smem_u32(smch);
    int tid = threadIdx.x;
    int wid = tid >> 5, lid = tid & 31;
    int warp_m = wid & 1;
    int warp_n = wid >> 1;
    int row0 = blockIdx.y * 128;
    int col0 = blockIdx.x * 64;
    int iters = K >> 5;

    int ra0 = tid >> 2,          ca0 = tid & 3;
    int ra1 = (tid + 256) >> 2,  ca1 = (tid + 256) & 3;
    uint32_t soA0 = ra0*64 + ((ca0 ^ ((ra0 >> 1) & 3)) << 4);
    uint32_t soA1 = ra1*64 + ((ca1 ^ ((ra1 >> 1) & 3)) << 4);
    const char* gA0 = (const char*)(A + (size_t)(row0 + ra0)*K) + ca0*16;
    const char* gA1 = (const char*)(A + (size_t)(row0 + ra1)*K) + ca1*16;
    // B: 32 rows x 8 chunks = 256 chunks per matrix; each thread 1 chunk each
    int rb = tid >> 3, cb = tid & 7;
    uint32_t soB = rb*128 + ((cb ^ (rb & 7)) << 4);
    const char* g1p = (const char*)(W1c + (size_t)rb*N + col0) + cb*16;
    const char* g3p = (const char*)(W3c + (size_t)rb*N + col0) + cb*16;
    size_t bstep = (size_t)32 * N * 2;

    float acc1[4][2][4], acc3[4][2][4];
    #pragma unroll
    for (int i = 0; i < 4; i++)
        #pragma unroll
        for (int j = 0; j < 2; j++)
            #pragma unroll
            for (int q = 0; q < 4; q++) { acc1[i][j][q] = 0.f; acc3[i][j][q] = 0.f; }

    uint32_t aAddr[4];
    {
        int rr = lid & 15;
        int half = lid >> 4;
        #pragma unroll
        for (int mt = 0; mt < 4; mt++) {
            int row = warp_m*64 + mt*16 + rr;
            aAddr[mt] = row*64 + half;
        }
    }
    int matq = lid >> 3, r8 = lid & 7;

    #pragma unroll
    for (int p = 0; p < 2; p++) {
        uint32_t tA = sb + p*16384, tB1 = tA + 8192, tB3 = tA + 12288;
        asm volatile("cp.async.cg.shared.global [%0], [%1], 16;" :: "r"(tA+soA0),  "l"(gA0 + p*64));
        asm volatile("cp.async.cg.shared.global [%0], [%1], 16;" :: "r"(tA+soA1),  "l"(gA1 + p*64));
        asm volatile("cp.async.cg.shared.global [%0], [%1], 16;" :: "r"(tB1+soB), "l"(g1p + p*bstep));
        asm volatile("cp.async.cg.shared.global [%0], [%1], 16;" :: "r"(tB3+soB), "l"(g3p + p*bstep));
        asm volatile("cp.async.commit_group;");
    }

    int sidx = 0, pidx = 2;
    for (int kt = 0; kt < iters; kt++) {
        if (kt < iters-1) asm volatile("cp.async.wait_group 1;" ::: "memory");
        else              asm volatile("cp.async.wait_group 0;" ::: "memory");
        __syncthreads();

        if (kt + 2 < iters) {
            uint32_t tA = sb + pidx*16384, tB1 = tA + 8192, tB3 = tA + 12288;
            size_t ka = (size_t)(kt + 2) * 64;
            size_t kb = (size_t)(kt + 2) * bstep;
            asm volatile("cp.async.cg.shared.global [%0], [%1], 16;" :: "r"(tA+soA0),  "l"(gA0+ka));
            asm volatile("cp.async.cg.shared.global [%0], [%1], 16;" :: "r"(tA+soA1),  "l"(gA1+ka));
            asm volatile("cp.async.cg.shared.global [%0], [%1], 16;" :: "r"(tB1+soB), "l"(g1p+kb));
            asm volatile("cp.async.cg.shared.global [%0], [%1], 16;" :: "r"(tB3+soB), "l"(g3p+kb));
            asm volatile("cp.async.commit_group;");
        }

        uint32_t sA = sb + sidx*16384, sB1 = sA + 8192, sB3 = sA + 12288;
        #pragma unroll
        for (int ks = 0; ks < 2; ks++) {
            uint32_t a[4][4];
            #pragma unroll
            for (int mt = 0; mt < 4; mt++) {
                int row = (aAddr[mt] >> 6);
                int ck = ks*2 + (aAddr[mt] & 63);
                uint32_t ad = sA + (row*64) + (((ck) ^ ((row >> 1) & 3)) << 4);
                asm volatile("ldmatrix.sync.aligned.m8n8.x4.shared.b16 {%0,%1,%2,%3}, [%4];"
                    : "=r"(a[mt][0]), "=r"(a[mt][1]), "=r"(a[mt][2]), "=r"(a[mt][3]) : "r"(ad));
            }
            int krow = ks*16 + ((matq & 1) << 3) + r8;
            int ch = warp_n*2 + (matq >> 1);
            uint32_t swoff = krow*128 + ((ch ^ (krow & 7)) << 4);
            uint32_t b1[4], b3[4];
            asm volatile("ldmatrix.sync.aligned.m8n8.x4.trans.shared.b16 {%0,%1,%2,%3}, [%4];"
                : "=r"(b1[0]), "=r"(b1[1]), "=r"(b1[2]), "=r"(b1[3]) : "r"(sB1 + swoff));
            asm volatile("ldmatrix.sync.aligned.m8n8.x4.trans.shared.b16 {%0,%1,%2,%3}, [%4];"
                : "=r"(b3[0]), "=r"(b3[1]), "=r"(b3[2]), "=r"(b3[3]) : "r"(sB3 + swoff));
            #pragma unroll
            for (int mt = 0; mt < 4; mt++) {
                #pragma unroll
                for (int nt = 0; nt < 2; nt++) {
                    asm volatile(
                        "mma.sync.aligned.m16n8k16.row.col.f32.bf16.bf16.f32 "
                        "{%0,%1,%2,%3}, {%4,%5,%6,%7}, {%8,%9}, {%0,%1,%2,%3};"
                        : "+f"(acc1[mt][nt][0]), "+f"(acc1[mt][nt][1]),
                          "+f"(acc1[mt][nt][2]), "+f"(acc1[mt][nt][3])
                        : "r"(a[mt][0]), "r"(a[mt][1]), "r"(a[mt][2]), "r"(a[mt][3]),
                          "r"(b1[nt*2]), "r"(b1[nt*2+1]));
                    asm volatile(
                        "mma.sync.aligned.m16n8k16.row.col.f32.bf16.bf16.f32 "
                        "{%0,%1,%2,%3}, {%4,%5,%6,%7}, {%8,%9}, {%0,%1,%2,%3};"
                        : "+f"(acc3[mt][nt][0]), "+f"(acc3[mt][nt][1]),
                          "+f"(acc3[mt][nt][2]), "+f"(acc3[mt][nt][3])
                        : "r"(a[mt][0]), "r"(a[mt][1]), "r"(a[mt][2]), "r"(a[mt][3]),
                          "r"(b3[nt*2]), "r"(b3[nt*2+1]));
                }
            }
        }
        sidx = (sidx == 2) ? 0 : sidx + 1;
        pidx = (pidx == 2) ? 0 : pidx + 1;
    }

    int lr = lid >> 2;
    int lc = (lid & 3) * 2;
    #pragma unroll
    for (int mt = 0; mt < 4; mt++) {
        size_t mrow = (size_t)(row0 + warp_m*64 + mt*16 + lr);
        #pragma unroll
        for (int nt = 0; nt < 2; nt++) {
            int col = col0 + warp_n*16 + nt*8 + lc;
            float s0 = acc1[mt][nt][0], s1 = acc1[mt][nt][1];
            float s2 = acc1[mt][nt][2], s3 = acc1[mt][nt][3];
            float o0 = s0 / (1.f + __expf(-s0)) * acc3[mt][nt][0];
            float o1 = s1 / (1.f + __expf(-s1)) * acc3[mt][nt][1];
            float o2 = s2 / (1.f + __expf(-s2)) * acc3[mt][nt][2];
            float o3 = s3 / (1.f + __expf(-s3)) * acc3[mt][nt][3];
            *(__nv_bfloat162*)(Og + mrow*N + col)     = __floats2bfloat162_rn(o0, o1);
            *(__nv_bfloat162*)(Og + (mrow+8)*N + col) = __floats2bfloat162_rn(o2, o3);
        }
    }
}

// ===========================================================================
// layernorm + RoPE for q and k in one launch (blockIdx.y selects)
// ===========================================================================
__global__ __launch_bounds__(256) void lnrope2_kernel(
    const float* __restrict__ qf, const float* __restrict__ kf,
    const float* __restrict__ qw, const float* __restrict__ qb,
    const float* __restrict__ kw, const float* __restrict__ kb,
    const float* __restrict__ cosT, const float* __restrict__ sinT,
    __nv_bfloat16* __restrict__ qbf, __nv_bfloat16* __restrict__ kbf)
{
    __shared__ float redm[256], redv[256];
    int sel = blockIdx.y;
    const float* t = sel ? kf : qf;
    const float* w = sel ? kw : qw;
    const float* bvec = sel ? kb : qb;
    __nv_bfloat16* dst = sel ? kbf : qbf;
    int row = blockIdx.x;
    int s = row & (SEQ-1);
    int tid = threadIdx.x;
    float4 v = ((const float4*)(t + (size_t)row*DIM))[tid];
    redm[tid] = v.x + v.y + v.z + v.w;
    redv[tid] = v.x*v.x + v.y*v.y + v.z*v.z + v.w*v.w;
    __syncthreads();
    for (int st = 128; st > 0; st >>= 1) {
        if (tid < st) { redm[tid] += redm[tid+st]; redv[tid] += redv[tid+st]; }
        __syncthreads();
    }
    float mu = redm[0] * (1.f/DIM);
    float var = redv[0] * (1.f/DIM) - mu*mu;
    float rs = rsqrtf(var + 1e-5f);
    int d = tid*4;
    float4 wv = *(const float4*)(w + d);
    float4 bv = *(const float4*)(bvec + d);
    float y0 = (v.x-mu)*rs*wv.x + bv.x;
    float y1 = (v.y-mu)*rs*wv.y + bv.y;
    float y2 = (v.z-mu)*rs*wv.z + bv.z;
    float y3 = (v.w-mu)*rs*wv.w + bv.w;
    int i0 = (d & 63) >> 1;
    float c0 = cosT[s*32 + i0],   s0 = sinT[s*32 + i0];
    float c1 = cosT[s*32 + i0+1], s1 = sinT[s*32 + i0+1];
    float o0 = y0*c0 - y1*s0;
    float o1 = y0*s0 + y1*c0;
    float o2 = y2*c1 - y3*s1;
    float o3 = y2*s1 + y3*c1;
    __nv_bfloat162* dp = (__nv_bfloat162*)(dst + (size_t)row*DIM);
    dp[tid*2]   = __floats2bfloat162_rn(o0, o1);
    dp[tid*2+1] = __floats2bfloat162_rn(o2, o3);
}

// ===========================================================================
// Tensor-core flash attention (unchanged from round 6)
// ===========================================================================
#define ATT_SMEM 49152

__global__ __launch_bounds__(256, 1) void attn_mma_kernel(
    const __nv_bfloat16* __restrict__ q, const __nv_bfloat16* __restrict__ k,
    const __nv_bfloat16* __restrict__ v, __nv_bfloat16* __restrict__ o)
{
    extern __shared__ __align__(128) char smch[];
    uint32_t sb = smem_u32(smch);
    const uint32_t sq  = sb;
    const uint32_t sk0 = sb + 16384;
    const uint32_t sv0 = sb + 32768;
    int tid = threadIdx.x, wid = tid >> 5, lid = tid & 31;
    int qt = blockIdx.x, h = blockIdx.y, b = blockIdx.z;
    int hoffb = h * HD * 2;
    int qbase = b*SEQ + qt*128;
    int kbb   = b*SEQ;

    #pragma unroll
    for (int i = 0; i < 4; i++) {
        int cid = tid + 256*i;
        int row = cid >> 3, ch = cid & 7;
        const char* g = (const char*)(q + (size_t)(qbase+row)*DIM) + hoffb + ch*16;
        uint32_t so = sq + row*128 + ((ch ^ (row & 7)) << 4);
        asm volatile("cp.async.cg.shared.global [%0], [%1], 16;" :: "r"(so), "l"(g));
    }
    #pragma unroll
    for (int i = 0; i < 2; i++) {
        int cid = tid + 256*i;
        int row = cid >> 3, ch = cid & 7;
        uint32_t so = row*128 + ((ch ^ (row & 7)) << 4);
        const char* gk = (const char*)(k + (size_t)(kbb+row)*DIM) + hoffb + ch*16;
        const char* gv = (const char*)(v + (size_t)(kbb+row)*DIM) + hoffb + ch*16;
        asm volatile("cp.async.cg.shared.global [%0], [%1], 16;" :: "r"(sk0+so), "l"(gk));
        asm volatile("cp.async.cg.shared.global [%0], [%1], 16;" :: "r"(sv0+so), "l"(gv));
    }
    asm volatile("cp.async.commit_group;");

    int wr = wid * 16;
    uint32_t qf[4][4];
    float oacc[8][4];
    #pragma unroll
    for (int j = 0; j < 8; j++)
        #pragma unroll
        for (int i = 0; i < 4; i++) oacc[j][i] = 0.f;
    float m0 = -INFINITY, m1 = -INFINITY, l0 = 0.f, l1 = 0.f;

    for (int kt = 0; kt < SEQ/64; kt++) {
        int s = kt & 1;
        if (kt + 1 < SEQ/64) {
            int ns = s ^ 1;
            int kb2 = kbb + (kt+1)*64;
            #pragma unroll
            for (int i = 0; i < 2; i++) {
                int cid = tid + 256*i;
                int row = cid >> 3, ch = cid & 7;
                uint32_t so = row*128 + ((ch ^ (row & 7)) << 4);
                const char* gk = (const char*)(k + (size_t)(kb2+row)*DIM) + hoffb + ch*16;
                const char* gv = (const char*)(v + (size_t)(kb2+row)*DIM) + hoffb + ch*16;
                asm volatile("cp.async.cg.shared.global [%0], [%1], 16;" :: "r"(sk0+ns*8192+so), "l"(gk));
                asm volatile("cp.async.cg.shared.global [%0], [%1], 16;" :: "r"(sv0+ns*8192+so), "l"(gv));
            }
            asm volatile("cp.async.commit_group;");
            asm volatile("cp.async.wait_group 1;" ::: "memory");
        } else {
            asm volatile("cp.async.wait_group 0;" ::: "memory");
        }
        __syncthreads();

        if (kt == 0) {
            int arow = wr + (lid & 15);
            #pragma unroll
            for (int s2 = 0; s2 < 4; s2++) {
                int ch = 2*s2 + (lid >> 4);
                uint32_t ad = sq + arow*128 + ((ch ^ (arow & 7)) << 4);
                asm volatile("ldmatrix.sync.aligned.m8n8.x4.shared.b16 {%0,%1,%2,%3}, [%4];"
                    : "=r"(qf[s2][0]), "=r"(qf[s2][1]), "=r"(qf[s2][2]), "=r"(qf[s2][3]) : "r"(ad));
            }
        }
        uint32_t skst = sk0 + s*8192, svst = sv0 + s*8192;

        float sa[8][4];
        #pragma unroll
        for (int j = 0; j < 8; j++)
            #pragma unroll
            for (int i = 0; i < 4; i++) sa[j][i] = 0.f;

        #pragma unroll
        for (int s2 = 0; s2 < 4; s2++) {
            #pragma unroll
            for (int p = 0; p < 4; p++) {
                int mat = lid >> 3;
                int krow = p*16 + ((mat >> 1) << 3) + (lid & 7);
                int ch = 2*s2 + (mat & 1);
                uint32_t ad = skst + krow*128 + ((ch ^ (krow & 7)) << 4);
                uint32_t b0, b1, b2, b3;
                asm volatile("ldmatrix.sync.aligned.m8n8.x4.shared.b16 {%0,%1,%2,%3}, [%4];"
                    : "=r"(b0), "=r"(b1), "=r"(b2), "=r"(b3) : "r"(ad));
                asm volatile(
                    "mma.sync.aligned.m16n8k16.row.col.f32.bf16.bf16.f32 "
                    "{%0,%1,%2,%3}, {%4,%5,%6,%7}, {%8,%9}, {%0,%1,%2,%3};"
                    : "+f"(sa[2*p][0]), "+f"(sa[2*p][1]), "+f"(sa[2*p][2]), "+f"(sa[2*p][3])
                    : "r"(qf[s2][0]), "r"(qf[s2][1]), "r"(qf[s2][2]), "r"(qf[s2][3]),
                      "r"(b0), "r"(b1));
                asm volatile(
                    "mma.sync.aligned.m16n8k16.row.col.f32.bf16.bf16.f32 "
                    "{%0,%1,%2,%3}, {%4,%5,%6,%7}, {%8,%9}, {%0,%1,%2,%3};"
                    : "+f"(sa[2*p+1][0]), "+f"(sa[2*p+1][1]), "+f"(sa[2*p+1][2]), "+f"(sa[2*p+1][3])
                    : "r"(qf[s2][0]), "r"(qf[s2][1]), "r"(qf[s2][2]), "r"(qf[s2][3]),
                      "r"(b2), "r"(b3));
            }
        }

        float mx0 = -INFINITY, mx1 = -INFINITY;
        #pragma unroll
        for (int j = 0; j < 8; j++) {
            sa[j][0] *= 0.125f; sa[j][1] *= 0.125f;
            sa[j][2] *= 0.125f; sa[j][3] *= 0.125f;
            mx0 = fmaxf(mx0, fmaxf(sa[j][0], sa[j][1]));
            mx1 = fmaxf(mx1, fmaxf(sa[j][2], sa[j][3]));
        }
        mx0 = fmaxf(mx0, __shfl_xor_sync(0xffffffffu, mx0, 1));
        mx0 = fmaxf(mx0, __shfl_xor_sync(0xffffffffu, mx0, 2));
        mx1 = fmaxf(mx1, __shfl_xor_sync(0xffffffffu, mx1, 1));
        mx1 = fmaxf(mx1, __shfl_xor_sync(0xffffffffu, mx1, 2));
        float nm0 = fmaxf(m0, mx0), nm1 = fmaxf(m1, mx1);

        float ps0 = 0.f, ps1 = 0.f;
        uint32_t pf[4][4];
        #pragma unroll
        for (int j = 0; j < 8; j++) {
            float e0 = __expf(sa[j][0] - nm0);
            float e1 = __expf(sa[j][1] - nm0);
            float e2 = __expf(sa[j][2] - nm1);
            float e3 = __expf(sa[j][3] - nm1);
            ps0 += e0 + e1; ps1 += e2 + e3;
            int s2 = j >> 1;
            __nv_bfloat162 lo = __floats2bfloat162_rn(e0, e1);
            __nv_bfloat162 hi = __floats2bfloat162_rn(e2, e3);
            if ((j & 1) == 0) {
                pf[s2][0] = *(uint32_t*)&lo;
                pf[s2][1] = *(uint32_t*)&hi;
            } else {
                pf[s2][2] = *(uint32_t*)&lo;
                pf[s2][3] = *(uint32_t*)&hi;
            }
        }
        ps0 += __shfl_xor_sync(0xffffffffu, ps0, 1);
        ps0 += __shfl_xor_sync(0xffffffffu, ps0, 2);
        ps1 += __shfl_xor_sync(0xffffffffu, ps1, 1);
        ps1 += __shfl_xor_sync(0xffffffffu, ps1, 2);

        float c0 = __expf(m0 - nm0), c1 = __expf(m1 - nm1);
        l0 = l0*c0 + ps0;  l1 = l1*c1 + ps1;
        m0 = nm0;  m1 = nm1;
        #pragma unroll
        for (int j = 0; j < 8; j++) {
            oacc[j][0] *= c0; oacc[j][1] *= c0;
            oacc[j][2] *= c1; oacc[j][3] *= c1;
        }

        #pragma unroll
        for (int s2 = 0; s2 < 4; s2++) {
            #pragma unroll
            for (int p = 0; p < 4; p++) {
                int mat = lid >> 3;
                int vrow = s2*16 + ((mat & 1) << 3) + (lid & 7);
                int ch = 2*p + (mat >> 1);
                uint32_t ad = svst + vrow*128 + ((ch ^ (vrow & 7)) << 4);
                uint32_t v0, v1, v2, v3;
                asm volatile("ldmatrix.sync.aligned.m8n8.x4.trans.shared.b16 {%0,%1,%2,%3}, [%4];"
                    : "=r"(v0), "=r"(v1), "=r"(v2), "=r"(v3) : "r"(ad));
                asm volatile(
                    "mma.sync.aligned.m16n8k16.row.col.f32.bf16.bf16.f32 "
                    "{%0,%1,%2,%3}, {%4,%5,%6,%7}, {%8,%9}, {%0,%1,%2,%3};"
                    : "+f"(oacc[2*p][0]), "+f"(oacc[2*p][1]), "+f"(oacc[2*p][2]), "+f"(oacc[2*p][3])
                    : "r"(pf[s2][0]), "r"(pf[s2][1]), "r"(pf[s2][2]), "r"(pf[s2][3]),
                      "r"(v0), "r"(v1));
                asm volatile(
                    "mma.sync.aligned.m16n8k16.row.col.f32.bf16.bf16.f32 "
                    "{%0,%1,%2,%3}, {%4,%5,%6,%7}, {%8,%9}, {%0,%1,%2,%3};"
                    : "+f"(oacc[2*p+1][0]), "+f"(oacc[2*p+1][1]), "+f"(oacc[2*p+1][2]), "+f"(oacc[2*p+1][3])
                    : "r"(pf[s2][0]), "r"(pf[s2][1]), "r"(pf[s2][2]), "r"(pf[s2][3]),
                      "r"(v2), "r"(v3));
            }
        }
        __syncthreads();
    }

    float inv0 = 1.f / l0, inv1 = 1.f / l1;
    int r = lid >> 2, c2 = (lid & 3) * 2;
    size_t row0 = (size_t)(qbase + wr + r)*DIM + h*HD + c2;
    size_t row1 = row0 + 8*DIM;
    #pragma unroll
    for (int j = 0; j < 8; j++) {
        *(__nv_bfloat162*)(o + row0 + 8*j) =
            __floats2bfloat162_rn(oacc[j][0]*inv0, oacc[j][1]*inv0);
        *(__nv_bfloat162*)(o + row1 + 8*j) =
            __floats2bfloat162_rn(oacc[j][2]*inv1, oacc[j][3]*inv1);
    }
}

// ===========================================================================
extern "C" void kernel_launch(void* const* d_in, const int* in_sizes, int n_in,
                              void* d_out, int out_size)
{
    const float* x        = (const float*)d_in[0];
    const float* adaln_in = (const float*)d_in[1];
    const float* cosT     = (const float*)d_in[2];
    const float* sinT     = (const float*)d_in[3];
    const float* wq       = (const float*)d_in[4];
    const float* wk       = (const float*)d_in[5];
    const float* wv       = (const float*)d_in[6];
    const float* wo       = (const float*)d_in[7];
    const float* q_norm_w = (const float*)d_in[8];
    const float* q_norm_b = (const float*)d_in[9];
    const float* k_norm_w = (const float*)d_in[10];
    const float* k_norm_b = (const float*)d_in[11];
    const float* attn_norm_w = (const float*)d_in[12];
    const float* ffn_norm_w  = (const float*)d_in[13];
    const float* ada_w    = (const float*)d_in[14];
    const float* ada_b    = (const float*)d_in[15];
    const float* w1       = (const float*)d_in[16];
    const float* w2       = (const float*)d_in[17];
    const float* w3       = (const float*)d_in[18];
    float* out = (float*)d_out;

    float* base = nullptr;
    cudaGetSymbolAddress((void**)&base, g_buf);
    float* m    = base + OFF_M;
    __nv_bfloat16* hbf  = (__nv_bfloat16*)(base + OFF_HBF);
    float* qf   = base + OFF_QF;
    float* kf   = base + OFF_KF;
    __nv_bfloat16* qbf  = (__nv_bfloat16*)(base + OFF_QBF);
    __nv_bfloat16* kbf  = (__nv_bfloat16*)(base + OFF_KBF);
    __nv_bfloat16* vbf  = (__nv_bfloat16*)(base + OFF_VBF);
    __nv_bfloat16* abf  = (__nv_bfloat16*)(base + OFF_ABF);
    float* xmid = base + OFF_XMID;
    __nv_bfloat16* g1bf = (__nv_bfloat16*)(base + OFF_G1BF);
    __nv_bfloat16* wqC  = (__nv_bfloat16*)(base + OFF_WQC);
    __nv_bfloat16* wkC  = (__nv_bfloat16*)(base + OFF_WKC);
    __nv_bfloat16* wvC  = (__nv_bfloat16*)(base + OFF_WVC);
    __nv_bfloat16* woC  = (__nv_bfloat16*)(base + OFF_WOC);
    __nv_bfloat16* w1C  = (__nv_bfloat16*)(base + OFF_W1C);
    __nv_bfloat16* w3C  = (__nv_bfloat16*)(base + OFF_W3C);
    __nv_bfloat16* w2C  = (__nv_bfloat16*)(base + OFF_W2C);

    cudaFuncSetAttribute(mma_gemm_kernel<2>, cudaFuncAttributeMaxDynamicSharedMemorySize, GSMEM);
    cudaFuncSetAttribute(mma_gemm_kernel<3>, cudaFuncAttributeMaxDynamicSharedMemorySize, GSMEM);
    cudaFuncSetAttribute(ffn_gemm_kernel, cudaFuncAttributeMaxDynamicSharedMemorySize, FSMEM);
    cudaFuncSetAttribute(attn_mma_kernel, cudaFuncAttributeMaxDynamicSharedMemorySize, ATT_SMEM);

    // weight converts (pure streaming, same layout)
    convert2_kernel<<<dim3(DIM*DIM/2048, 2), 256>>>(wq, wk, wqC, wkC);
    convert2_kernel<<<dim3(DIM*DIM/2048, 2), 256>>>(wv, wo, wvC, woC);
    convert3_kernel<<<dim3(DIM*HID/2048, 3), 256>>>(w1, w3, w2, w1C, w3C, w2C);

    adaln_kernel<<<dim3(MCOLS/256, BB), 256>>>(adaln_in, ada_w, ada_b, m);
    rmsmod_kernel<<<RR, 256>>>(x, attn_norm_w, m, 0, DIM, hbf);

    // fused QKV projection (launch #6 for ncu)
    mma_gemm_kernel<3><<<dim3(3*DIM/128, RR/128), 256, GSMEM>>>(
        hbf, wqC, wkC, wvC, DIM, qf, kf, vbf, nullptr, nullptr, 0, RR, DIM, DIM);

    lnrope2_kernel<<<dim3(RR, 2), 256>>>(qf, kf, q_norm_w, q_norm_b, k_norm_w, k_norm_b,
                                         cosT, sinT, qbf, kbf);

    attn_mma_kernel<<<dim3(SEQ/128, NH, BB), 256, ATT_SMEM>>>(qbf, kbf, vbf, abf);

    // wo projection + fused gated residual: xmid = x + gate_msa * (attn@wo)
    mma_gemm_kernel<2><<<dim3(DIM/128, RR/128), 256, GSMEM>>>(
        abf, woC, nullptr, nullptr, DIM, xmid, nullptr, nullptr, x, m, 2*DIM, RR, DIM, DIM);

    rmsmod_kernel<<<RR, 256>>>(xmid, ffn_norm_w, m, 3*DIM, 4*DIM, hbf);

    // fused dual FFN gemm: g1bf = bf16(silu(h@w1) * (h@w3))
    ffn_gemm_kernel<<<dim3(HID/64, RR/128), 256, FSMEM>>>(hbf, w1C, w3C, g1bf, RR, HID, DIM);

    // w2 projection + fused gated residual: out = xmid + gate_mlp * (g@w2)
    mma_gemm_kernel<2><<<dim3(DIM/128, RR/128), 256, GSMEM>>>(
        g1bf, w2C, nullptr, nullptr, DIM, out, nullptr, nullptr, xmid, m, 5*DIM, RR, DIM, HID);
}

// round 9
// speedup vs baseline: 7.8094x; 1.2508x over previous
#include <cuda_runtime.h>
#include <cuda_bf16.h>
#include <math.h>
#include <stdint.h>

#define BB 2
#define SEQ 2048
#define RR (BB*SEQ)          // 4096 rows
#define DIM 1024
#define HID 2816
#define NH 16
#define HD 64
#define MCOLS (6*DIM)        // 6144
#define KSPLIT 16

// ---- scratch (float units) ----
#define SZ_M     16384
#define SZ_MPART (KSPLIT*2*MCOLS)
#define SZ_RD    (RR*DIM)
#define SZ_RDH   (RR*DIM/2)
#define SZ_RHH   (RR*HID/2)
#define SZ_WS    (DIM*DIM/2)
#define SZ_WB    (DIM*HID/2)

#define OFF_M    0
#define OFF_MPART (OFF_M + SZ_M)
#define OFF_HBF  (OFF_MPART + SZ_MPART)
#define OFF_QF   (OFF_HBF + SZ_RDH)
#define OFF_KF   (OFF_QF + SZ_RD)
#define OFF_QBF  (OFF_KF + SZ_RD)
#define OFF_KBF  (OFF_QBF + SZ_RDH)
#define OFF_VBF  (OFF_KBF + SZ_RDH)
#define OFF_ABF  (OFF_VBF + SZ_RDH)
#define OFF_XMID (OFF_ABF + SZ_RDH)
#define OFF_G1BF (OFF_XMID + SZ_RD)
#define OFF_WQC  (OFF_G1BF + SZ_RHH)
#define OFF_WKC  (OFF_WQC + SZ_WS)
#define OFF_WVC  (OFF_WKC + SZ_WS)
#define OFF_WOC  (OFF_WVC + SZ_WS)
#define OFF_W1C  (OFF_WOC + SZ_WS)
#define OFF_W3C  (OFF_W1C + SZ_WB)
#define OFF_W2C  (OFF_W3C + SZ_WB)
#define TOTAL_F  (OFF_W2C + SZ_WB)

__device__ float g_buf[TOTAL_F];

__device__ __forceinline__ uint32_t smem_u32(const void* p) {
    uint32_t a;
    asm("{ .reg .u64 t; cvta.to.shared.u64 t, %1; cvt.u32.u64 %0, t; }" : "=r"(a) : "l"(p));
    return a;
}

// ===========================================================================
// adaLN split-K: block (jb, kz) computes partial sums over 64 k for both
// batches; deterministic two-stage reduction (no atomics).
// ===========================================================================
__global__ __launch_bounds__(256) void adaln_part_kernel(
    const float* __restrict__ a, const float* __restrict__ W,
    float* __restrict__ mpart)
{
    __shared__ float act0[64], act1[64];
    int j = blockIdx.x * 256 + threadIdx.x;
    int k0 = blockIdx.y * 64;
    if (threadIdx.x < 64) {
        float v = a[k0 + threadIdx.x];
        act0[threadIdx.x] = v / (1.f + __expf(-v));
    } else if (threadIdx.x < 128) {
        float v = a[DIM + k0 + threadIdx.x - 64];
        act1[threadIdx.x - 64] = v / (1.f + __expf(-v));
    }
    __syncthreads();
    float acc0 = 0.f, acc1 = 0.f;
    const float* Wp = W + (size_t)k0 * MCOLS + j;
    #pragma unroll 8
    for (int k = 0; k < 64; k++) {
        float w = Wp[(size_t)k * MCOLS];
        acc0 += act0[k] * w;
        acc1 += act1[k] * w;
    }
    mpart[(blockIdx.y*2 + 0)*MCOLS + j] = acc0;
    mpart[(blockIdx.y*2 + 1)*MCOLS + j] = acc1;
}

__global__ __launch_bounds__(256) void adaln_reduce_kernel(
    const float* __restrict__ mpart, const float* __restrict__ bias,
    float* __restrict__ m)
{
    int j = blockIdx.x * 256 + threadIdx.x;
    float b = bias[j];
    float s0 = b, s1 = b;
    #pragma unroll
    for (int kz = 0; kz < KSPLIT; kz++) {
        s0 += mpart[(kz*2 + 0)*MCOLS + j];
        s1 += mpart[(kz*2 + 1)*MCOLS + j];
    }
    m[j] = s0;
    m[MCOLS + j] = s1;
}

// ===========================================================================
// streaming fp32 -> bf16 converts (same layout), 2 or 3 matrices per launch
// ===========================================================================
__device__ __forceinline__ void conv8(const float* s, __nv_bfloat16* d, int i) {
    float4 a = *(const float4*)(s + i);
    float4 b = *(const float4*)(s + i + 4);
    __nv_bfloat162 p0 = __floats2bfloat162_rn(a.x, a.y);
    __nv_bfloat162 p1 = __floats2bfloat162_rn(a.z, a.w);
    __nv_bfloat162 p2 = __floats2bfloat162_rn(b.x, b.y);
    __nv_bfloat162 p3 = __floats2bfloat162_rn(b.z, b.w);
    uint4 o;
    o.x = *(uint32_t*)&p0; o.y = *(uint32_t*)&p1;
    o.z = *(uint32_t*)&p2; o.w = *(uint32_t*)&p3;
    *(uint4*)(d + i) = o;
}

__global__ __launch_bounds__(256) void convert2_kernel(
    const float* __restrict__ s0, const float* __restrict__ s1,
    __nv_bfloat16* __restrict__ d0, __nv_bfloat16* __restrict__ d1)
{
    const float* s = blockIdx.y ? s1 : s0;
    __nv_bfloat16* d = blockIdx.y ? d1 : d0;
    conv8(s, d, (blockIdx.x*256 + threadIdx.x)*8);
}

__global__ __launch_bounds__(256) void convert3_kernel(
    const float* __restrict__ s0, const float* __restrict__ s1, const float* __restrict__ s2,
    __nv_bfloat16* __restrict__ d0, __nv_bfloat16* __restrict__ d1, __nv_bfloat16* __restrict__ d2)
{
    const float* s = (blockIdx.y == 0) ? s0 : (blockIdx.y == 1) ? s1 : s2;
    __nv_bfloat16* d = (blockIdx.y == 0) ? d0 : (blockIdx.y == 1) ? d1 : d2;
    conv8(s, d, (blockIdx.x*256 + threadIdx.x)*8);
}

// ===========================================================================
// rmsnorm + modulate -> bf16
// ===========================================================================
__global__ __launch_bounds__(256) void rmsmod_kernel(
    const float* __restrict__ src, const float* __restrict__ w,
    const float* __restrict__ m, int shift_off, int scale_off,
    __nv_bfloat16* __restrict__ dst)
{
    __shared__ float red[256];
    int row = blockIdx.x;
    int b = row >> 11;
    int tid = threadIdx.x;
    float4 v = ((const float4*)(src + (size_t)row*DIM))[tid];
    red[tid] = v.x*v.x + v.y*v.y + v.z*v.z + v.w*v.w;
    __syncthreads();
    for (int s = 128; s > 0; s >>= 1) {
        if (tid < s) red[tid] += red[tid+s];
        __syncthreads();
    }
    float rms = rsqrtf(red[0] * (1.f/DIM) + 1e-5f);
    int d = tid * 4;
    float4 wv = *(const float4*)(w + d);
    float4 sh = *(const float4*)(m + b*MCOLS + shift_off + d);
    float4 sc = *(const float4*)(m + b*MCOLS + scale_off + d);
    float o0 = v.x*rms*wv.x*(1.f+sc.x) + sh.x;
    float o1 = v.y*rms*wv.y*(1.f+sc.y) + sh.y;
    float o2 = v.z*rms*wv.z*(1.f+sc.z) + sh.z;
    float o3 = v.w*rms*wv.w*(1.f+sc.w) + sh.w;
    __nv_bfloat162* dp = (__nv_bfloat162*)(dst + (size_t)row*DIM);
    dp[tid*2]   = __floats2bfloat162_rn(o0, o1);
    dp[tid*2+1] = __floats2bfloat162_rn(o2, o3);
}

// ===========================================================================
// Shared GEMM building blocks (A [M,K] k-contig bf16; B [K,N] n-contig bf16)
// ===========================================================================
#define GSMEM (3*16384)

// MODE 2: fp32 C = xres + gate*acc   MODE 3: fused QKV (3 outputs)
template<int MODE>
__global__ __launch_bounds__(256) void mma_gemm_kernel(
    const __nv_bfloat16* __restrict__ A,
    const __nv_bfloat16* __restrict__ B0,
    const __nv_bfloat16* __restrict__ B1m,
    const __nv_bfloat16* __restrict__ B2m,
    int ldb,
    float* __restrict__ Cf,
    float* __restrict__ kf,
    __nv_bfloat16* __restrict__ vbf,
    const float* __restrict__ xres,
    const float* __restrict__ mvec, int gate_off,
    int M, int N, int K)
{
    extern __shared__ __align__(128) char smch[];
    uint32_t sb = smem_u32(smch);
    int tid = threadIdx.x;
    int wid = tid >> 5, lid = tid & 31;
    int warp_m = wid & 1;
    int warp_n = wid >> 1;
    int row0 = blockIdx.y * 128;
    int col0 = blockIdx.x * 128;
    int iters = K >> 5;

    const __nv_bfloat16* B = B0;
    int msel = 0, colB = col0;
    if (MODE == 3) {
        msel = col0 >> 10;
        colB = col0 & 1023;
        B = (msel == 0) ? B0 : (msel == 1) ? B1m : B2m;
    }

    int ra0 = tid >> 2,          ca0 = tid & 3;
    int ra1 = (tid + 256) >> 2,  ca1 = (tid + 256) & 3;
    uint32_t soA0 = ra0*64 + ((ca0 ^ ((ra0 >> 1) & 3)) << 4);
    uint32_t soA1 = ra1*64 + ((ca1 ^ ((ra1 >> 1) & 3)) << 4);
    const char* gA0 = (const char*)(A + (size_t)(row0 + ra0)*K) + ca0*16;
    const char* gA1 = (const char*)(A + (size_t)(row0 + ra1)*K) + ca1*16;
    int rb0 = tid >> 4,          cb0 = tid & 15;
    int rb1 = (tid + 256) >> 4,  cb1 = (tid + 256) & 15;
    uint32_t soB0 = rb0*256 + ((cb0 ^ (rb0 & 7)) << 4);
    uint32_t soB1 = rb1*256 + ((cb1 ^ (rb1 & 7)) << 4);
    const char* gB0 = (const char*)(B + (size_t)rb0*ldb + colB) + cb0*16;
    const char* gB1 = (const char*)(B + (size_t)rb1*ldb + colB) + cb1*16;
    size_t bstep = (size_t)32 * ldb * 2;

    float acc[4][4][4];
    #pragma unroll
    for (int i = 0; i < 4; i++)
        #pragma unroll
        for (int j = 0; j < 4; j++)
            #pragma unroll
            for (int q = 0; q < 4; q++) acc[i][j][q] = 0.f;

    uint32_t aAddr[4];
    {
        int rr = lid & 15;
        int half = lid >> 4;
        #pragma unroll
        for (int mt = 0; mt < 4; mt++) {
            int row = warp_m*64 + mt*16 + rr;
            aAddr[mt] = row*64 + half;
        }
    }
    int matq = lid >> 3, r8 = lid & 7;

    #pragma unroll
    for (int p = 0; p < 2; p++) {
        uint32_t tA = sb + p*16384, tB = tA + 8192;
        asm volatile("cp.async.cg.shared.global [%0], [%1], 16;" :: "r"(tA+soA0), "l"(gA0 + p*64));
        asm volatile("cp.async.cg.shared.global [%0], [%1], 16;" :: "r"(tA+soA1), "l"(gA1 + p*64));
        asm volatile("cp.async.cg.shared.global [%0], [%1], 16;" :: "r"(tB+soB0), "l"(gB0 + p*bstep));
        asm volatile("cp.async.cg.shared.global [%0], [%1], 16;" :: "r"(tB+soB1), "l"(gB1 + p*bstep));
        asm volatile("cp.async.commit_group;");
    }

    int sidx = 0, pidx = 2;
    for (int kt = 0; kt < iters; kt++) {
        if (kt < iters-1) asm volatile("cp.async.wait_group 1;" ::: "memory");
        else              asm volatile("cp.async.wait_group 0;" ::: "memory");
        __syncthreads();

        if (kt + 2 < iters) {
            uint32_t tA = sb + pidx*16384, tB = tA + 8192;
            size_t ka = (size_t)(kt + 2) * 64;
            size_t kb = (size_t)(kt + 2) * bstep;
            asm volatile("cp.async.cg.shared.global [%0], [%1], 16;" :: "r"(tA+soA0), "l"(gA0+ka));
            asm volatile("cp.async.cg.shared.global [%0], [%1], 16;" :: "r"(tA+soA1), "l"(gA1+ka));
            asm volatile("cp.async.cg.shared.global [%0], [%1], 16;" :: "r"(tB+soB0), "l"(gB0+kb));
            asm volatile("cp.async.cg.shared.global [%0], [%1], 16;" :: "r"(tB+soB1), "l"(gB1+kb));
            asm volatile("cp.async.commit_group;");
        }

        uint32_t sA = sb + sidx*16384, sB = sA + 8192;
        #pragma unroll
        for (int ks = 0; ks < 2; ks++) {
            uint32_t a[4][4], b[4][2];
            #pragma unroll
            for (int mt = 0; mt < 4; mt++) {
                int row = (aAddr[mt] >> 6);
                int ck = ks*2 + (aAddr[mt] & 63);
                uint32_t ad = sA + (row*64) + (((ck) ^ ((row >> 1) & 3)) << 4);
                asm volatile("ldmatrix.sync.aligned.m8n8.x4.shared.b16 {%0,%1,%2,%3}, [%4];"
                    : "=r"(a[mt][0]), "=r"(a[mt][1]), "=r"(a[mt][2]), "=r"(a[mt][3]) : "r"(ad));
            }
            #pragma unroll
            for (int nt2 = 0; nt2 < 2; nt2++) {
                int krow = ks*16 + ((matq & 1) << 3) + r8;
                int ch = warp_n*4 + nt2*2 + (matq >> 1);
                uint32_t ad = sB + krow*256 + ((ch ^ (krow & 7)) << 4);
                asm volatile("ldmatrix.sync.aligned.m8n8.x4.trans.shared.b16 {%0,%1,%2,%3}, [%4];"
                    : "=r"(b[nt2*2][0]), "=r"(b[nt2*2][1]),
                      "=r"(b[nt2*2+1][0]), "=r"(b[nt2*2+1][1]) : "r"(ad));
            }
            #pragma unroll
            for (int mt = 0; mt < 4; mt++)
                #pragma unroll
                for (int nt = 0; nt < 4; nt++) {
                    asm volatile(
                        "mma.sync.aligned.m16n8k16.row.col.f32.bf16.bf16.f32 "
                        "{%0,%1,%2,%3}, {%4,%5,%6,%7}, {%8,%9}, {%0,%1,%2,%3};"
                        : "+f"(acc[mt][nt][0]), "+f"(acc[mt][nt][1]),
                          "+f"(acc[mt][nt][2]), "+f"(acc[mt][nt][3])
                        : "r"(a[mt][0]), "r"(a[mt][1]), "r"(a[mt][2]), "r"(a[mt][3]),
                          "r"(b[nt][0]), "r"(b[nt][1]));
                }
        }
        sidx = (sidx == 2) ? 0 : sidx + 1;
        pidx = (pidx == 2) ? 0 : pidx + 1;
    }

    int lr = lid >> 2;
    int lc = (lid & 3) * 2;
    if (MODE == 2) {
        int bsel = row0 >> 11;
        const float* gv = mvec + bsel*MCOLS + gate_off;
        #pragma unroll
        for (int mt = 0; mt < 4; mt++) {
            size_t mrow = (size_t)(row0 + warp_m*64 + mt*16 + lr);
            #pragma unroll
            for (int nt = 0; nt < 4; nt++) {
                int col = col0 + warp_n*32 + nt*8 + lc;
                float2 g = *(const float2*)(gv + col);
                float2 x0 = *(const float2*)(xres + mrow*N + col);
                float2 x1 = *(const float2*)(xres + (mrow+8)*N + col);
                *(float2*)(Cf + mrow*N + col) =
                    make_float2(x0.x + g.x*acc[mt][nt][0], x0.y + g.y*acc[mt][nt][1]);
                *(float2*)(Cf + (mrow+8)*N + col) =
                    make_float2(x1.x + g.x*acc[mt][nt][2], x1.y + g.y*acc[mt][nt][3]);
            }
        }
    } else {  // MODE 3
        #pragma unroll
        for (int mt = 0; mt < 4; mt++) {
            size_t mrow = (size_t)(row0 + warp_m*64 + mt*16 + lr);
            #pragma unroll
            for (int nt = 0; nt < 4; nt++) {
                int col = colB + warp_n*32 + nt*8 + lc;
                if (msel == 2) {
                    *(__nv_bfloat162*)(vbf + mrow*DIM + col) =
                        __floats2bfloat162_rn(acc[mt][nt][0], acc[mt][nt][1]);
                    *(__nv_bfloat162*)(vbf + (mrow+8)*DIM + col) =
                        __floats2bfloat162_rn(acc[mt][nt][2], acc[mt][nt][3]);
                } else {
                    float* dst = msel ? kf : Cf;
                    *(float2*)(dst + mrow*DIM + col) =
                        make_float2(acc[mt][nt][0], acc[mt][nt][1]);
                    *(float2*)(dst + (mrow+8)*DIM + col) =
                        make_float2(acc[mt][nt][2], acc[mt][nt][3]);
                }
            }
        }
    }
}

// ===========================================================================
// Fused FFN dual GEMM: g = bf16( silu(A@W1) * (A@W3) )
// ===========================================================================
#define FSMEM (3*16384)

__global__ __launch_bounds__(256) void ffn_gemm_kernel(
    const __nv_bfloat16* __restrict__ A,
    const __nv_bfloat16* __restrict__ W1c,
    const __nv_bfloat16* __restrict__ W3c,
    __nv_bfloat16* __restrict__ Og, int M, int N, int K)
{
    extern __shared__ __align__(128) char smch[];
    uint32_t sb = smem_u32(smch);
    int tid = threadIdx.x;
    int wid = tid >> 5, lid = tid & 31;
    int warp_m = wid & 1;
    int warp_n = wid >> 1;
    int row0 = blockIdx.y * 128;
    int col0 = blockIdx.x * 64;
    int iters = K >> 5;

    int ra0 = tid >> 2,          ca0 = tid & 3;
    int ra1 = (tid + 256) >> 2,  ca1 = (tid + 256) & 3;
    uint32_t soA0 = ra0*64 + ((ca0 ^ ((ra0 >> 1) & 3)) << 4);
    uint32_t soA1 = ra1*64 + ((ca1 ^ ((ra1 >> 1) & 3)) << 4);
    const char* gA0 = (const char*)(A + (size_t)(row0 + ra0)*K) + ca0*16;
    const char* gA1 = (const char*)(A + (size_t)(row0 + ra1)*K) + ca1*16;
    int rb = tid >> 3, cb = tid & 7;
    uint32_t soB = rb*128 + ((cb ^ (rb & 7)) << 4);
    const char* g1p = (const char*)(W1c + (size_t)rb*N + col0) + cb*16;
    const char* g3p = (const char*)(W3c + (size_t)rb*N + col0) + cb*16;
    size_t bstep = (size_t)32 * N * 2;

    float acc1[4][2][4], acc3[4][2][4];
    #pragma unroll
    for (int i = 0; i < 4; i++)
        #pragma unroll
        for (int j = 0; j < 2; j++)
            #pragma unroll
            for (int q = 0; q < 4; q++) { acc1[i][j][q] = 0.f; acc3[i][j][q] = 0.f; }

    uint32_t aAddr[4];
    {
        int rr = lid & 15;
        int half = lid >> 4;
        #pragma unroll
        for (int mt = 0; mt < 4; mt++) {
            int row = warp_m*64 + mt*16 + rr;
            aAddr[mt] = row*64 + half;
        }
    }
    int matq = lid >> 3, r8 = lid & 7;

    #pragma unroll
    for (int p = 0; p < 2; p++) {
        uint32_t tA = sb + p*16384, tB1 = tA + 8192, tB3 = tA + 12288;
        asm volatile("cp.async.cg.shared.global [%0], [%1], 16;" :: "r"(tA+soA0),  "l"(gA0 + p*64));
        asm volatile("cp.async.cg.shared.global [%0], [%1], 16;" :: "r"(tA+soA1),  "l"(gA1 + p*64));
        asm volatile("cp.async.cg.shared.global [%0], [%1], 16;" :: "r"(tB1+soB), "l"(g1p + p*bstep));
        asm volatile("cp.async.cg.shared.global [%0], [%1], 16;" :: "r"(tB3+soB), "l"(g3p + p*bstep));
        asm volatile("cp.async.commit_group;");
    }

    int sidx = 0, pidx = 2;
    for (int kt = 0; kt < iters; kt++) {
        if (kt < iters-1) asm volatile("cp.async.wait_group 1;" ::: "memory");
        else              asm volatile("cp.async.wait_group 0;" ::: "memory");
        __syncthreads();

        if (kt + 2 < iters) {
            uint32_t tA = sb + pidx*16384, tB1 = tA + 8192, tB3 = tA + 12288;
            size_t ka = (size_t)(kt + 2) * 64;
            size_t kb = (size_t)(kt + 2) * bstep;
            asm volatile("cp.async.cg.shared.global [%0], [%1], 16;" :: "r"(tA+soA0),  "l"(gA0+ka));
            asm volatile("cp.async.cg.shared.global [%0], [%1], 16;" :: "r"(tA+soA1),  "l"(gA1+ka));
            asm volatile("cp.async.cg.shared.global [%0], [%1], 16;" :: "r"(tB1+soB), "l"(g1p+kb));
            asm volatile("cp.async.cg.shared.global [%0], [%1], 16;" :: "r"(tB3+soB), "l"(g3p+kb));
            asm volatile("cp.async.commit_group;");
        }

        uint32_t sA = sb + sidx*16384, sB1 = sA + 8192, sB3 = sA + 12288;
        #pragma unroll
        for (int ks = 0; ks < 2; ks++) {
            uint32_t a[4][4];
            #pragma unroll
            for (int mt = 0; mt < 4; mt++) {
                int row = (aAddr[mt] >> 6);
                int ck = ks*2 + (aAddr[mt] & 63);
                uint32_t ad = sA + (row*64) + (((ck) ^ ((row >> 1) & 3)) << 4);
                asm volatile("ldmatrix.sync.aligned.m8n8.x4.shared.b16 {%0,%1,%2,%3}, [%4];"
                    : "=r"(a[mt][0]), "=r"(a[mt][1]), "=r"(a[mt][2]), "=r"(a[mt][3]) : "r"(ad));
            }
            int krow = ks*16 + ((matq & 1) << 3) + r8;
            int ch = warp_n*2 + (matq >> 1);
            uint32_t swoff = krow*128 + ((ch ^ (krow & 7)) << 4);
            uint32_t b1[4], b3[4];
            asm volatile("ldmatrix.sync.aligned.m8n8.x4.trans.shared.b16 {%0,%1,%2,%3}, [%4];"
                : "=r"(b1[0]), "=r"(b1[1]), "=r"(b1[2]), "=r"(b1[3]) : "r"(sB1 + swoff));
            asm volatile("ldmatrix.sync.aligned.m8n8.x4.trans.shared.b16 {%0,%1,%2,%3}, [%4];"
                : "=r"(b3[0]), "=r"(b3[1]), "=r"(b3[2]), "=r"(b3[3]) : "r"(sB3 + swoff));
            #pragma unroll
            for (int mt = 0; mt < 4; mt++) {
                #pragma unroll
                for (int nt = 0; nt < 2; nt++) {
                    asm volatile(
                        "mma.sync.aligned.m16n8k16.row.col.f32.bf16.bf16.f32 "
                        "{%0,%1,%2,%3}, {%4,%5,%6,%7}, {%8,%9}, {%0,%1,%2,%3};"
                        : "+f"(acc1[mt][nt][0]), "+f"(acc1[mt][nt][1]),
                          "+f"(acc1[mt][nt][2]), "+f"(acc1[mt][nt][3])
                        : "r"(a[mt][0]), "r"(a[mt][1]), "r"(a[mt][2]), "r"(a[mt][3]),
                          "r"(b1[nt*2]), "r"(b1[nt*2+1]));
                    asm volatile(
                        "mma.sync.aligned.m16n8k16.row.col.f32.bf16.bf16.f32 "
                        "{%0,%1,%2,%3}, {%4,%5,%6,%7}, {%8,%9}, {%0,%1,%2,%3};"
                        : "+f"(acc3[mt][nt][0]), "+f"(acc3[mt][nt][1]),
                          "+f"(acc3[mt][nt][2]), "+f"(acc3[mt][nt][3])
                        : "r"(a[mt][0]), "r"(a[mt][1]), "r"(a[mt][2]), "r"(a[mt][3]),
                          "r"(b3[nt*2]), "r"(b3[nt*2+1]));
                }
            }
        }
        sidx = (sidx == 2) ? 0 : sidx + 1;
        pidx = (pidx == 2) ? 0 : pidx + 1;
    }

    int lr = lid >> 2;
    int lc = (lid & 3) * 2;
    #pragma unroll
    for (int mt = 0; mt < 4; mt++) {
        size_t mrow = (size_t)(row0 + warp_m*64 + mt*16 + lr);
        #pragma unroll
        for (int nt = 0; nt < 2; nt++) {
            int col = col0 + warp_n*16 + nt*8 + lc;
            float s0 = acc1[mt][nt][0], s1 = acc1[mt][nt][1];
            float s2 = acc1[mt][nt][2], s3 = acc1[mt][nt][3];
            float o0 = s0 / (1.f + __expf(-s0)) * acc3[mt][nt][0];
            float o1 = s1 / (1.f + __expf(-s1)) * acc3[mt][nt][1];
            float o2 = s2 / (1.f + __expf(-s2)) * acc3[mt][nt][2];
            float o3 = s3 / (1.f + __expf(-s3)) * acc3[mt][nt][3];
            *(__nv_bfloat162*)(Og + mrow*N + col)     = __floats2bfloat162_rn(o0, o1);
            *(__nv_bfloat162*)(Og + (mrow+8)*N + col) = __floats2bfloat162_rn(o2, o3);
        }
    }
}

// ===========================================================================
// layernorm + RoPE for q and k in one launch
// ===========================================================================
__global__ __launch_bounds__(256) void lnrope2_kernel(
    const float* __restrict__ qf, const float* __restrict__ kf,
    const float* __restrict__ qw, const float* __restrict__ qb,
    const float* __restrict__ kw, const float* __restrict__ kb,
    const float* __restrict__ cosT, const float* __restrict__ sinT,
    __nv_bfloat16* __restrict__ qbf, __nv_bfloat16* __restrict__ kbf)
{
    __shared__ float redm[256], redv[256];
    int sel = blockIdx.y;
    const float* t = sel ? kf : qf;
    const float* w = sel ? kw : qw;
    const float* bvec = sel ? kb : qb;
    __nv_bfloat16* dst = sel ? kbf : qbf;
    int row = blockIdx.x;
    int s = row & (SEQ-1);
    int tid = threadIdx.x;
    float4 v = ((const float4*)(t + (size_t)row*DIM))[tid];
    redm[tid] = v.x + v.y + v.z + v.w;
    redv[tid] = v.x*v.x + v.y*v.y + v.z*v.z + v.w*v.w;
    __syncthreads();
    for (int st = 128; st > 0; st >>= 1) {
        if (tid < st) { redm[tid] += redm[tid+st]; redv[tid] += redv[tid+st]; }
        __syncthreads();
    }
    float mu = redm[0] * (1.f/DIM);
    float var = redv[0] * (1.f/DIM) - mu*mu;
    float rs = rsqrtf(var + 1e-5f);
    int d = tid*4;
    float4 wv = *(const float4*)(w + d);
    float4 bv = *(const float4*)(bvec + d);
    float y0 = (v.x-mu)*rs*wv.x + bv.x;
    float y1 = (v.y-mu)*rs*wv.y + bv.y;
    float y2 = (v.z-mu)*rs*wv.z + bv.z;
    float y3 = (v.w-mu)*rs*wv.w + bv.w;
    int i0 = (d & 63) >> 1;
    float c0 = cosT[s*32 + i0],   s0 = sinT[s*32 + i0];
    float c1 = cosT[s*32 + i0+1], s1 = sinT[s*32 + i0+1];
    float o0 = y0*c0 - y1*s0;
    float o1 = y0*s0 + y1*c0;
    float o2 = y2*c1 - y3*s1;
    float o3 = y2*s1 + y3*c1;
    __nv_bfloat162* dp = (__nv_bfloat162*)(dst + (size_t)row*DIM);
    dp[tid*2]   = __floats2bfloat162_rn(o0, o1);
    dp[tid*2+1] = __floats2bfloat162_rn(o2, o3);
}

// ===========================================================================
// Tensor-core flash attention
// ===========================================================================
#define ATT_SMEM 49152

__global__ __launch_bounds__(256, 1) void attn_mma_kernel(
    const __nv_bfloat16* __restrict__ q, const __nv_bfloat16* __restrict__ k,
    const __nv_bfloat16* __restrict__ v, __nv_bfloat16* __restrict__ o)
{
    extern __shared__ __align__(128) char smch[];
    uint32_t sb = smem_u32(smch);
    const uint32_t sq  = sb;
    const uint32_t sk0 = sb + 16384;
    const uint32_t sv0 = sb + 32768;
    int tid = threadIdx.x, wid = tid >> 5, lid = tid & 31;
    int qt = blockIdx.x, h = blockIdx.y, b = blockIdx.z;
    int hoffb = h * HD * 2;
    int qbase = b*SEQ + qt*128;
    int kbb   = b*SEQ;

    #pragma unroll
    for (int i = 0; i < 4; i++) {
        int cid = tid + 256*i;
        int row = cid >> 3, ch = cid & 7;
        const char* g = (const char*)(q + (size_t)(qbase+row)*DIM) + hoffb + ch*16;
        uint32_t so = sq + row*128 + ((ch ^ (row & 7)) << 4);
        asm volatile("cp.async.cg.shared.global [%0], [%1], 16;" :: "r"(so), "l"(g));
    }
    #pragma unroll
    for (int i = 0; i < 2; i++) {
        int cid = tid + 256*i;
        int row = cid >> 3, ch = cid & 7;
        uint32_t so = row*128 + ((ch ^ (row & 7)) << 4);
        const char* gk = (const char*)(k + (size_t)(kbb+row)*DIM) + hoffb + ch*16;
        const char* gv = (const char*)(v + (size_t)(kbb+row)*DIM) + hoffb + ch*16;
        asm volatile("cp.async.cg.shared.global [%0], [%1], 16;" :: "r"(sk0+so), "l"(gk));
        asm volatile("cp.async.cg.shared.global [%0], [%1], 16;" :: "r"(sv0+so), "l"(gv));
    }
    asm volatile("cp.async.commit_group;");

    int wr = wid * 16;
    uint32_t qf[4][4];
    float oacc[8][4];
    #pragma unroll
    for (int j = 0; j < 8; j++)
        #pragma unroll
        for (int i = 0; i < 4; i++) oacc[j][i] = 0.f;
    float m0 = -INFINITY, m1 = -INFINITY, l0 = 0.f, l1 = 0.f;

    for (int kt = 0; kt < SEQ/64; kt++) {
        int s = kt & 1;
        if (kt + 1 < SEQ/64) {
            int ns = s ^ 1;
            int kb2 = kbb + (kt+1)*64;
            #pragma unroll
            for (int i = 0; i < 2; i++) {
                int cid = tid + 256*i;
                int row = cid >> 3, ch = cid & 7;
                uint32_t so = row*128 + ((ch ^ (row & 7)) << 4);
                const char* gk = (const char*)(k + (size_t)(kb2+row)*DIM) + hoffb + ch*16;
                const char* gv = (const char*)(v + (size_t)(kb2+row)*DIM) + hoffb + ch*16;
                asm volatile("cp.async.cg.shared.global [%0], [%1], 16;" :: "r"(sk0+ns*8192+so), "l"(gk));
                asm volatile("cp.async.cg.shared.global [%0], [%1], 16;" :: "r"(sv0+ns*8192+so), "l"(gv));
            }
            asm volatile("cp.async.commit_group;");
            asm volatile("cp.async.wait_group 1;" ::: "memory");
        } else {
            asm volatile("cp.async.wait_group 0;" ::: "memory");
        }
        __syncthreads();

        if (kt == 0) {
            int arow = wr + (lid & 15);
            #pragma unroll
            for (int s2 = 0; s2 < 4; s2++) {
                int ch = 2*s2 + (lid >> 4);
                uint32_t ad = sq + arow*128 + ((ch ^ (arow & 7)) << 4);
                asm volatile("ldmatrix.sync.aligned.m8n8.x4.shared.b16 {%0,%1,%2,%3}, [%4];"
                    : "=r"(qf[s2][0]), "=r"(qf[s2][1]), "=r"(qf[s2][2]), "=r"(qf[s2][3]) : "r"(ad));
            }
        }
        uint32_t skst = sk0 + s*8192, svst = sv0 + s*8192;

        float sa[8][4];
        #pragma unroll
        for (int j = 0; j < 8; j++)
            #pragma unroll
            for (int i = 0; i < 4; i++) sa[j][i] = 0.f;

        #pragma unroll
        for (int s2 = 0; s2 < 4; s2++) {
            #pragma unroll
            for (int p = 0; p < 4; p++) {
                int mat = lid >> 3;
                int krow = p*16 + ((mat >> 1) << 3) + (lid & 7);
                int ch = 2*s2 + (mat & 1);
                uint32_t ad = skst + krow*128 + ((ch ^ (krow & 7)) << 4);
                uint32_t b0, b1, b2, b3;
                asm volatile("ldmatrix.sync.aligned.m8n8.x4.shared.b16 {%0,%1,%2,%3}, [%4];"
                    : "=r"(b0), "=r"(b1), "=r"(b2), "=r"(b3) : "r"(ad));
                asm volatile(
                    "mma.sync.aligned.m16n8k16.row.col.f32.bf16.bf16.f32 "
                    "{%0,%1,%2,%3}, {%4,%5,%6,%7}, {%8,%9}, {%0,%1,%2,%3};"
                    : "+f"(sa[2*p][0]), "+f"(sa[2*p][1]), "+f"(sa[2*p][2]), "+f"(sa[2*p][3])
                    : "r"(qf[s2][0]), "r"(qf[s2][1]), "r"(qf[s2][2]), "r"(qf[s2][3]),
                      "r"(b0), "r"(b1));
                asm volatile(
                    "mma.sync.aligned.m16n8k16.row.col.f32.bf16.bf16.f32 "
                    "{%0,%1,%2,%3}, {%4,%5,%6,%7}, {%8,%9}, {%0,%1,%2,%3};"
                    : "+f"(sa[2*p+1][0]), "+f"(sa[2*p+1][1]), "+f"(sa[2*p+1][2]), "+f"(sa[2*p+1][3])
                    : "r"(qf[s2][0]), "r"(qf[s2][1]), "r"(qf[s2][2]), "r"(qf[s2][3]),
                      "r"(b2), "r"(b3));
            }
        }

        float mx0 = -INFINITY, mx1 = -INFINITY;
        #pragma unroll
        for (int j = 0; j < 8; j++) {
            sa[j][0] *= 0.125f; sa[j][1] *= 0.125f;
            sa[j][2] *= 0.125f; sa[j][3] *= 0.125f;
            mx0 = fmaxf(mx0, fmaxf(sa[j][0], sa[j][1]));
            mx1 = fmaxf(mx1, fmaxf(sa[j][2], sa[j][3]));
        }
        mx0 = fmaxf(mx0, __shfl_xor_sync(0xffffffffu, mx0, 1));
        mx0 = fmaxf(mx0, __shfl_xor_sync(0xffffffffu, mx0, 2));
        mx1 = fmaxf(mx1, __shfl_xor_sync(0xffffffffu, mx1, 1));
        mx1 = fmaxf(mx1, __shfl_xor_sync(0xffffffffu, mx1, 2));
        float nm0 = fmaxf(m0, mx0), nm1 = fmaxf(m1, mx1);

        float ps0 = 0.f, ps1 = 0.f;
        uint32_t pf[4][4];
        #pragma unroll
        for (int j = 0; j < 8; j++) {
            float e0 = __expf(sa[j][0] - nm0);
            float e1 = __expf(sa[j][1] - nm0);
            float e2 = __expf(sa[j][2] - nm1);
            float e3 = __expf(sa[j][3] - nm1);
            ps0 += e0 + e1; ps1 += e2 + e3;
            int s2 = j >> 1;
            __nv_bfloat162 lo = __floats2bfloat162_rn(e0, e1);
            __nv_bfloat162 hi = __floats2bfloat162_rn(e2, e3);
            if ((j & 1) == 0) {
                pf[s2][0] = *(uint32_t*)&lo;
                pf[s2][1] = *(uint32_t*)&hi;
            } else {
                pf[s2][2] = *(uint32_t*)&lo;
                pf[s2][3] = *(uint32_t*)&hi;
            }
        }
        ps0 += __shfl_xor_sync(0xffffffffu, ps0, 1);
        ps0 += __shfl_xor_sync(0xffffffffu, ps0, 2);
        ps1 += __shfl_xor_sync(0xffffffffu, ps1, 1);
        ps1 += __shfl_xor_sync(0xffffffffu, ps1, 2);

        float c0 = __expf(m0 - nm0), c1 = __expf(m1 - nm1);
        l0 = l0*c0 + ps0;  l1 = l1*c1 + ps1;
        m0 = nm0;  m1 = nm1;
        #pragma unroll
        for (int j = 0; j < 8; j++) {
            oacc[j][0] *= c0; oacc[j][1] *= c0;
            oacc[j][2] *= c1; oacc[j][3] *= c1;
        }

        #pragma unroll
        for (int s2 = 0; s2 < 4; s2++) {
            #pragma unroll
            for (int p = 0; p < 4; p++) {
                int mat = lid >> 3;
                int vrow = s2*16 + ((mat & 1) << 3) + (lid & 7);
                int ch = 2*p + (mat >> 1);
                uint32_t ad = svst + vrow*128 + ((ch ^ (vrow & 7)) << 4);
                uint32_t v0, v1, v2, v3;
                asm volatile("ldmatrix.sync.aligned.m8n8.x4.trans.shared.b16 {%0,%1,%2,%3}, [%4];"
                    : "=r"(v0), "=r"(v1), "=r"(v2), "=r"(v3) : "r"(ad));
                asm volatile(
                    "mma.sync.aligned.m16n8k16.row.col.f32.bf16.bf16.f32 "
                    "{%0,%1,%2,%3}, {%4,%5,%6,%7}, {%8,%9}, {%0,%1,%2,%3};"
                    : "+f"(oacc[2*p][0]), "+f"(oacc[2*p][1]), "+f"(oacc[2*p][2]), "+f"(oacc[2*p][3])
                    : "r"(pf[s2][0]), "r"(pf[s2][1]), "r"(pf[s2][2]), "r"(pf[s2][3]),
                      "r"(v0), "r"(v1));
                asm volatile(
                    "mma.sync.aligned.m16n8k16.row.col.f32.bf16.bf16.f32 "
                    "{%0,%1,%2,%3}, {%4,%5,%6,%7}, {%8,%9}, {%0,%1,%2,%3};"
                    : "+f"(oacc[2*p+1][0]), "+f"(oacc[2*p+1][1]), "+f"(oacc[2*p+1][2]), "+f"(oacc[2*p+1][3])
                    : "r"(pf[s2][0]), "r"(pf[s2][1]), "r"(pf[s2][2]), "r"(pf[s2][3]),
                      "r"(v2), "r"(v3));
            }
        }
        __syncthreads();
    }

    float inv0 = 1.f / l0, inv1 = 1.f / l1;
    int r = lid >> 2, c2 = (lid & 3) * 2;
    size_t row0 = (size_t)(qbase + wr + r)*DIM + h*HD + c2;
    size_t row1 = row0 + 8*DIM;
    #pragma unroll
    for (int j = 0; j < 8; j++) {
        *(__nv_bfloat162*)(o + row0 + 8*j) =
            __floats2bfloat162_rn(oacc[j][0]*inv0, oacc[j][1]*inv0);
        *(__nv_bfloat162*)(o + row1 + 8*j) =
            __floats2bfloat162_rn(oacc[j][2]*inv1, oacc[j][3]*inv1);
    }
}

// ===========================================================================
extern "C" void kernel_launch(void* const* d_in, const int* in_sizes, int n_in,
                              void* d_out, int out_size)
{
    const float* x        = (const float*)d_in[0];
    const float* adaln_in = (const float*)d_in[1];
    const float* cosT     = (const float*)d_in[2];
    const float* sinT     = (const float*)d_in[3];
    const float* wq       = (const float*)d_in[4];
    const float* wk       = (const float*)d_in[5];
    const float* wv       = (const float*)d_in[6];
    const float* wo       = (const float*)d_in[7];
    const float* q_norm_w = (const float*)d_in[8];
    const float* q_norm_b = (const float*)d_in[9];
    const float* k_norm_w = (const float*)d_in[10];
    const float* k_norm_b = (const float*)d_in[11];
    const float* attn_norm_w = (const float*)d_in[12];
    const float* ffn_norm_w  = (const float*)d_in[13];
    const float* ada_w    = (const float*)d_in[14];
    const float* ada_b    = (const float*)d_in[15];
    const float* w1       = (const float*)d_in[16];
    const float* w2       = (const float*)d_in[17];
    const float* w3       = (const float*)d_in[18];
    float* out = (float*)d_out;

    float* base = nullptr;
    cudaGetSymbolAddress((void**)&base, g_buf);
    float* m     = base + OFF_M;
    float* mpart = base + OFF_MPART;
    __nv_bfloat16* hbf  = (__nv_bfloat16*)(base + OFF_HBF);
    float* qf   = base + OFF_QF;
    float* kf   = base + OFF_KF;
    __nv_bfloat16* qbf  = (__nv_bfloat16*)(base + OFF_QBF);
    __nv_bfloat16* kbf  = (__nv_bfloat16*)(base + OFF_KBF);
    __nv_bfloat16* vbf  = (__nv_bfloat16*)(base + OFF_VBF);
    __nv_bfloat16* abf  = (__nv_bfloat16*)(base + OFF_ABF);
    float* xmid = base + OFF_XMID;
    __nv_bfloat16* g1bf = (__nv_bfloat16*)(base + OFF_G1BF);
    __nv_bfloat16* wqC  = (__nv_bfloat16*)(base + OFF_WQC);
    __nv_bfloat16* wkC  = (__nv_bfloat16*)(base + OFF_WKC);
    __nv_bfloat16* wvC  = (__nv_bfloat16*)(base + OFF_WVC);
    __nv_bfloat16* woC  = (__nv_bfloat16*)(base + OFF_WOC);
    __nv_bfloat16* w1C  = (__nv_bfloat16*)(base + OFF_W1C);
    __nv_bfloat16* w3C  = (__nv_bfloat16*)(base + OFF_W3C);
    __nv_bfloat16* w2C  = (__nv_bfloat16*)(base + OFF_W2C);

    cudaFuncSetAttribute(mma_gemm_kernel<2>, cudaFuncAttributeMaxDynamicSharedMemorySize, GSMEM);
    cudaFuncSetAttribute(mma_gemm_kernel<3>, cudaFuncAttributeMaxDynamicSharedMemorySize, GSMEM);
    cudaFuncSetAttribute(ffn_gemm_kernel, cudaFuncAttributeMaxDynamicSharedMemorySize, FSMEM);
    cudaFuncSetAttribute(attn_mma_kernel, cudaFuncAttributeMaxDynamicSharedMemorySize, ATT_SMEM);

    // weight converts (pure streaming, same layout)
    convert2_kernel<<<dim3(DIM*DIM/2048, 2), 256>>>(wq, wk, wqC, wkC);
    convert2_kernel<<<dim3(DIM*DIM/2048, 2), 256>>>(wv, wo, wvC, woC);
    convert3_kernel<<<dim3(DIM*HID/2048, 3), 256>>>(w1, w3, w2, w1C, w3C, w2C);

    // adaLN: split-K partials + deterministic reduce
    adaln_part_kernel<<<dim3(MCOLS/256, KSPLIT), 256>>>(adaln_in, ada_w, mpart);
    adaln_reduce_kernel<<<MCOLS/256, 256>>>(mpart, ada_b, m);

    rmsmod_kernel<<<RR, 256>>>(x, attn_norm_w, m, 0, DIM, hbf);

    // fused QKV projection
    mma_gemm_kernel<3><<<dim3(3*DIM/128, RR/128), 256, GSMEM>>>(
        hbf, wqC, wkC, wvC, DIM, qf, kf, vbf, nullptr, nullptr, 0, RR, DIM, DIM);

    lnrope2_kernel<<<dim3(RR, 2), 256>>>(qf, kf, q_norm_w, q_norm_b, k_norm_w, k_norm_b,
                                         cosT, sinT, qbf, kbf);

    attn_mma_kernel<<<dim3(SEQ/128, NH, BB), 256, ATT_SMEM>>>(qbf, kbf, vbf, abf);

    // wo projection + fused gated residual: xmid = x + gate_msa * (attn@wo)
    mma_gemm_kernel<2><<<dim3(DIM/128, RR/128), 256, GSMEM>>>(
        abf, woC, nullptr, nullptr, DIM, xmid, nullptr, nullptr, x, m, 2*DIM, RR, DIM, DIM);

    rmsmod_kernel<<<RR, 256>>>(xmid, ffn_norm_w, m, 3*DIM, 4*DIM, hbf);

    // fused dual FFN gemm: g1bf = bf16(silu(h@w1) * (h@w3))
    ffn_gemm_kernel<<<dim3(HID/64, RR/128), 256, FSMEM>>>(hbf, w1C, w3C, g1bf, RR, HID, DIM);

    // w2 projection + fused gated residual: out = xmid + gate_mlp * (g@w2)
    mma_gemm_kernel<2><<<dim3(DIM/128, RR/128), 256, GSMEM>>>(
        g1bf, w2C, nullptr, nullptr, DIM, out, nullptr, nullptr, xmid, m, 5*DIM, RR, DIM, HID);
}

// round 11
// speedup vs baseline: 8.1897x; 1.0487x over previous
#include <cuda_runtime.h>
#include <cuda_bf16.h>
#include <math.h>
#include <stdint.h>

#define BB 2
#define SEQ 2048
#define RR (BB*SEQ)          // 4096 rows
#define DIM 1024
#define HID 2816
#define NH 16
#define HD 64
#define MCOLS (6*DIM)        // 6144
#define KSPLIT 32

// ---- scratch (float units) ----
#define SZ_M     16384
#define SZ_MPART (KSPLIT*2*MCOLS)
#define SZ_RD    (RR*DIM)
#define SZ_RDH   (RR*DIM/2)
#define SZ_RHH   (RR*HID/2)
#define SZ_WS    (DIM*DIM/2)
#define SZ_WB    (DIM*HID/2)

#define OFF_M    0
#define OFF_MPART (OFF_M + SZ_M)
#define OFF_HBF  (OFF_MPART + SZ_MPART)
#define OFF_QF   (OFF_HBF + SZ_RDH)
#define OFF_KF   (OFF_QF + SZ_RD)
#define OFF_QBF  (OFF_KF + SZ_RD)
#define OFF_KBF  (OFF_QBF + SZ_RDH)
#define OFF_VBF  (OFF_KBF + SZ_RDH)
#define OFF_ABF  (OFF_VBF + SZ_RDH)
#define OFF_XMID (OFF_ABF + SZ_RDH)
#define OFF_G1BF (OFF_XMID + SZ_RD)
#define OFF_WQC  (OFF_G1BF + SZ_RHH)
#define OFF_WKC  (OFF_WQC + SZ_WS)
#define OFF_WVC  (OFF_WKC + SZ_WS)
#define OFF_WOC  (OFF_WVC + SZ_WS)
#define OFF_W1C  (OFF_WOC + SZ_WS)
#define OFF_W3C  (OFF_W1C + SZ_WB)
#define OFF_W2C  (OFF_W3C + SZ_WB)
#define TOTAL_F  (OFF_W2C + SZ_WB)

__device__ float g_buf[TOTAL_F];

__device__ __forceinline__ uint32_t smem_u32(const void* p) {
    uint32_t a;
    asm("{ .reg .u64 t; cvta.to.shared.u64 t, %1; cvt.u32.u64 %0, t; }" : "=r"(a) : "l"(p));
    return a;
}

// ===========================================================================
// adaLN split-K (32 splits of 32 k each) + deterministic reduce
// ===========================================================================
__global__ __launch_bounds__(256) void adaln_part_kernel(
    const float* __restrict__ a, const float* __restrict__ W,
    float* __restrict__ mpart)
{
    __shared__ float act0[32], act1[32];
    int j = blockIdx.x * 256 + threadIdx.x;
    int k0 = blockIdx.y * 32;
    if (threadIdx.x < 32) {
        float v = a[k0 + threadIdx.x];
        act0[threadIdx.x] = v / (1.f + __expf(-v));
    } else if (threadIdx.x < 64) {
        float v = a[DIM + k0 + threadIdx.x - 32];
        act1[threadIdx.x - 32] = v / (1.f + __expf(-v));
    }
    __syncthreads();
    float acc0 = 0.f, acc1 = 0.f;
    const float* Wp = W + (size_t)k0 * MCOLS + j;
    #pragma unroll 8
    for (int k = 0; k < 32; k++) {
        float w = Wp[(size_t)k * MCOLS];
        acc0 += act0[k] * w;
        acc1 += act1[k] * w;
    }
    mpart[(blockIdx.y*2 + 0)*MCOLS + j] = acc0;
    mpart[(blockIdx.y*2 + 1)*MCOLS + j] = acc1;
}

__global__ __launch_bounds__(256) void adaln_reduce_kernel(
    const float* __restrict__ mpart, const float* __restrict__ bias,
    float* __restrict__ m)
{
    int j = blockIdx.x * 256 + threadIdx.x;
    float b = bias[j];
    float s0 = b, s1 = b;
    #pragma unroll
    for (int kz = 0; kz < KSPLIT; kz++) {
        s0 += mpart[(kz*2 + 0)*MCOLS + j];
        s1 += mpart[(kz*2 + 1)*MCOLS + j];
    }
    m[j] = s0;
    m[MCOLS + j] = s1;
}

// ===========================================================================
// streaming fp32 -> bf16 converts
// ===========================================================================
__device__ __forceinline__ void conv8(const float* s, __nv_bfloat16* d, int i) {
    float4 a = *(const float4*)(s + i);
    float4 b = *(const float4*)(s + i + 4);
    __nv_bfloat162 p0 = __floats2bfloat162_rn(a.x, a.y);
    __nv_bfloat162 p1 = __floats2bfloat162_rn(a.z, a.w);
    __nv_bfloat162 p2 = __floats2bfloat162_rn(b.x, b.y);
    __nv_bfloat162 p3 = __floats2bfloat162_rn(b.z, b.w);
    uint4 o;
    o.x = *(uint32_t*)&p0; o.y = *(uint32_t*)&p1;
    o.z = *(uint32_t*)&p2; o.w = *(uint32_t*)&p3;
    *(uint4*)(d + i) = o;
}

__global__ __launch_bounds__(256) void convert2_kernel(
    const float* __restrict__ s0, const float* __restrict__ s1,
    __nv_bfloat16* __restrict__ d0, __nv_bfloat16* __restrict__ d1)
{
    const float* s = blockIdx.y ? s1 : s0;
    __nv_bfloat16* d = blockIdx.y ? d1 : d0;
    conv8(s, d, (blockIdx.x*256 + threadIdx.x)*8);
}

__global__ __launch_bounds__(256) void convert3_kernel(
    const float* __restrict__ s0, const float* __restrict__ s1, const float* __restrict__ s2,
    __nv_bfloat16* __restrict__ d0, __nv_bfloat16* __restrict__ d1, __nv_bfloat16* __restrict__ d2)
{
    const float* s = (blockIdx.y == 0) ? s0 : (blockIdx.y == 1) ? s1 : s2;
    __nv_bfloat16* d = (blockIdx.y == 0) ? d0 : (blockIdx.y == 1) ? d1 : d2;
    conv8(s, d, (blockIdx.x*256 + threadIdx.x)*8);
}

// ===========================================================================
// rmsnorm + modulate -> bf16
// ===========================================================================
__global__ __launch_bounds__(256) void rmsmod_kernel(
    const float* __restrict__ src, const float* __restrict__ w,
    const float* __restrict__ m, int shift_off, int scale_off,
    __nv_bfloat16* __restrict__ dst)
{
    __shared__ float red[256];
    int row = blockIdx.x;
    int b = row >> 11;
    int tid = threadIdx.x;
    float4 v = ((const float4*)(src + (size_t)row*DIM))[tid];
    red[tid] = v.x*v.x + v.y*v.y + v.z*v.z + v.w*v.w;
    __syncthreads();
    for (int s = 128; s > 0; s >>= 1) {
        if (tid < s) red[tid] += red[tid+s];
        __syncthreads();
    }
    float rms = rsqrtf(red[0] * (1.f/DIM) + 1e-5f);
    int d = tid * 4;
    float4 wv = *(const float4*)(w + d);
    float4 sh = *(const float4*)(m + b*MCOLS + shift_off + d);
    float4 sc = *(const float4*)(m + b*MCOLS + scale_off + d);
    float o0 = v.x*rms*wv.x*(1.f+sc.x) + sh.x;
    float o1 = v.y*rms*wv.y*(1.f+sc.y) + sh.y;
    float o2 = v.z*rms*wv.z*(1.f+sc.z) + sh.z;
    float o3 = v.w*rms*wv.w*(1.f+sc.w) + sh.w;
    __nv_bfloat162* dp = (__nv_bfloat162*)(dst + (size_t)row*DIM);
    dp[tid*2]   = __floats2bfloat162_rn(o0, o1);
    dp[tid*2+1] = __floats2bfloat162_rn(o2, o3);
}

// ===========================================================================
// bf16 mma GEMM, BK=64: A [M,K] k-contig, 128B rows; B [K,N] n-contig, 256B
// rows; 3-stage cp.async (32KB/stage). MODE 2: C = xres + gate*acc (fp32).
// MODE 3: fused QKV.
// ===========================================================================
#define GSMEM (3*32768)

template<int MODE>
__global__ __launch_bounds__(256) void mma_gemm_kernel(
    const __nv_bfloat16* __restrict__ A,
    const __nv_bfloat16* __restrict__ B0,
    const __nv_bfloat16* __restrict__ B1m,
    const __nv_bfloat16* __restrict__ B2m,
    int ldb,
    float* __restrict__ Cf,
    float* __restrict__ kf,
    __nv_bfloat16* __restrict__ vbf,
    const float* __restrict__ xres,
    const float* __restrict__ mvec, int gate_off,
    int M, int N, int K)
{
    extern __shared__ __align__(128) char smch[];
    uint32_t sb = smem_u32(smch);
    int tid = threadIdx.x;
    int wid = tid >> 5, lid = tid & 31;
    int warp_m = wid & 1;
    int warp_n = wid >> 1;
    int row0 = blockIdx.y * 128;
    int col0 = blockIdx.x * 128;
    int iters = K >> 6;

    const __nv_bfloat16* B = B0;
    int msel = 0, colB = col0;
    if (MODE == 3) {
        msel = col0 >> 10;
        colB = col0 & 1023;
        B = (msel == 0) ? B0 : (msel == 1) ? B1m : B2m;
    }

    // A tile: 128 rows x 128B (8 chunks); 1024 chunks -> 4 per thread
    uint32_t soA[4]; const char* gA[4];
    #pragma unroll
    for (int i = 0; i < 4; i++) {
        int cid = tid + 256*i;
        int row = cid >> 3, ch = cid & 7;
        soA[i] = row*128 + ((ch ^ (row & 7)) << 4);
        gA[i] = (const char*)(A + (size_t)(row0 + row)*K) + ch*16;
    }
    // B tile: 64 rows x 256B (16 chunks); 1024 chunks -> 4 per thread
    uint32_t soB[4]; const char* gB[4];
    #pragma unroll
    for (int i = 0; i < 4; i++) {
        int cid = tid + 256*i;
        int rb = cid >> 4, cb = cid & 15;
        soB[i] = rb*256 + ((cb ^ (rb & 7)) << 4);
        gB[i] = (const char*)(B + (size_t)rb*ldb + colB) + cb*16;
    }
    size_t bstep = (size_t)64 * ldb * 2;

    float acc[4][4][4];
    #pragma unroll
    for (int i = 0; i < 4; i++)
        #pragma unroll
        for (int j = 0; j < 4; j++)
            #pragma unroll
            for (int q = 0; q < 4; q++) acc[i][j][q] = 0.f;

    int arow[4];
    #pragma unroll
    for (int mt = 0; mt < 4; mt++)
        arow[mt] = warp_m*64 + mt*16 + (lid & 15);
    int ahalf = lid >> 4;
    int matq = lid >> 3, r8 = lid & 7;

    #pragma unroll
    for (int p = 0; p < 2; p++) {
        uint32_t tA = sb + p*32768, tB = tA + 16384;
        #pragma unroll
        for (int i = 0; i < 4; i++) {
            asm volatile("cp.async.cg.shared.global [%0], [%1], 16;" :: "r"(tA+soA[i]), "l"(gA[i] + p*128));
            asm volatile("cp.async.cg.shared.global [%0], [%1], 16;" :: "r"(tB+soB[i]), "l"(gB[i] + p*bstep));
        }
        asm volatile("cp.async.commit_group;");
    }

    int sidx = 0, pidx = 2;
    for (int kt = 0; kt < iters; kt++) {
        if (kt < iters-1) asm volatile("cp.async.wait_group 1;" ::: "memory");
        else              asm volatile("cp.async.wait_group 0;" ::: "memory");
        __syncthreads();

        if (kt + 2 < iters) {
            uint32_t tA = sb + pidx*32768, tB = tA + 16384;
            size_t ka = (size_t)(kt + 2) * 128;
            size_t kb = (size_t)(kt + 2) * bstep;
            #pragma unroll
            for (int i = 0; i < 4; i++) {
                asm volatile("cp.async.cg.shared.global [%0], [%1], 16;" :: "r"(tA+soA[i]), "l"(gA[i]+ka));
                asm volatile("cp.async.cg.shared.global [%0], [%1], 16;" :: "r"(tB+soB[i]), "l"(gB[i]+kb));
            }
            asm volatile("cp.async.commit_group;");
        }

        uint32_t sA = sb + sidx*32768, sB = sA + 16384;
        #pragma unroll
        for (int ks = 0; ks < 4; ks++) {
            uint32_t a[4][4], b[4][2];
            #pragma unroll
            for (int mt = 0; mt < 4; mt++) {
                int row = arow[mt];
                int ck = ks*2 + ahalf;
                uint32_t ad = sA + row*128 + ((ck ^ (row & 7)) << 4);
                asm volatile("ldmatrix.sync.aligned.m8n8.x4.shared.b16 {%0,%1,%2,%3}, [%4];"
                    : "=r"(a[mt][0]), "=r"(a[mt][1]), "=r"(a[mt][2]), "=r"(a[mt][3]) : "r"(ad));
            }
            #pragma unroll
            for (int nt2 = 0; nt2 < 2; nt2++) {
                int krow = ks*16 + ((matq & 1) << 3) + r8;
                int ch = warp_n*4 + nt2*2 + (matq >> 1);
                uint32_t ad = sB + krow*256 + ((ch ^ (krow & 7)) << 4);
                asm volatile("ldmatrix.sync.aligned.m8n8.x4.trans.shared.b16 {%0,%1,%2,%3}, [%4];"
                    : "=r"(b[nt2*2][0]), "=r"(b[nt2*2][1]),
                      "=r"(b[nt2*2+1][0]), "=r"(b[nt2*2+1][1]) : "r"(ad));
            }
            #pragma unroll
            for (int mt = 0; mt < 4; mt++)
                #pragma unroll
                for (int nt = 0; nt < 4; nt++) {
                    asm volatile(
                        "mma.sync.aligned.m16n8k16.row.col.f32.bf16.bf16.f32 "
                        "{%0,%1,%2,%3}, {%4,%5,%6,%7}, {%8,%9}, {%0,%1,%2,%3};"
                        : "+f"(acc[mt][nt][0]), "+f"(acc[mt][nt][1]),
                          "+f"(acc[mt][nt][2]), "+f"(acc[mt][nt][3])
                        : "r"(a[mt][0]), "r"(a[mt][1]), "r"(a[mt][2]), "r"(a[mt][3]),
                          "r"(b[nt][0]), "r"(b[nt][1]));
                }
        }
        sidx = (sidx == 2) ? 0 : sidx + 1;
        pidx = (pidx == 2) ? 0 : pidx + 1;
    }

    int lr = lid >> 2;
    int lc = (lid & 3) * 2;
    if (MODE == 2) {
        int bsel = row0 >> 11;
        const float* gv = mvec + bsel*MCOLS + gate_off;
        #pragma unroll
        for (int mt = 0; mt < 4; mt++) {
            size_t mrow = (size_t)(row0 + warp_m*64 + mt*16 + lr);
            #pragma unroll
            for (int nt = 0; nt < 4; nt++) {
                int col = col0 + warp_n*32 + nt*8 + lc;
                float2 g = *(const float2*)(gv + col);
                float2 x0 = *(const float2*)(xres + mrow*N + col);
                float2 x1 = *(const float2*)(xres + (mrow+8)*N + col);
                *(float2*)(Cf + mrow*N + col) =
                    make_float2(x0.x + g.x*acc[mt][nt][0], x0.y + g.y*acc[mt][nt][1]);
                *(float2*)(Cf + (mrow+8)*N + col) =
                    make_float2(x1.x + g.x*acc[mt][nt][2], x1.y + g.y*acc[mt][nt][3]);
            }
        }
    } else {  // MODE 3
        #pragma unroll
        for (int mt = 0; mt < 4; mt++) {
            size_t mrow = (size_t)(row0 + warp_m*64 + mt*16 + lr);
            #pragma unroll
            for (int nt = 0; nt < 4; nt++) {
                int col = colB + warp_n*32 + nt*8 + lc;
                if (msel == 2) {
                    *(__nv_bfloat162*)(vbf + mrow*DIM + col) =
                        __floats2bfloat162_rn(acc[mt][nt][0], acc[mt][nt][1]);
                    *(__nv_bfloat162*)(vbf + (mrow+8)*DIM + col) =
                        __floats2bfloat162_rn(acc[mt][nt][2], acc[mt][nt][3]);
                } else {
                    float* dst = msel ? kf : Cf;
                    *(float2*)(dst + mrow*DIM + col) =
                        make_float2(acc[mt][nt][0], acc[mt][nt][1]);
                    *(float2*)(dst + (mrow+8)*DIM + col) =
                        make_float2(acc[mt][nt][2], acc[mt][nt][3]);
                }
            }
        }
    }
}

// ===========================================================================
// Fused FFN dual GEMM, BK=64: g = bf16( silu(A@W1) * (A@W3) )
// stage: A 16KB + B1 8KB + B3 8KB = 32KB, 3 stages.
// ===========================================================================
#define FSMEM (3*32768)

__global__ __launch_bounds__(256) void ffn_gemm_kernel(
    const __nv_bfloat16* __restrict__ A,
    const __nv_bfloat16* __restrict__ W1c,
    const __nv_bfloat16* __restrict__ W3c,
    __nv_bfloat16* __restrict__ Og, int M, int N, int K)
{
    extern __shared__ __align__(128) char smch[];
    uint32_t sb = smem_u32(smch);
    int tid = threadIdx.x;
    int wid = tid >> 5, lid = tid & 31;
    int warp_m = wid & 1;
    int warp_n = wid >> 1;
    int row0 = blockIdx.y * 128;
    int col0 = blockIdx.x * 64;
    int iters = K >> 6;

    uint32_t soA[4]; const char* gA[4];
    #pragma unroll
    for (int i = 0; i < 4; i++) {
        int cid = tid + 256*i;
        int row = cid >> 3, ch = cid & 7;
        soA[i] = row*128 + ((ch ^ (row & 7)) << 4);
        gA[i] = (const char*)(A + (size_t)(row0 + row)*K) + ch*16;
    }
    // B: 64 rows x 128B = 512 chunks per matrix -> 2 per thread each
    uint32_t soB[2]; const char *g1[2], *g3[2];
    #pragma unroll
    for (int i = 0; i < 2; i++) {
        int cid = tid + 256*i;
        int rb = cid >> 3, cb = cid & 7;
        soB[i] = rb*128 + ((cb ^ (rb & 7)) << 4);
        g1[i] = (const char*)(W1c + (size_t)rb*N + col0) + cb*16;
        g3[i] = (const char*)(W3c + (size_t)rb*N + col0) + cb*16;
    }
    size_t bstep = (size_t)64 * N * 2;

    float acc1[4][2][4], acc3[4][2][4];
    #pragma unroll
    for (int i = 0; i < 4; i++)
        #pragma unroll
        for (int j = 0; j < 2; j++)
            #pragma unroll
            for (int q = 0; q < 4; q++) { acc1[i][j][q] = 0.f; acc3[i][j][q] = 0.f; }

    int arow[4];
    #pragma unroll
    for (int mt = 0; mt < 4; mt++)
        arow[mt] = warp_m*64 + mt*16 + (lid & 15);
    int ahalf = lid >> 4;
    int matq = lid >> 3, r8 = lid & 7;

    #pragma unroll
    for (int p = 0; p < 2; p++) {
        uint32_t tA = sb + p*32768, tB1 = tA + 16384, tB3 = tA + 24576;
        #pragma unroll
        for (int i = 0; i < 4; i++)
            asm volatile("cp.async.cg.shared.global [%0], [%1], 16;" :: "r"(tA+soA[i]), "l"(gA[i] + p*128));
        #pragma unroll
        for (int i = 0; i < 2; i++) {
            asm volatile("cp.async.cg.shared.global [%0], [%1], 16;" :: "r"(tB1+soB[i]), "l"(g1[i] + p*bstep));
            asm volatile("cp.async.cg.shared.global [%0], [%1], 16;" :: "r"(tB3+soB[i]), "l"(g3[i] + p*bstep));
        }
        asm volatile("cp.async.commit_group;");
    }

    int sidx = 0, pidx = 2;
    for (int kt = 0; kt < iters; kt++) {
        if (kt < iters-1) asm volatile("cp.async.wait_group 1;" ::: "memory");
        else              asm volatile("cp.async.wait_group 0;" ::: "memory");
        __syncthreads();

        if (kt + 2 < iters) {
            uint32_t tA = sb + pidx*32768, tB1 = tA + 16384, tB3 = tA + 24576;
            size_t ka = (size_t)(kt + 2) * 128;
            size_t kb = (size_t)(kt + 2) * bstep;
            #pragma unroll
            for (int i = 0; i < 4; i++)
                asm volatile("cp.async.cg.shared.global [%0], [%1], 16;" :: "r"(tA+soA[i]), "l"(gA[i]+ka));
            #pragma unroll
            for (int i = 0; i < 2; i++) {
                asm volatile("cp.async.cg.shared.global [%0], [%1], 16;" :: "r"(tB1+soB[i]), "l"(g1[i]+kb));
                asm volatile("cp.async.cg.shared.global [%0], [%1], 16;" :: "r"(tB3+soB[i]), "l"(g3[i]+kb));
            }
            asm volatile("cp.async.commit_group;");
        }

        uint32_t sA = sb + sidx*32768, sB1 = sA + 16384, sB3 = sA + 24576;
        #pragma unroll
        for (int ks = 0; ks < 4; ks++) {
            uint32_t a[4][4];
            #pragma unroll
            for (int mt = 0; mt < 4; mt++) {
                int row = arow[mt];
                int ck = ks*2 + ahalf;
                uint32_t ad = sA + row*128 + ((ck ^ (row & 7)) << 4);
                asm volatile("ldmatrix.sync.aligned.m8n8.x4.shared.b16 {%0,%1,%2,%3}, [%4];"
                    : "=r"(a[mt][0]), "=r"(a[mt][1]), "=r"(a[mt][2]), "=r"(a[mt][3]) : "r"(ad));
            }
            int krow = ks*16 + ((matq & 1) << 3) + r8;
            int ch = warp_n*2 + (matq >> 1);
            uint32_t swoff = krow*128 + ((ch ^ (krow & 7)) << 4);
            uint32_t b1[4], b3[4];
            asm volatile("ldmatrix.sync.aligned.m8n8.x4.trans.shared.b16 {%0,%1,%2,%3}, [%4];"
                : "=r"(b1[0]), "=r"(b1[1]), "=r"(b1[2]), "=r"(b1[3]) : "r"(sB1 + swoff));
            asm volatile("ldmatrix.sync.aligned.m8n8.x4.trans.shared.b16 {%0,%1,%2,%3}, [%4];"
                : "=r"(b3[0]), "=r"(b3[1]), "=r"(b3[2]), "=r"(b3[3]) : "r"(sB3 + swoff));
            #pragma unroll
            for (int mt = 0; mt < 4; mt++) {
                #pragma unroll
                for (int nt = 0; nt < 2; nt++) {
                    asm volatile(
                        "mma.sync.aligned.m16n8k16.row.col.f32.bf16.bf16.f32 "
                        "{%0,%1,%2,%3}, {%4,%5,%6,%7}, {%8,%9}, {%0,%1,%2,%3};"
                        : "+f"(acc1[mt][nt][0]), "+f"(acc1[mt][nt][1]),
                          "+f"(acc1[mt][nt][2]), "+f"(acc1[mt][nt][3])
                        : "r"(a[mt][0]), "r"(a[mt][1]), "r"(a[mt][2]), "r"(a[mt][3]),
                          "r"(b1[nt*2]), "r"(b1[nt*2+1]));
                    asm volatile(
                        "mma.sync.aligned.m16n8k16.row.col.f32.bf16.bf16.f32 "
                        "{%0,%1,%2,%3}, {%4,%5,%6,%7}, {%8,%9}, {%0,%1,%2,%3};"
                        : "+f"(acc3[mt][nt][0]), "+f"(acc3[mt][nt][1]),
                          "+f"(acc3[mt][nt][2]), "+f"(acc3[mt][nt][3])
                        : "r"(a[mt][0]), "r"(a[mt][1]), "r"(a[mt][2]), "r"(a[mt][3]),
                          "r"(b3[nt*2]), "r"(b3[nt*2+1]));
                }
            }
        }
        sidx = (sidx == 2) ? 0 : sidx + 1;
        pidx = (pidx == 2) ? 0 : pidx + 1;
    }

    int lr = lid >> 2;
    int lc = (lid & 3) * 2;
    #pragma unroll
    for (int mt = 0; mt < 4; mt++) {
        size_t mrow = (size_t)(row0 + warp_m*64 + mt*16 + lr);
        #pragma unroll
        for (int nt = 0; nt < 2; nt++) {
            int col = col0 + warp_n*16 + nt*8 + lc;
            float s0 = acc1[mt][nt][0], s1 = acc1[mt][nt][1];
            float s2 = acc1[mt][nt][2], s3 = acc1[mt][nt][3];
            float o0 = s0 / (1.f + __expf(-s0)) * acc3[mt][nt][0];
            float o1 = s1 / (1.f + __expf(-s1)) * acc3[mt][nt][1];
            float o2 = s2 / (1.f + __expf(-s2)) * acc3[mt][nt][2];
            float o3 = s3 / (1.f + __expf(-s3)) * acc3[mt][nt][3];
            *(__nv_bfloat162*)(Og + mrow*N + col)     = __floats2bfloat162_rn(o0, o1);
            *(__nv_bfloat162*)(Og + (mrow+8)*N + col) = __floats2bfloat162_rn(o2, o3);
        }
    }
}

// ===========================================================================
// layernorm + RoPE for q and k in one launch
// ===========================================================================
__global__ __launch_bounds__(256) void lnrope2_kernel(
    const float* __restrict__ qf, const float* __restrict__ kf,
    const float* __restrict__ qw, const float* __restrict__ qb,
    const float* __restrict__ kw, const float* __restrict__ kb,
    const float* __restrict__ cosT, const float* __restrict__ sinT,
    __nv_bfloat16* __restrict__ qbf, __nv_bfloat16* __restrict__ kbf)
{
    __shared__ float redm[256], redv[256];
    int sel = blockIdx.y;
    const float* t = sel ? kf : qf;
    const float* w = sel ? kw : qw;
    const float* bvec = sel ? kb : qb;
    __nv_bfloat16* dst = sel ? kbf : qbf;
    int row = blockIdx.x;
    int s = row & (SEQ-1);
    int tid = threadIdx.x;
    float4 v = ((const float4*)(t + (size_t)row*DIM))[tid];
    redm[tid] = v.x + v.y + v.z + v.w;
    redv[tid] = v.x*v.x + v.y*v.y + v.z*v.z + v.w*v.w;
    __syncthreads();
    for (int st = 128; st > 0; st >>= 1) {
        if (tid < st) { redm[tid] += redm[tid+st]; redv[tid] += redv[tid+st]; }
        __syncthreads();
    }
    float mu = redm[0] * (1.f/DIM);
    float var = redv[0] * (1.f/DIM) - mu*mu;
    float rs = rsqrtf(var + 1e-5f);
    int d = tid*4;
    float4 wv = *(const float4*)(w + d);
    float4 bv = *(const float4*)(bvec + d);
    float y0 = (v.x-mu)*rs*wv.x + bv.x;
    float y1 = (v.y-mu)*rs*wv.y + bv.y;
    float y2 = (v.z-mu)*rs*wv.z + bv.z;
    float y3 = (v.w-mu)*rs*wv.w + bv.w;
    int i0 = (d & 63) >> 1;
    float c0 = cosT[s*32 + i0],   s0 = sinT[s*32 + i0];
    float c1 = cosT[s*32 + i0+1], s1 = sinT[s*32 + i0+1];
    float o0 = y0*c0 - y1*s0;
    float o1 = y0*s0 + y1*c0;
    float o2 = y2*c1 - y3*s1;
    float o3 = y2*s1 + y3*c1;
    __nv_bfloat162* dp = (__nv_bfloat162*)(dst + (size_t)row*DIM);
    dp[tid*2]   = __floats2bfloat162_rn(o0, o1);
    dp[tid*2+1] = __floats2bfloat162_rn(o2, o3);
}

// ===========================================================================
// Tensor-core flash attention
// ===========================================================================
#define ATT_SMEM 49152

__global__ __launch_bounds__(256, 1) void attn_mma_kernel(
    const __nv_bfloat16* __restrict__ q, const __nv_bfloat16* __restrict__ k,
    const __nv_bfloat16* __restrict__ v, __nv_bfloat16* __restrict__ o)
{
    extern __shared__ __align__(128) char smch[];
    uint32_t sb = smem_u32(smch);
    const uint32_t sq  = sb;
    const uint32_t sk0 = sb + 16384;
    const uint32_t sv0 = sb + 32768;
    int tid = threadIdx.x, wid = tid >> 5, lid = tid & 31;
    int qt = blockIdx.x, h = blockIdx.y, b = blockIdx.z;
    int hoffb = h * HD * 2;
    int qbase = b*SEQ + qt*128;
    int kbb   = b*SEQ;

    #pragma unroll
    for (int i = 0; i < 4; i++) {
        int cid = tid + 256*i;
        int row = cid >> 3, ch = cid & 7;
        const char* g = (const char*)(q + (size_t)(qbase+row)*DIM) + hoffb + ch*16;
        uint32_t so = sq + row*128 + ((ch ^ (row & 7)) << 4);
        asm volatile("cp.async.cg.shared.global [%0], [%1], 16;" :: "r"(so), "l"(g));
    }
    #pragma unroll
    for (int i = 0; i < 2; i++) {
        int cid = tid + 256*i;
        int row = cid >> 3, ch = cid & 7;
        uint32_t so = row*128 + ((ch ^ (row & 7)) << 4);
        const char* gk = (const char*)(k + (size_t)(kbb+row)*DIM) + hoffb + ch*16;
        const char* gv = (const char*)(v + (size_t)(kbb+row)*DIM) + hoffb + ch*16;
        asm volatile("cp.async.cg.shared.global [%0], [%1], 16;" :: "r"(sk0+so), "l"(gk));
        asm volatile("cp.async.cg.shared.global [%0], [%1], 16;" :: "r"(sv0+so), "l"(gv));
    }
    asm volatile("cp.async.commit_group;");

    int wr = wid * 16;
    uint32_t qf[4][4];
    float oacc[8][4];
    #pragma unroll
    for (int j = 0; j < 8; j++)
        #pragma unroll
        for (int i = 0; i < 4; i++) oacc[j][i] = 0.f;
    float m0 = -INFINITY, m1 = -INFINITY, l0 = 0.f, l1 = 0.f;

    for (int kt = 0; kt < SEQ/64; kt++) {
        int s = kt & 1;
        if (kt + 1 < SEQ/64) {
            int ns = s ^ 1;
            int kb2 = kbb + (kt+1)*64;
            #pragma unroll
            for (int i = 0; i < 2; i++) {
                int cid = tid + 256*i;
                int row = cid >> 3, ch = cid & 7;
                uint32_t so = row*128 + ((ch ^ (row & 7)) << 4);
                const char* gk = (const char*)(k + (size_t)(kb2+row)*DIM) + hoffb + ch*16;
                const char* gv = (const char*)(v + (size_t)(kb2+row)*DIM) + hoffb + ch*16;
                asm volatile("cp.async.cg.shared.global [%0], [%1], 16;" :: "r"(sk0+ns*8192+so), "l"(gk));
                asm volatile("cp.async.cg.shared.global [%0], [%1], 16;" :: "r"(sv0+ns*8192+so), "l"(gv));
            }
            asm volatile("cp.async.commit_group;");
            asm volatile("cp.async.wait_group 1;" ::: "memory");
        } else {
            asm volatile("cp.async.wait_group 0;" ::: "memory");
        }
        __syncthreads();

        if (kt == 0) {
            int arow2 = wr + (lid & 15);
            #pragma unroll
            for (int s2 = 0; s2 < 4; s2++) {
                int ch = 2*s2 + (lid >> 4);
                uint32_t ad = sq + arow2*128 + ((ch ^ (arow2 & 7)) << 4);
                asm volatile("ldmatrix.sync.aligned.m8n8.x4.shared.b16 {%0,%1,%2,%3}, [%4];"
                    : "=r"(qf[s2][0]), "=r"(qf[s2][1]), "=r"(qf[s2][2]), "=r"(qf[s2][3]) : "r"(ad));
            }
        }
        uint32_t skst = sk0 + s*8192, svst = sv0 + s*8192;

        float sa[8][4];
        #pragma unroll
        for (int j = 0; j < 8; j++)
            #pragma unroll
            for (int i = 0; i < 4; i++) sa[j][i] = 0.f;

        #pragma unroll
        for (int s2 = 0; s2 < 4; s2++) {
            #pragma unroll
            for (int p = 0; p < 4; p++) {
                int mat = lid >> 3;
                int krow = p*16 + ((mat >> 1) << 3) + (lid & 7);
                int ch = 2*s2 + (mat & 1);
                uint32_t ad = skst + krow*128 + ((ch ^ (krow & 7)) << 4);
                uint32_t b0, b1, b2, b3;
                asm volatile("ldmatrix.sync.aligned.m8n8.x4.shared.b16 {%0,%1,%2,%3}, [%4];"
                    : "=r"(b0), "=r"(b1), "=r"(b2), "=r"(b3) : "r"(ad));
                asm volatile(
                    "mma.sync.aligned.m16n8k16.row.col.f32.bf16.bf16.f32 "
                    "{%0,%1,%2,%3}, {%4,%5,%6,%7}, {%8,%9}, {%0,%1,%2,%3};"
                    : "+f"(sa[2*p][0]), "+f"(sa[2*p][1]), "+f"(sa[2*p][2]), "+f"(sa[2*p][3])
                    : "r"(qf[s2][0]), "r"(qf[s2][1]), "r"(qf[s2][2]), "r"(qf[s2][3]),
                      "r"(b0), "r"(b1));
                asm volatile(
                    "mma.sync.aligned.m16n8k16.row.col.f32.bf16.bf16.f32 "
                    "{%0,%1,%2,%3}, {%4,%5,%6,%7}, {%8,%9}, {%0,%1,%2,%3};"
                    : "+f"(sa[2*p+1][0]), "+f"(sa[2*p+1][1]), "+f"(sa[2*p+1][2]), "+f"(sa[2*p+1][3])
                    : "r"(qf[s2][0]), "r"(qf[s2][1]), "r"(qf[s2][2]), "r"(qf[s2][3]),
                      "r"(b2), "r"(b3));
            }
        }

        float mx0 = -INFINITY, mx1 = -INFINITY;
        #pragma unroll
        for (int j = 0; j < 8; j++) {
            sa[j][0] *= 0.125f; sa[j][1] *= 0.125f;
            sa[j][2] *= 0.125f; sa[j][3] *= 0.125f;
            mx0 = fmaxf(mx0, fmaxf(sa[j][0], sa[j][1]));
            mx1 = fmaxf(mx1, fmaxf(sa[j][2], sa[j][3]));
        }
        mx0 = fmaxf(mx0, __shfl_xor_sync(0xffffffffu, mx0, 1));
        mx0 = fmaxf(mx0, __shfl_xor_sync(0xffffffffu, mx0, 2));
        mx1 = fmaxf(mx1, __shfl_xor_sync(0xffffffffu, mx1, 1));
        mx1 = fmaxf(mx1, __shfl_xor_sync(0xffffffffu, mx1, 2));
        float nm0 = fmaxf(m0, mx0), nm1 = fmaxf(m1, mx1);

        float ps0 = 0.f, ps1 = 0.f;
        uint32_t pf[4][4];
        #pragma unroll
        for (int j = 0; j < 8; j++) {
            float e0 = __expf(sa[j][0] - nm0);
            float e1 = __expf(sa[j][1] - nm0);
            float e2 = __expf(sa[j][2] - nm1);
            float e3 = __expf(sa[j][3] - nm1);
            ps0 += e0 + e1; ps1 += e2 + e3;
            int s2 = j >> 1;
            __nv_bfloat162 lo = __floats2bfloat162_rn(e0, e1);
            __nv_bfloat162 hi = __floats2bfloat162_rn(e2, e3);
            if ((j & 1) == 0) {
                pf[s2][0] = *(uint32_t*)&lo;
                pf[s2][1] = *(uint32_t*)&hi;
            } else {
                pf[s2][2] = *(uint32_t*)&lo;
                pf[s2][3] = *(uint32_t*)&hi;
            }
        }
        ps0 += __shfl_xor_sync(0xffffffffu, ps0, 1);
        ps0 += __shfl_xor_sync(0xffffffffu, ps0, 2);
        ps1 += __shfl_xor_sync(0xffffffffu, ps1, 1);
        ps1 += __shfl_xor_sync(0xffffffffu, ps1, 2);

        float c0 = __expf(m0 - nm0), c1 = __expf(m1 - nm1);
        l0 = l0*c0 + ps0;  l1 = l1*c1 + ps1;
        m0 = nm0;  m1 = nm1;
        #pragma unroll
        for (int j = 0; j < 8; j++) {
            oacc[j][0] *= c0; oacc[j][1] *= c0;
            oacc[j][2] *= c1; oacc[j][3] *= c1;
        }

        #pragma unroll
        for (int s2 = 0; s2 < 4; s2++) {
            #pragma unroll
            for (int p = 0; p < 4; p++) {
                int mat = lid >> 3;
                int vrow = s2*16 + ((mat & 1) << 3) + (lid & 7);
                int ch = 2*p + (mat >> 1);
                uint32_t ad = svst + vrow*128 + ((ch ^ (vrow & 7)) << 4);
                uint32_t v0, v1, v2, v3;
                asm volatile("ldmatrix.sync.aligned.m8n8.x4.trans.shared.b16 {%0,%1,%2,%3}, [%4];"
                    : "=r"(v0), "=r"(v1), "=r"(v2), "=r"(v3) : "r"(ad));
                asm volatile(
                    "mma.sync.aligned.m16n8k16.row.col.f32.bf16.bf16.f32 "
                    "{%0,%1,%2,%3}, {%4,%5,%6,%7}, {%8,%9}, {%0,%1,%2,%3};"
                    : "+f"(oacc[2*p][0]), "+f"(oacc[2*p][1]), "+f"(oacc[2*p][2]), "+f"(oacc[2*p][3])
                    : "r"(pf[s2][0]), "r"(pf[s2][1]), "r"(pf[s2][2]), "r"(pf[s2][3]),
                      "r"(v0), "r"(v1));
                asm volatile(
                    "mma.sync.aligned.m16n8k16.row.col.f32.bf16.bf16.f32 "
                    "{%0,%1,%2,%3}, {%4,%5,%6,%7}, {%8,%9}, {%0,%1,%2,%3};"
                    : "+f"(oacc[2*p+1][0]), "+f"(oacc[2*p+1][1]), "+f"(oacc[2*p+1][2]), "+f"(oacc[2*p+1][3])
                    : "r"(pf[s2][0]), "r"(pf[s2][1]), "r"(pf[s2][2]), "r"(pf[s2][3]),
                      "r"(v2), "r"(v3));
            }
        }
        __syncthreads();
    }

    float inv0 = 1.f / l0, inv1 = 1.f / l1;
    int r = lid >> 2, c2 = (lid & 3) * 2;
    size_t row0 = (size_t)(qbase + wr + r)*DIM + h*HD + c2;
    size_t row1 = row0 + 8*DIM;
    #pragma unroll
    for (int j = 0; j < 8; j++) {
        *(__nv_bfloat162*)(o + row0 + 8*j) =
            __floats2bfloat162_rn(oacc[j][0]*inv0, oacc[j][1]*inv0);
        *(__nv_bfloat162*)(o + row1 + 8*j) =
            __floats2bfloat162_rn(oacc[j][2]*inv1, oacc[j][3]*inv1);
    }
}

// ===========================================================================
extern "C" void kernel_launch(void* const* d_in, const int* in_sizes, int n_in,
                              void* d_out, int out_size)
{
    const float* x        = (const float*)d_in[0];
    const float* adaln_in = (const float*)d_in[1];
    const float* cosT     = (const float*)d_in[2];
    const float* sinT     = (const float*)d_in[3];
    const float* wq       = (const float*)d_in[4];
    const float* wk       = (const float*)d_in[5];
    const float* wv       = (const float*)d_in[6];
    const float* wo       = (const float*)d_in[7];
    const float* q_norm_w = (const float*)d_in[8];
    const float* q_norm_b = (const float*)d_in[9];
    const float* k_norm_w = (const float*)d_in[10];
    const float* k_norm_b = (const float*)d_in[11];
    const float* attn_norm_w = (const float*)d_in[12];
    const float* ffn_norm_w  = (const float*)d_in[13];
    const float* ada_w    = (const float*)d_in[14];
    const float* ada_b    = (const float*)d_in[15];
    const float* w1       = (const float*)d_in[16];
    const float* w2       = (const float*)d_in[17];
    const float* w3       = (const float*)d_in[18];
    float* out = (float*)d_out;

    float* base = nullptr;
    cudaGetSymbolAddress((void**)&base, g_buf);
    float* m     = base + OFF_M;
    float* mpart = base + OFF_MPART;
    __nv_bfloat16* hbf  = (__nv_bfloat16*)(base + OFF_HBF);
    float* qf   = base + OFF_QF;
    float* kf   = base + OFF_KF;
    __nv_bfloat16* qbf  = (__nv_bfloat16*)(base + OFF_QBF);
    __nv_bfloat16* kbf  = (__nv_bfloat16*)(base + OFF_KBF);
    __nv_bfloat16* vbf  = (__nv_bfloat16*)(base + OFF_VBF);
    __nv_bfloat16* abf  = (__nv_bfloat16*)(base + OFF_ABF);
    float* xmid = base + OFF_XMID;
    __nv_bfloat16* g1bf = (__nv_bfloat16*)(base + OFF_G1BF);
    __nv_bfloat16* wqC  = (__nv_bfloat16*)(base + OFF_WQC);
    __nv_bfloat16* wkC  = (__nv_bfloat16*)(base + OFF_WKC);
    __nv_bfloat16* wvC  = (__nv_bfloat16*)(base + OFF_WVC);
    __nv_bfloat16* woC  = (__nv_bfloat16*)(base + OFF_WOC);
    __nv_bfloat16* w1C  = (__nv_bfloat16*)(base + OFF_W1C);
    __nv_bfloat16* w3C  = (__nv_bfloat16*)(base + OFF_W3C);
    __nv_bfloat16* w2C  = (__nv_bfloat16*)(base + OFF_W2C);

    cudaFuncSetAttribute(mma_gemm_kernel<2>, cudaFuncAttributeMaxDynamicSharedMemorySize, GSMEM);
    cudaFuncSetAttribute(mma_gemm_kernel<3>, cudaFuncAttributeMaxDynamicSharedMemorySize, GSMEM);
    cudaFuncSetAttribute(ffn_gemm_kernel, cudaFuncAttributeMaxDynamicSharedMemorySize, FSMEM);
    cudaFuncSetAttribute(attn_mma_kernel, cudaFuncAttributeMaxDynamicSharedMemorySize, ATT_SMEM);

    // weight converts (pure streaming, same layout)
    convert2_kernel<<<dim3(DIM*DIM/2048, 2), 256>>>(wq, wk, wqC, wkC);
    convert2_kernel<<<dim3(DIM*DIM/2048, 2), 256>>>(wv, wo, wvC, woC);
    convert3_kernel<<<dim3(DIM*HID/2048, 3), 256>>>(w1, w3, w2, w1C, w3C, w2C);

    // adaLN: split-K partials + deterministic reduce
    adaln_part_kernel<<<dim3(MCOLS/256, KSPLIT), 256>>>(adaln_in, ada_w, mpart);
    adaln_reduce_kernel<<<MCOLS/256, 256>>>(mpart, ada_b, m);

    rmsmod_kernel<<<RR, 256>>>(x, attn_norm_w, m, 0, DIM, hbf);

    // fused QKV projection
    mma_gemm_kernel<3><<<dim3(3*DIM/128, RR/128), 256, GSMEM>>>(
        hbf, wqC, wkC, wvC, DIM, qf, kf, vbf, nullptr, nullptr, 0, RR, DIM, DIM);

    lnrope2_kernel<<<dim3(RR, 2), 256>>>(qf, kf, q_norm_w, q_norm_b, k_norm_w, k_norm_b,
                                         cosT, sinT, qbf, kbf);

    attn_mma_kernel<<<dim3(SEQ/128, NH, BB), 256, ATT_SMEM>>>(qbf, kbf, vbf, abf);

    // wo projection + fused gated residual: xmid = x + gate_msa * (attn@wo)
    mma_gemm_kernel<2><<<dim3(DIM/128, RR/128), 256, GSMEM>>>(
        abf, woC, nullptr, nullptr, DIM, xmid, nullptr, nullptr, x, m, 2*DIM, RR, DIM, DIM);

    rmsmod_kernel<<<RR, 256>>>(xmid, ffn_norm_w, m, 3*DIM, 4*DIM, hbf);

    // fused dual FFN gemm: g1bf = bf16(silu(h@w1) * (h@w3))
    ffn_gemm_kernel<<<dim3(HID/64, RR/128), 256, FSMEM>>>(hbf, w1C, w3C, g1bf, RR, HID, DIM);

    // w2 projection + fused gated residual: out = xmid + gate_mlp * (g@w2)
    mma_gemm_kernel<2><<<dim3(DIM/128, RR/128), 256, GSMEM>>>(
        g1bf, w2C, nullptr, nullptr, DIM, out, nullptr, nullptr, xmid, m, 5*DIM, RR, DIM, HID);
}